// round 1
// baseline (speedup 1.0000x reference)
#include <cuda_runtime.h>
#include <math.h>

// ---------------- problem constants ----------------
#define MTOT   73728          // B*N = 8*9216 rows
#define CFEAT  1152
#define HD1    768
#define HD2    512
#define HD3    256
#define RED    144            // 1152/8
#define NSEQ   9216
#define NBATCH 8
#define WS     32
#define NWIN   2304           // 8 * 9216/32

// ---------------- scratch (no cudaMalloc allowed) ----------------
__device__ float g_h1[(size_t)MTOT * HD1];
__device__ float g_h2[(size_t)MTOT * HD2];
__device__ float g_h3[(size_t)MTOT * HD3];
__device__ float g_y [(size_t)MTOT * CFEAT];
__device__ float g_pool[NBATCH * CFEAT];
__device__ float g_s   [NBATCH * CFEAT];

__device__ __forceinline__ float gelu_exact(float x) {
    return 0.5f * x * (1.0f + erff(x * 0.70710678118654752f));
}

// ---------------- GEMM: C = act(A @ W + bias), optional column-sum pooling ----
// A: MxK row-major, W: KxN row-major. Tiles 128x128x8, 256 threads, 8x8/thread.
template<bool DO_GELU, bool DO_POOL>
__global__ void __launch_bounds__(256, 2)
gemm_kernel(const float* __restrict__ A, const float* __restrict__ W,
            const float* __restrict__ bias, float* __restrict__ Cout,
            int M, int N, int K, float* __restrict__ pool)
{
    __shared__ __align__(16) float As[8][128];
    __shared__ __align__(16) float Bs[8][128];
    __shared__ float csum[128];

    const int bx = blockIdx.x, by = blockIdx.y;
    const int tid = threadIdx.x;

    // A tile load: 128 rows x 8 k (one float4 per thread)
    const int aRow = tid >> 1;
    const int aCol = (tid & 1) << 2;
    const float* Ap = A + (size_t)(by * 128 + aRow) * K + aCol;
    // W tile load: 8 k x 128 cols (one float4 per thread)
    const int bRow = tid >> 5;
    const int bCol = (tid & 31) << 2;
    const float* Bp = W + (size_t)bRow * N + bx * 128 + bCol;

    float4 aF = *(const float4*)Ap;
    float4 bF = *(const float4*)Bp;

    float acc[8][8];
#pragma unroll
    for (int i = 0; i < 8; i++)
#pragma unroll
        for (int j = 0; j < 8; j++) acc[i][j] = 0.f;

    const int ty = tid >> 4, tx = tid & 15;

    for (int k0 = 0; k0 < K; k0 += 8) {
        As[aCol + 0][aRow] = aF.x;
        As[aCol + 1][aRow] = aF.y;
        As[aCol + 2][aRow] = aF.z;
        As[aCol + 3][aRow] = aF.w;
        *(float4*)&Bs[bRow][bCol] = bF;
        __syncthreads();
        if (k0 + 8 < K) {                        // prefetch next tile
            aF = *(const float4*)(Ap + k0 + 8);
            bF = *(const float4*)(Bp + (size_t)(k0 + 8) * N);
        }
#pragma unroll
        for (int k = 0; k < 8; ++k) {
            float4 a0 = *(const float4*)&As[k][ty << 3];
            float4 a1 = *(const float4*)&As[k][(ty << 3) + 4];
            float4 b0 = *(const float4*)&Bs[k][tx << 3];
            float4 b1 = *(const float4*)&Bs[k][(tx << 3) + 4];
            float av[8] = {a0.x, a0.y, a0.z, a0.w, a1.x, a1.y, a1.z, a1.w};
            float bv[8] = {b0.x, b0.y, b0.z, b0.w, b1.x, b1.y, b1.z, b1.w};
#pragma unroll
            for (int i = 0; i < 8; i++)
#pragma unroll
                for (int j = 0; j < 8; j++)
                    acc[i][j] = fmaf(av[i], bv[j], acc[i][j]);
        }
        __syncthreads();
    }

    // epilogue: bias (+gelu), store
    float bcol[8];
#pragma unroll
    for (int j = 0; j < 8; j++) bcol[j] = bias[bx * 128 + (tx << 3) + j];
#pragma unroll
    for (int i = 0; i < 8; i++) {
#pragma unroll
        for (int j = 0; j < 8; j++) {
            float v = acc[i][j] + bcol[j];
            if (DO_GELU) v = gelu_exact(v);
            acc[i][j] = v;
        }
        const int row = by * 128 + (ty << 3) + i;
        float* cp = Cout + (size_t)row * N + bx * 128 + (tx << 3);
        *(float4*)cp       = make_float4(acc[i][0], acc[i][1], acc[i][2], acc[i][3]);
        *(float4*)(cp + 4) = make_float4(acc[i][4], acc[i][5], acc[i][6], acc[i][7]);
    }

    if (DO_POOL) {
        if (tid < 128) csum[tid] = 0.f;
        __syncthreads();
#pragma unroll
        for (int j = 0; j < 8; j++) {
            float ps = 0.f;
#pragma unroll
            for (int i = 0; i < 8; i++) ps += acc[i][j];
            atomicAdd(&csum[(tx << 3) + j], ps);
        }
        __syncthreads();
        if (tid < 128) {
            const int batch = (by * 128) / NSEQ;   // 9216 % 128 == 0 -> tile within one batch
            atomicAdd(&pool[batch * CFEAT + bx * 128 + tid], csum[tid]);
        }
    }
}

// ---------------- LayerNorm over last dim (warp per row) ----------------
template<int H>
__global__ void ln_kernel(float* __restrict__ x, const float* __restrict__ g,
                          const float* __restrict__ be, int M)
{
    const int warp = threadIdx.x >> 5, lane = threadIdx.x & 31;
    const int row = blockIdx.x * (blockDim.x >> 5) + warp;
    if (row >= M) return;
    float* p = x + (size_t)row * H;
    constexpr int NV = H / 32;
    float v[NV];
    float s = 0.f;
#pragma unroll
    for (int i = 0; i < NV; i++) { v[i] = p[lane + (i << 5)]; s += v[i]; }
#pragma unroll
    for (int o = 16; o > 0; o >>= 1) s += __shfl_xor_sync(0xffffffffu, s, o);
    const float mu = s * (1.0f / H);
    float var = 0.f;
#pragma unroll
    for (int i = 0; i < NV; i++) { float d = v[i] - mu; var += d * d; }
#pragma unroll
    for (int o = 16; o > 0; o >>= 1) var += __shfl_xor_sync(0xffffffffu, var, o);
    const float rstd = rsqrtf(var * (1.0f / H) + 1e-5f);
#pragma unroll
    for (int i = 0; i < NV; i++) {
        const int c = lane + (i << 5);
        p[c] = (v[i] - mu) * rstd * g[c] + be[c];
    }
}

// ---------------- SE channel attention (tiny): s = sigmoid(relu(pool@w1+b1)@w2+b2)
__global__ void se_kernel(const float* __restrict__ pool,
                          const float* __restrict__ w1, const float* __restrict__ b1,
                          const float* __restrict__ w2, const float* __restrict__ b2,
                          float* __restrict__ s)
{
    __shared__ float p[CFEAT];
    __shared__ float hid[RED];
    const int b = blockIdx.x, t = threadIdx.x;
    for (int i = t; i < CFEAT; i += 256) p[i] = pool[b * CFEAT + i] * (1.0f / NSEQ);
    __syncthreads();
    if (t < RED) {
        float a = b1[t];
        for (int c = 0; c < CFEAT; c++) a = fmaf(p[c], w1[c * RED + t], a);
        hid[t] = fmaxf(a, 0.f);
    }
    __syncthreads();
    for (int c = t; c < CFEAT; c += 256) {
        float a = b2[c];
        for (int h = 0; h < RED; h++) a = fmaf(hid[h], w2[h * CFEAT + c], a);
        s[b * CFEAT + c] = 1.0f / (1.0f + expf(-a));
    }
}

// ---------------- fused SE-scale + windowed self-attention ----------------
// One block per 32-token window. Dynamic smem: Y (32 x 1153 f32) + S (32 x 33).
#define SDIM 1153
#define SSTR 33
#define ATTN_SMEM_BYTES ((32 * SDIM + 32 * SSTR) * (int)sizeof(float))

__global__ void __launch_bounds__(256)
attn_kernel(const float* __restrict__ y, const float* __restrict__ s,
            float* __restrict__ out)
{
    extern __shared__ float sm[];
    float* Ys = sm;                  // [32][SDIM]
    float* Ss = sm + 32 * SDIM;      // [32][SSTR]

    const int win = blockIdx.x;      // global row base = win*32 (windows sequential)
    const int b = win / (NSEQ / WS);
    const size_t base = (size_t)win * 32;
    const int tid = threadIdx.x;
    const float* sb = s + b * CFEAT;

    // phase 1: load scaled tile (float4 gmem reads, scalar smem stores)
    for (int idx = tid; idx < 32 * (CFEAT / 4); idx += 256) {
        const int r = idx / (CFEAT / 4);
        const int c4 = (idx % (CFEAT / 4)) * 4;
        float4 v  = *(const float4*)(y + (base + r) * CFEAT + c4);
        float4 sv = *(const float4*)(sb + c4);
        Ys[r * SDIM + c4 + 0] = v.x * sv.x;
        Ys[r * SDIM + c4 + 1] = v.y * sv.y;
        Ys[r * SDIM + c4 + 2] = v.z * sv.z;
        Ys[r * SDIM + c4 + 3] = v.w * sv.w;
    }
    for (int i = tid; i < 32 * SSTR; i += 256) Ss[i] = 0.f;
    __syncthreads();

    // phase 2: scores S = Y Y^T  (2x2 per thread, K split across 4 groups)
    {
        const int cg = tid >> 6;            // 0..3 -> K chunk
        const int r8 = (tid >> 3) & 7;      // q group (4 rows)
        const int cl = tid & 7;             // k group (4 cols)
        float acc[4][4] = {};
        const int c0 = cg * (CFEAT / 4), c1 = c0 + (CFEAT / 4);
        for (int c = c0; c < c1; c++) {
            float qv[4], kv[4];
#pragma unroll
            for (int i = 0; i < 4; i++) qv[i] = Ys[(r8 * 4 + i) * SDIM + c];
#pragma unroll
            for (int j = 0; j < 4; j++) kv[j] = Ys[(cl * 4 + j) * SDIM + c];
#pragma unroll
            for (int i = 0; i < 4; i++)
#pragma unroll
                for (int j = 0; j < 4; j++)
                    acc[i][j] = fmaf(qv[i], kv[j], acc[i][j]);
        }
#pragma unroll
        for (int i = 0; i < 4; i++)
#pragma unroll
            for (int j = 0; j < 4; j++)
                atomicAdd(&Ss[(r8 * 4 + i) * SSTR + (cl * 4 + j)], acc[i][j]);
    }
    __syncthreads();

    // softmax over k (warp per row)
    {
        const int warp = tid >> 5, lane = tid & 31;
        const float scale = 1.0f / sqrtf((float)CFEAT);
        for (int q = warp; q < 32; q += 8) {
            float v = Ss[q * SSTR + lane] * scale;
            float m = v;
#pragma unroll
            for (int o = 16; o > 0; o >>= 1) m = fmaxf(m, __shfl_xor_sync(0xffffffffu, m, o));
            float e = expf(v - m);
            float sum = e;
#pragma unroll
            for (int o = 16; o > 0; o >>= 1) sum += __shfl_xor_sync(0xffffffffu, sum, o);
            Ss[q * SSTR + lane] = e / sum;
        }
    }
    __syncthreads();

    // phase 3: out = P @ Y  (8 q-rows x 6 cols per thread per chunk)
    {
        const int qg = tid >> 6;        // 0..3 -> 8 q rows
        const int ct = tid & 63;        // column lane
        for (int gIdx = 0; gIdx < 3; gIdx++) {
            float acc[8][6];
#pragma unroll
            for (int i = 0; i < 8; i++)
#pragma unroll
                for (int u = 0; u < 6; u++) acc[i][u] = 0.f;
            for (int k = 0; k < 32; k++) {
                float sv[8];
#pragma unroll
                for (int i = 0; i < 8; i++) sv[i] = Ss[(qg * 8 + i) * SSTR + k];
#pragma unroll
                for (int u = 0; u < 6; u++) {
                    const int c = ct + ((gIdx * 6 + u) << 6);
                    const float yv = Ys[k * SDIM + c];
#pragma unroll
                    for (int i = 0; i < 8; i++) acc[i][u] = fmaf(sv[i], yv, acc[i][u]);
                }
            }
#pragma unroll
            for (int i = 0; i < 8; i++) {
                const size_t row = base + qg * 8 + i;
#pragma unroll
                for (int u = 0; u < 6; u++) {
                    const int c = ct + ((gIdx * 6 + u) << 6);
                    out[row * CFEAT + c] = acc[i][u];
                }
            }
        }
    }
}

// ---------------- launch ----------------
extern "C" void kernel_launch(void* const* d_in, const int* in_sizes, int n_in,
                              void* d_out, int out_size)
{
    const float* x    = (const float*)d_in[0];
    const float* W1   = (const float*)d_in[1];
    const float* b1   = (const float*)d_in[2];
    const float* g1   = (const float*)d_in[3];
    const float* be1  = (const float*)d_in[4];
    const float* W2   = (const float*)d_in[5];
    const float* b2   = (const float*)d_in[6];
    const float* g2   = (const float*)d_in[7];
    const float* be2  = (const float*)d_in[8];
    const float* W3   = (const float*)d_in[9];
    const float* b3   = (const float*)d_in[10];
    const float* g3   = (const float*)d_in[11];
    const float* be3  = (const float*)d_in[12];
    const float* Wo   = (const float*)d_in[13];
    const float* bo   = (const float*)d_in[14];
    const float* caw1 = (const float*)d_in[15];
    const float* cab1 = (const float*)d_in[16];
    const float* caw2 = (const float*)d_in[17];
    const float* cab2 = (const float*)d_in[18];
    float* out = (float*)d_out;

    float *h1p, *h2p, *h3p, *yp, *poolp, *sp;
    cudaGetSymbolAddress((void**)&h1p, g_h1);
    cudaGetSymbolAddress((void**)&h2p, g_h2);
    cudaGetSymbolAddress((void**)&h3p, g_h3);
    cudaGetSymbolAddress((void**)&yp,  g_y);
    cudaGetSymbolAddress((void**)&poolp, g_pool);
    cudaGetSymbolAddress((void**)&sp,  g_s);

    cudaFuncSetAttribute((const void*)attn_kernel,
                         cudaFuncAttributeMaxDynamicSharedMemorySize, ATTN_SMEM_BYTES);

    cudaMemsetAsync(poolp, 0, NBATCH * CFEAT * sizeof(float));

    dim3 blk(256);
    // layer 1: LN(GELU(x @ W1 + b1))
    gemm_kernel<true, false><<<dim3(HD1 / 128, MTOT / 128), blk>>>(
        x, W1, b1, h1p, MTOT, HD1, CFEAT, nullptr);
    ln_kernel<HD1><<<MTOT / 8, 256>>>(h1p, g1, be1, MTOT);
    // layer 2
    gemm_kernel<true, false><<<dim3(HD2 / 128, MTOT / 128), blk>>>(
        h1p, W2, b2, h2p, MTOT, HD2, HD1, nullptr);
    ln_kernel<HD2><<<MTOT / 8, 256>>>(h2p, g2, be2, MTOT);
    // layer 3
    gemm_kernel<true, false><<<dim3(HD3 / 128, MTOT / 128), blk>>>(
        h2p, W3, b3, h3p, MTOT, HD3, HD2, nullptr);
    ln_kernel<HD3><<<MTOT / 8, 256>>>(h3p, g3, be3, MTOT);
    // output projection + pooled column sums
    gemm_kernel<false, true><<<dim3(CFEAT / 128, MTOT / 128), blk>>>(
        h3p, Wo, bo, yp, MTOT, CFEAT, HD3, poolp);
    // SE gate
    se_kernel<<<NBATCH, 256>>>(poolp, caw1, cab1, caw2, cab2, sp);
    // fused SE-scale + windowed attention -> final output
    attn_kernel<<<NWIN, 256, ATTN_SMEM_BYTES>>>(yp, sp, out);
}

// round 2
// speedup vs baseline: 2.3001x; 2.3001x over previous
#include <cuda_runtime.h>
#include <math.h>
#include <stdint.h>

// ---------------- problem constants ----------------
#define MTOT   73728          // B*N = 8*9216 rows
#define CFEAT  1152
#define HD1    768
#define HD2    512
#define HD3    256
#define RED    144            // 1152/8
#define NSEQ   9216
#define NBATCH 8
#define WS     32
#define NWIN   2304           // 8 * 9216/32

// ---------------- scratch (no cudaMalloc allowed) ----------------
__device__ float g_h1[(size_t)MTOT * HD1];
__device__ float g_h2[(size_t)MTOT * HD2];
__device__ float g_h3[(size_t)MTOT * HD3];
__device__ float g_y [(size_t)MTOT * CFEAT];
__device__ float g_pool[NBATCH * CFEAT];
__device__ float g_s   [NBATCH * CFEAT];
// tf32-rounded weight copies
__device__ float g_w1r[CFEAT * HD1];
__device__ float g_w2r[HD1 * HD2];
__device__ float g_w3r[HD2 * HD3];
__device__ float g_wor[HD3 * CFEAT];

__device__ __forceinline__ float gelu_exact(float x) {
    return 0.5f * x * (1.0f + erff(x * 0.70710678118654752f));
}

__device__ __forceinline__ uint32_t tf32_rna(float x) {
    uint32_t r;
    asm("cvt.rna.tf32.f32 %0, %1;" : "=r"(r) : "f"(x));
    return r;
}

__device__ __forceinline__ void cp16(float* dst, const float* src) {
    uint32_t d = (uint32_t)__cvta_generic_to_shared(dst);
    asm volatile("cp.async.ca.shared.global [%0], [%1], 16;" :: "r"(d), "l"(src));
}
__device__ __forceinline__ void cp_commit() {
    asm volatile("cp.async.commit_group;");
}
__device__ __forceinline__ void cp_wait0() {
    asm volatile("cp.async.wait_group 0;");
}
__device__ __forceinline__ void cp_wait1() {
    asm volatile("cp.async.wait_group 1;");
}

__device__ __forceinline__ void mma_tf32(float* c, const uint32_t* a, const uint32_t* b) {
    asm volatile(
        "mma.sync.aligned.m16n8k8.row.col.f32.tf32.tf32.f32 "
        "{%0,%1,%2,%3}, {%4,%5,%6,%7}, {%8,%9}, {%0,%1,%2,%3};"
        : "+f"(c[0]), "+f"(c[1]), "+f"(c[2]), "+f"(c[3])
        : "r"(a[0]), "r"(a[1]), "r"(a[2]), "r"(a[3]), "r"(b[0]), "r"(b[1]));
}

// ---------------- weight rounding prep ----------------
__global__ void round_kernel(const float* __restrict__ src, float* __restrict__ dst, int n) {
    int i = blockIdx.x * 256 + threadIdx.x;
    if (i < n) dst[i] = __uint_as_float(tf32_rna(src[i]));
}

// ---------------- tf32 tensor-core GEMM ----------------
// C = act(A @ W + bias); A: MxK row-major (tf32-prerounded unless ROUND_A),
// W: KxN row-major tf32-prerounded. Block 128x128x32, 8 warps, warp 32x64.
#define BM 128
#define BN 128
#define BK 32
#define ASTR 36     // pad 4: fragment gather banks = 4*g + t  (conflict-free)
#define BSTR 136    // pad 8: fragment gather banks = 8*t + g  (conflict-free)
#define GEMM_SMEM_FLOATS (2 * BM * ASTR + 2 * BK * BSTR)
#define GEMM_SMEM_BYTES  (GEMM_SMEM_FLOATS * (int)sizeof(float))   // 71680

template<bool DO_GELU, bool ROUND_A, bool DO_POOL>
__global__ void __launch_bounds__(256, 2)
mma_gemm(const float* __restrict__ A, const float* __restrict__ W,
         const float* __restrict__ bias, float* __restrict__ Cout,
         int M, int N, int K, float* __restrict__ pool)
{
    extern __shared__ float sm[];
    float* Asm = sm;                          // [2][BM*ASTR]
    float* Bsm = sm + 2 * BM * ASTR;          // [2][BK*BSTR]

    const int tid  = threadIdx.x;
    const int warp = tid >> 5, lane = tid & 31;
    const int g = lane >> 2, t = lane & 3;
    const int wy = warp >> 1, wx = warp & 1;  // warp grid 4x2 (32x64 per warp)

    // global load mapping
    const int arow = tid >> 3;                // 0..31
    const int acol = (tid & 7) << 2;          // k within tile
    const float* Ag = A + (size_t)(blockIdx.y * BM + arow) * K + acol;
    const int brow = tid >> 5;                // 0..7
    const int bcol = (tid & 31) << 2;
    const float* Bg = W + (size_t)brow * N + blockIdx.x * BN + bcol;

    float acc[2][8][4];
#pragma unroll
    for (int im = 0; im < 2; im++)
#pragma unroll
        for (int in = 0; in < 8; in++)
#pragma unroll
            for (int c = 0; c < 4; c++) acc[im][in][c] = 0.f;

    const int nk = K / BK;

    // prologue: tile 0
    {
        float* Ad = Asm;
        float* Bd = Bsm;
#pragma unroll
        for (int i = 0; i < 4; i++)
            cp16(&Ad[(arow + i * 32) * ASTR + acol], Ag + (size_t)(i * 32) * K);
#pragma unroll
        for (int i = 0; i < 4; i++)
            cp16(&Bd[(brow + i * 8) * BSTR + bcol], Bg + (size_t)(i * 8) * N);
        cp_commit();
    }

    for (int kt = 0; kt < nk; kt++) {
        const int buf = kt & 1;
        if (kt + 1 < nk) {
            const int k0 = (kt + 1) * BK;
            float* Ad = Asm + (buf ^ 1) * (BM * ASTR);
            float* Bd = Bsm + (buf ^ 1) * (BK * BSTR);
#pragma unroll
            for (int i = 0; i < 4; i++)
                cp16(&Ad[(arow + i * 32) * ASTR + acol], Ag + (size_t)(i * 32) * K + k0);
#pragma unroll
            for (int i = 0; i < 4; i++)
                cp16(&Bd[(brow + i * 8) * BSTR + bcol], Bg + (size_t)(k0 + i * 8) * N);
            cp_commit();
            cp_wait1();
        } else {
            cp_wait0();
        }
        __syncthreads();

        const float* Ab = Asm + buf * (BM * ASTR);
        const float* Bb = Bsm + buf * (BK * BSTR);
#pragma unroll
        for (int ks = 0; ks < 4; ks++) {
            const int kk = ks * 8;
            uint32_t af[2][4];
#pragma unroll
            for (int im = 0; im < 2; im++) {
                const int m = wy * 32 + im * 16 + g;
                float a0 = Ab[m * ASTR + kk + t];
                float a1 = Ab[(m + 8) * ASTR + kk + t];
                float a2 = Ab[m * ASTR + kk + t + 4];
                float a3 = Ab[(m + 8) * ASTR + kk + t + 4];
                if (ROUND_A) {
                    af[im][0] = tf32_rna(a0); af[im][1] = tf32_rna(a1);
                    af[im][2] = tf32_rna(a2); af[im][3] = tf32_rna(a3);
                } else {
                    af[im][0] = __float_as_uint(a0); af[im][1] = __float_as_uint(a1);
                    af[im][2] = __float_as_uint(a2); af[im][3] = __float_as_uint(a3);
                }
            }
            uint32_t bf[8][2];
#pragma unroll
            for (int in = 0; in < 8; in++) {
                const int n = wx * 64 + in * 8 + g;
                bf[in][0] = __float_as_uint(Bb[(kk + t) * BSTR + n]);
                bf[in][1] = __float_as_uint(Bb[(kk + t + 4) * BSTR + n]);
            }
#pragma unroll
            for (int im = 0; im < 2; im++)
#pragma unroll
                for (int in = 0; in < 8; in++)
                    mma_tf32(acc[im][in], af[im], bf[in]);
        }
        __syncthreads();
    }

    // ---- epilogue: bias (+gelu), store; optional pooled column sums ----
    float* csum = sm;   // smem reuse (all buffers retired)
    if (DO_POOL) {
        if (tid < 128) csum[tid] = 0.f;
        __syncthreads();
    }

#pragma unroll
    for (int im = 0; im < 2; im++) {
        const int r0 = blockIdx.y * BM + wy * 32 + im * 16 + g;
#pragma unroll
        for (int in = 0; in < 8; in++) {
            const int col = blockIdx.x * BN + wx * 64 + in * 8 + 2 * t;
            const float bv0 = bias[col], bv1 = bias[col + 1];
            float v00 = acc[im][in][0] + bv0;
            float v01 = acc[im][in][1] + bv1;
            float v10 = acc[im][in][2] + bv0;
            float v11 = acc[im][in][3] + bv1;
            if (DO_GELU) {
                v00 = gelu_exact(v00); v01 = gelu_exact(v01);
                v10 = gelu_exact(v10); v11 = gelu_exact(v11);
            }
            *(float2*)(Cout + (size_t)r0 * N + col)       = make_float2(v00, v01);
            *(float2*)(Cout + (size_t)(r0 + 8) * N + col) = make_float2(v10, v11);
            if (DO_POOL) {
                const int lc = wx * 64 + in * 8 + 2 * t;
                atomicAdd(&csum[lc],     v00 + v10);
                atomicAdd(&csum[lc + 1], v01 + v11);
            }
        }
    }

    if (DO_POOL) {
        __syncthreads();
        if (tid < 128) {
            const int batch = (blockIdx.y * BM) / NSEQ;   // 9216 % 128 == 0
            atomicAdd(&pool[batch * CFEAT + blockIdx.x * BN + tid], csum[tid]);
        }
    }
}

// ---------------- LayerNorm over last dim (warp per row), tf32-rounded out ----
template<int H>
__global__ void ln_kernel(float* __restrict__ x, const float* __restrict__ g,
                          const float* __restrict__ be, int M)
{
    const int warp = threadIdx.x >> 5, lane = threadIdx.x & 31;
    const int row = blockIdx.x * (blockDim.x >> 5) + warp;
    if (row >= M) return;
    float* p = x + (size_t)row * H;
    constexpr int NV = H / 32;
    float v[NV];
    float s = 0.f;
#pragma unroll
    for (int i = 0; i < NV; i++) { v[i] = p[lane + (i << 5)]; s += v[i]; }
#pragma unroll
    for (int o = 16; o > 0; o >>= 1) s += __shfl_xor_sync(0xffffffffu, s, o);
    const float mu = s * (1.0f / H);
    float var = 0.f;
#pragma unroll
    for (int i = 0; i < NV; i++) { float d = v[i] - mu; var += d * d; }
#pragma unroll
    for (int o = 16; o > 0; o >>= 1) var += __shfl_xor_sync(0xffffffffu, var, o);
    const float rstd = rsqrtf(var * (1.0f / H) + 1e-5f);
#pragma unroll
    for (int i = 0; i < NV; i++) {
        const int c = lane + (i << 5);
        const float o = (v[i] - mu) * rstd * g[c] + be[c];
        p[c] = __uint_as_float(tf32_rna(o));   // pre-round for next tf32 GEMM
    }
}

// ---------------- SE channel attention ----------------
__global__ void se_kernel(const float* __restrict__ pool,
                          const float* __restrict__ w1, const float* __restrict__ b1,
                          const float* __restrict__ w2, const float* __restrict__ b2,
                          float* __restrict__ s)
{
    __shared__ float p[CFEAT];
    __shared__ float hid[RED];
    const int b = blockIdx.x, t = threadIdx.x;
    for (int i = t; i < CFEAT; i += 256) p[i] = pool[b * CFEAT + i] * (1.0f / NSEQ);
    __syncthreads();
    if (t < RED) {
        float a = b1[t];
        for (int c = 0; c < CFEAT; c++) a = fmaf(p[c], w1[c * RED + t], a);
        hid[t] = fmaxf(a, 0.f);
    }
    __syncthreads();
    for (int c = t; c < CFEAT; c += 256) {
        float a = b2[c];
        for (int h = 0; h < RED; h++) a = fmaf(hid[h], w2[h * CFEAT + c], a);
        s[b * CFEAT + c] = 1.0f / (1.0f + expf(-a));
    }
}

// ---------------- fused SE-scale + windowed self-attention ----------------
#define SDIM 1153
#define SSTR 33
#define ATTN_SMEM_BYTES ((32 * SDIM + 32 * SSTR) * (int)sizeof(float))

__global__ void __launch_bounds__(256)
attn_kernel(const float* __restrict__ y, const float* __restrict__ s,
            float* __restrict__ out)
{
    extern __shared__ float sm[];
    float* Ys = sm;                  // [32][SDIM]
    float* Ss = sm + 32 * SDIM;      // [32][SSTR]

    const int win = blockIdx.x;
    const int b = win / (NSEQ / WS);
    const size_t base = (size_t)win * 32;
    const int tid = threadIdx.x;
    const float* sb = s + b * CFEAT;

    for (int idx = tid; idx < 32 * (CFEAT / 4); idx += 256) {
        const int r = idx / (CFEAT / 4);
        const int c4 = (idx % (CFEAT / 4)) * 4;
        float4 v  = *(const float4*)(y + (base + r) * CFEAT + c4);
        float4 sv = *(const float4*)(sb + c4);
        Ys[r * SDIM + c4 + 0] = v.x * sv.x;
        Ys[r * SDIM + c4 + 1] = v.y * sv.y;
        Ys[r * SDIM + c4 + 2] = v.z * sv.z;
        Ys[r * SDIM + c4 + 3] = v.w * sv.w;
    }
    for (int i = tid; i < 32 * SSTR; i += 256) Ss[i] = 0.f;
    __syncthreads();

    {
        const int cg = tid >> 6;
        const int r8 = (tid >> 3) & 7;
        const int cl = tid & 7;
        float acc[4][4] = {};
        const int c0 = cg * (CFEAT / 4), c1 = c0 + (CFEAT / 4);
        for (int c = c0; c < c1; c++) {
            float qv[4], kv[4];
#pragma unroll
            for (int i = 0; i < 4; i++) qv[i] = Ys[(r8 * 4 + i) * SDIM + c];
#pragma unroll
            for (int j = 0; j < 4; j++) kv[j] = Ys[(cl * 4 + j) * SDIM + c];
#pragma unroll
            for (int i = 0; i < 4; i++)
#pragma unroll
                for (int j = 0; j < 4; j++)
                    acc[i][j] = fmaf(qv[i], kv[j], acc[i][j]);
        }
#pragma unroll
        for (int i = 0; i < 4; i++)
#pragma unroll
            for (int j = 0; j < 4; j++)
                atomicAdd(&Ss[(r8 * 4 + i) * SSTR + (cl * 4 + j)], acc[i][j]);
    }
    __syncthreads();

    {
        const int warp = tid >> 5, lane = tid & 31;
        const float scale = 1.0f / sqrtf((float)CFEAT);
        for (int q = warp; q < 32; q += 8) {
            float v = Ss[q * SSTR + lane] * scale;
            float m = v;
#pragma unroll
            for (int o = 16; o > 0; o >>= 1) m = fmaxf(m, __shfl_xor_sync(0xffffffffu, m, o));
            float e = expf(v - m);
            float sum = e;
#pragma unroll
            for (int o = 16; o > 0; o >>= 1) sum += __shfl_xor_sync(0xffffffffu, sum, o);
            Ss[q * SSTR + lane] = e / sum;
        }
    }
    __syncthreads();

    {
        const int qg = tid >> 6;
        const int ct = tid & 63;
        for (int gIdx = 0; gIdx < 3; gIdx++) {
            float acc[8][6];
#pragma unroll
            for (int i = 0; i < 8; i++)
#pragma unroll
                for (int u = 0; u < 6; u++) acc[i][u] = 0.f;
            for (int k = 0; k < 32; k++) {
                float sv[8];
#pragma unroll
                for (int i = 0; i < 8; i++) sv[i] = Ss[(qg * 8 + i) * SSTR + k];
#pragma unroll
                for (int u = 0; u < 6; u++) {
                    const int c = ct + ((gIdx * 6 + u) << 6);
                    const float yv = Ys[k * SDIM + c];
#pragma unroll
                    for (int i = 0; i < 8; i++) acc[i][u] = fmaf(sv[i], yv, acc[i][u]);
                }
            }
#pragma unroll
            for (int i = 0; i < 8; i++) {
                const size_t row = base + qg * 8 + i;
#pragma unroll
                for (int u = 0; u < 6; u++) {
                    const int c = ct + ((gIdx * 6 + u) << 6);
                    out[row * CFEAT + c] = acc[i][u];
                }
            }
        }
    }
}

// ---------------- launch ----------------
extern "C" void kernel_launch(void* const* d_in, const int* in_sizes, int n_in,
                              void* d_out, int out_size)
{
    const float* x    = (const float*)d_in[0];
    const float* W1   = (const float*)d_in[1];
    const float* b1   = (const float*)d_in[2];
    const float* g1   = (const float*)d_in[3];
    const float* be1  = (const float*)d_in[4];
    const float* W2   = (const float*)d_in[5];
    const float* b2   = (const float*)d_in[6];
    const float* g2   = (const float*)d_in[7];
    const float* be2  = (const float*)d_in[8];
    const float* W3   = (const float*)d_in[9];
    const float* b3   = (const float*)d_in[10];
    const float* g3   = (const float*)d_in[11];
    const float* be3  = (const float*)d_in[12];
    const float* Wo   = (const float*)d_in[13];
    const float* bo   = (const float*)d_in[14];
    const float* caw1 = (const float*)d_in[15];
    const float* cab1 = (const float*)d_in[16];
    const float* caw2 = (const float*)d_in[17];
    const float* cab2 = (const float*)d_in[18];
    float* out = (float*)d_out;

    float *h1p, *h2p, *h3p, *yp, *poolp, *sp;
    float *w1r, *w2r, *w3r, *wor;
    cudaGetSymbolAddress((void**)&h1p, g_h1);
    cudaGetSymbolAddress((void**)&h2p, g_h2);
    cudaGetSymbolAddress((void**)&h3p, g_h3);
    cudaGetSymbolAddress((void**)&yp,  g_y);
    cudaGetSymbolAddress((void**)&poolp, g_pool);
    cudaGetSymbolAddress((void**)&sp,  g_s);
    cudaGetSymbolAddress((void**)&w1r, g_w1r);
    cudaGetSymbolAddress((void**)&w2r, g_w2r);
    cudaGetSymbolAddress((void**)&w3r, g_w3r);
    cudaGetSymbolAddress((void**)&wor, g_wor);

    cudaFuncSetAttribute((const void*)mma_gemm<true, true, false>,
                         cudaFuncAttributeMaxDynamicSharedMemorySize, GEMM_SMEM_BYTES);
    cudaFuncSetAttribute((const void*)mma_gemm<true, false, false>,
                         cudaFuncAttributeMaxDynamicSharedMemorySize, GEMM_SMEM_BYTES);
    cudaFuncSetAttribute((const void*)mma_gemm<false, false, true>,
                         cudaFuncAttributeMaxDynamicSharedMemorySize, GEMM_SMEM_BYTES);
    cudaFuncSetAttribute((const void*)attn_kernel,
                         cudaFuncAttributeMaxDynamicSharedMemorySize, ATTN_SMEM_BYTES);

    cudaMemsetAsync(poolp, 0, NBATCH * CFEAT * sizeof(float));

    // prep: round weights to tf32 once per launch
    round_kernel<<<(CFEAT * HD1) / 256, 256>>>(W1, w1r, CFEAT * HD1);
    round_kernel<<<(HD1 * HD2) / 256, 256>>>(W2, w2r, HD1 * HD2);
    round_kernel<<<(HD2 * HD3) / 256, 256>>>(W3, w3r, HD2 * HD3);
    round_kernel<<<(HD3 * CFEAT) / 256, 256>>>(Wo, wor, HD3 * CFEAT);

    dim3 blk(256);
    // layer 1: LN(GELU(x @ W1 + b1)) — A needs in-loop tf32 rounding
    mma_gemm<true, true, false><<<dim3(HD1 / BN, MTOT / BM), blk, GEMM_SMEM_BYTES>>>(
        x, w1r, b1, h1p, MTOT, HD1, CFEAT, nullptr);
    ln_kernel<HD1><<<MTOT / 8, 256>>>(h1p, g1, be1, MTOT);
    // layer 2
    mma_gemm<true, false, false><<<dim3(HD2 / BN, MTOT / BM), blk, GEMM_SMEM_BYTES>>>(
        h1p, w2r, b2, h2p, MTOT, HD2, HD1, nullptr);
    ln_kernel<HD2><<<MTOT / 8, 256>>>(h2p, g2, be2, MTOT);
    // layer 3
    mma_gemm<true, false, false><<<dim3(HD3 / BN, MTOT / BM), blk, GEMM_SMEM_BYTES>>>(
        h2p, w3r, b3, h3p, MTOT, HD3, HD2, nullptr);
    ln_kernel<HD3><<<MTOT / 8, 256>>>(h3p, g3, be3, MTOT);
    // output projection + fused pooled column sums
    mma_gemm<false, false, true><<<dim3(CFEAT / BN, MTOT / BM), blk, GEMM_SMEM_BYTES>>>(
        h3p, wor, bo, yp, MTOT, CFEAT, HD3, poolp);
    // SE gate
    se_kernel<<<NBATCH, 256>>>(poolp, caw1, cab1, caw2, cab2, sp);
    // fused SE-scale + windowed attention -> final output
    attn_kernel<<<NWIN, 256, ATTN_SMEM_BYTES>>>(yp, sp, out);
}

// round 3
// speedup vs baseline: 2.3004x; 1.0001x over previous
#include <cuda_runtime.h>
#include <math.h>
#include <stdint.h>

// ---------------- problem constants ----------------
#define MTOT   73728          // B*N = 8*9216 rows
#define CFEAT  1152
#define HD1    768
#define HD2    512
#define HD3    256
#define RED    144            // 1152/8
#define NSEQ   9216
#define NBATCH 8
#define WS     32
#define NWIN   2304           // 8 * 9216/32

// ---------------- scratch (no cudaMalloc allowed) ----------------
__device__ float g_h1[(size_t)MTOT * HD1];
__device__ float g_h2[(size_t)MTOT * HD2];
__device__ float g_h3[(size_t)MTOT * HD3];
__device__ float g_y [(size_t)MTOT * CFEAT];
__device__ float g_pool[NBATCH * CFEAT];
__device__ float g_s   [NBATCH * CFEAT];
// tf32-rounded weight copies
__device__ float g_w1r[CFEAT * HD1];
__device__ float g_w2r[HD1 * HD2];
__device__ float g_w3r[HD2 * HD3];
__device__ float g_wor[HD3 * CFEAT];

__device__ __forceinline__ float gelu_exact(float x) {
    return 0.5f * x * (1.0f + erff(x * 0.70710678118654752f));
}

__device__ __forceinline__ uint32_t tf32_rna(float x) {
    uint32_t r;
    asm("cvt.rna.tf32.f32 %0, %1;" : "=r"(r) : "f"(x));
    return r;
}

__device__ __forceinline__ void cp16(float* dst, const float* src) {
    uint32_t d = (uint32_t)__cvta_generic_to_shared(dst);
    asm volatile("cp.async.ca.shared.global [%0], [%1], 16;" :: "r"(d), "l"(src));
}
__device__ __forceinline__ void cp_commit() {
    asm volatile("cp.async.commit_group;");
}
__device__ __forceinline__ void cp_wait0() {
    asm volatile("cp.async.wait_group 0;");
}
__device__ __forceinline__ void cp_wait1() {
    asm volatile("cp.async.wait_group 1;");
}

__device__ __forceinline__ void mma_tf32(float* c, const uint32_t* a, const uint32_t* b) {
    asm volatile(
        "mma.sync.aligned.m16n8k8.row.col.f32.tf32.tf32.f32 "
        "{%0,%1,%2,%3}, {%4,%5,%6,%7}, {%8,%9}, {%0,%1,%2,%3};"
        : "+f"(c[0]), "+f"(c[1]), "+f"(c[2]), "+f"(c[3])
        : "r"(a[0]), "r"(a[1]), "r"(a[2]), "r"(a[3]), "r"(b[0]), "r"(b[1]));
}

// ---------------- weight rounding prep ----------------
__global__ void round_kernel(const float* __restrict__ src, float* __restrict__ dst, int n) {
    int i = blockIdx.x * 256 + threadIdx.x;
    if (i < n) dst[i] = __uint_as_float(tf32_rna(src[i]));
}

// ---------------- tf32 tensor-core GEMM ----------------
// C = act(A @ W + bias); A: MxK row-major (tf32-prerounded unless ROUND_A),
// W: KxN row-major tf32-prerounded. Block 128x128x32, 8 warps, warp 32x64.
#define BM 128
#define BN 128
#define BK 32
#define ASTR 36     // pad 4: fragment gather banks = 4*g + t  (conflict-free)
#define BSTR 136    // pad 8: fragment gather banks = 8*t + g  (conflict-free)
#define GEMM_SMEM_FLOATS (2 * BM * ASTR + 2 * BK * BSTR)
#define GEMM_SMEM_BYTES  (GEMM_SMEM_FLOATS * (int)sizeof(float))   // 71680

template<bool DO_GELU, bool ROUND_A, bool DO_POOL>
__global__ void __launch_bounds__(256, 2)
mma_gemm(const float* __restrict__ A, const float* __restrict__ W,
         const float* __restrict__ bias, float* __restrict__ Cout,
         int M, int N, int K, float* __restrict__ pool)
{
    extern __shared__ float sm[];
    float* Asm = sm;                          // [2][BM*ASTR]
    float* Bsm = sm + 2 * BM * ASTR;          // [2][BK*BSTR]

    const int tid  = threadIdx.x;
    const int warp = tid >> 5, lane = tid & 31;
    const int g = lane >> 2, t = lane & 3;
    const int wy = warp >> 1, wx = warp & 1;  // warp grid 4x2 (32x64 per warp)

    // global load mapping
    const int arow = tid >> 3;                // 0..31
    const int acol = (tid & 7) << 2;          // k within tile
    const float* Ag = A + (size_t)(blockIdx.y * BM + arow) * K + acol;
    const int brow = tid >> 5;                // 0..7
    const int bcol = (tid & 31) << 2;
    const float* Bg = W + (size_t)brow * N + blockIdx.x * BN + bcol;

    float acc[2][8][4];
#pragma unroll
    for (int im = 0; im < 2; im++)
#pragma unroll
        for (int in = 0; in < 8; in++)
#pragma unroll
            for (int c = 0; c < 4; c++) acc[im][in][c] = 0.f;

    const int nk = K / BK;

    // prologue: tile 0
    {
        float* Ad = Asm;
        float* Bd = Bsm;
#pragma unroll
        for (int i = 0; i < 4; i++)
            cp16(&Ad[(arow + i * 32) * ASTR + acol], Ag + (size_t)(i * 32) * K);
#pragma unroll
        for (int i = 0; i < 4; i++)
            cp16(&Bd[(brow + i * 8) * BSTR + bcol], Bg + (size_t)(i * 8) * N);
        cp_commit();
    }

    for (int kt = 0; kt < nk; kt++) {
        const int buf = kt & 1;
        if (kt + 1 < nk) {
            const int k0 = (kt + 1) * BK;
            float* Ad = Asm + (buf ^ 1) * (BM * ASTR);
            float* Bd = Bsm + (buf ^ 1) * (BK * BSTR);
#pragma unroll
            for (int i = 0; i < 4; i++)
                cp16(&Ad[(arow + i * 32) * ASTR + acol], Ag + (size_t)(i * 32) * K + k0);
#pragma unroll
            for (int i = 0; i < 4; i++)
                cp16(&Bd[(brow + i * 8) * BSTR + bcol], Bg + (size_t)(k0 + i * 8) * N);
            cp_commit();
            cp_wait1();
        } else {
            cp_wait0();
        }
        __syncthreads();

        const float* Ab = Asm + buf * (BM * ASTR);
        const float* Bb = Bsm + buf * (BK * BSTR);
#pragma unroll
        for (int ks = 0; ks < 4; ks++) {
            const int kk = ks * 8;
            uint32_t af[2][4];
#pragma unroll
            for (int im = 0; im < 2; im++) {
                const int m = wy * 32 + im * 16 + g;
                float a0 = Ab[m * ASTR + kk + t];
                float a1 = Ab[(m + 8) * ASTR + kk + t];
                float a2 = Ab[m * ASTR + kk + t + 4];
                float a3 = Ab[(m + 8) * ASTR + kk + t + 4];
                if (ROUND_A) {
                    af[im][0] = tf32_rna(a0); af[im][1] = tf32_rna(a1);
                    af[im][2] = tf32_rna(a2); af[im][3] = tf32_rna(a3);
                } else {
                    af[im][0] = __float_as_uint(a0); af[im][1] = __float_as_uint(a1);
                    af[im][2] = __float_as_uint(a2); af[im][3] = __float_as_uint(a3);
                }
            }
            uint32_t bf[8][2];
#pragma unroll
            for (int in = 0; in < 8; in++) {
                const int n = wx * 64 + in * 8 + g;
                bf[in][0] = __float_as_uint(Bb[(kk + t) * BSTR + n]);
                bf[in][1] = __float_as_uint(Bb[(kk + t + 4) * BSTR + n]);
            }
#pragma unroll
            for (int im = 0; im < 2; im++)
#pragma unroll
                for (int in = 0; in < 8; in++)
                    mma_tf32(acc[im][in], af[im], bf[in]);
        }
        __syncthreads();
    }

    // ---- epilogue: bias (+gelu), store; optional pooled column sums ----
    float* csum = sm;   // smem reuse (all buffers retired)
    if (DO_POOL) {
        if (tid < 128) csum[tid] = 0.f;
        __syncthreads();
    }

#pragma unroll
    for (int im = 0; im < 2; im++) {
        const int r0 = blockIdx.y * BM + wy * 32 + im * 16 + g;
#pragma unroll
        for (int in = 0; in < 8; in++) {
            const int col = blockIdx.x * BN + wx * 64 + in * 8 + 2 * t;
            const float bv0 = bias[col], bv1 = bias[col + 1];
            float v00 = acc[im][in][0] + bv0;
            float v01 = acc[im][in][1] + bv1;
            float v10 = acc[im][in][2] + bv0;
            float v11 = acc[im][in][3] + bv1;
            if (DO_GELU) {
                v00 = gelu_exact(v00); v01 = gelu_exact(v01);
                v10 = gelu_exact(v10); v11 = gelu_exact(v11);
            }
            *(float2*)(Cout + (size_t)r0 * N + col)       = make_float2(v00, v01);
            *(float2*)(Cout + (size_t)(r0 + 8) * N + col) = make_float2(v10, v11);
            if (DO_POOL) {
                const int lc = wx * 64 + in * 8 + 2 * t;
                atomicAdd(&csum[lc],     v00 + v10);
                atomicAdd(&csum[lc + 1], v01 + v11);
            }
        }
    }

    if (DO_POOL) {
        __syncthreads();
        if (tid < 128) {
            const int batch = (blockIdx.y * BM) / NSEQ;   // 9216 % 128 == 0
            atomicAdd(&pool[batch * CFEAT + blockIdx.x * BN + tid], csum[tid]);
        }
    }
}

// ---------------- LayerNorm over last dim (warp per row), tf32-rounded out ----
template<int H>
__global__ void ln_kernel(float* __restrict__ x, const float* __restrict__ g,
                          const float* __restrict__ be, int M)
{
    const int warp = threadIdx.x >> 5, lane = threadIdx.x & 31;
    const int row = blockIdx.x * (blockDim.x >> 5) + warp;
    if (row >= M) return;
    float* p = x + (size_t)row * H;
    constexpr int NV = H / 32;
    float v[NV];
    float s = 0.f;
#pragma unroll
    for (int i = 0; i < NV; i++) { v[i] = p[lane + (i << 5)]; s += v[i]; }
#pragma unroll
    for (int o = 16; o > 0; o >>= 1) s += __shfl_xor_sync(0xffffffffu, s, o);
    const float mu = s * (1.0f / H);
    float var = 0.f;
#pragma unroll
    for (int i = 0; i < NV; i++) { float d = v[i] - mu; var += d * d; }
#pragma unroll
    for (int o = 16; o > 0; o >>= 1) var += __shfl_xor_sync(0xffffffffu, var, o);
    const float rstd = rsqrtf(var * (1.0f / H) + 1e-5f);
#pragma unroll
    for (int i = 0; i < NV; i++) {
        const int c = lane + (i << 5);
        const float o = (v[i] - mu) * rstd * g[c] + be[c];
        p[c] = __uint_as_float(tf32_rna(o));   // pre-round for next tf32 GEMM
    }
}

// ---------------- SE channel attention ----------------
__global__ void se_kernel(const float* __restrict__ pool,
                          const float* __restrict__ w1, const float* __restrict__ b1,
                          const float* __restrict__ w2, const float* __restrict__ b2,
                          float* __restrict__ s)
{
    __shared__ float p[CFEAT];
    __shared__ float hid[RED];
    const int b = blockIdx.x, t = threadIdx.x;
    for (int i = t; i < CFEAT; i += 256) p[i] = pool[b * CFEAT + i] * (1.0f / NSEQ);
    __syncthreads();
    if (t < RED) {
        float a = b1[t];
        for (int c = 0; c < CFEAT; c++) a = fmaf(p[c], w1[c * RED + t], a);
        hid[t] = fmaxf(a, 0.f);
    }
    __syncthreads();
    for (int c = t; c < CFEAT; c += 256) {
        float a = b2[c];
        for (int h = 0; h < RED; h++) a = fmaf(hid[h], w2[h * CFEAT + c], a);
        s[b * CFEAT + c] = 1.0f / (1.0f + expf(-a));
    }
}

// ---------------- fused SE-scale + windowed self-attention ----------------
#define SDIM 1153
#define SSTR 33
#define ATTN_SMEM_BYTES ((32 * SDIM + 32 * SSTR) * (int)sizeof(float))

__global__ void __launch_bounds__(256)
attn_kernel(const float* __restrict__ y, const float* __restrict__ s,
            float* __restrict__ out)
{
    extern __shared__ float sm[];
    float* Ys = sm;                  // [32][SDIM]
    float* Ss = sm + 32 * SDIM;      // [32][SSTR]

    const int win = blockIdx.x;
    const int b = win / (NSEQ / WS);
    const size_t base = (size_t)win * 32;
    const int tid = threadIdx.x;
    const float* sb = s + b * CFEAT;

    for (int idx = tid; idx < 32 * (CFEAT / 4); idx += 256) {
        const int r = idx / (CFEAT / 4);
        const int c4 = (idx % (CFEAT / 4)) * 4;
        float4 v  = *(const float4*)(y + (base + r) * CFEAT + c4);
        float4 sv = *(const float4*)(sb + c4);
        Ys[r * SDIM + c4 + 0] = v.x * sv.x;
        Ys[r * SDIM + c4 + 1] = v.y * sv.y;
        Ys[r * SDIM + c4 + 2] = v.z * sv.z;
        Ys[r * SDIM + c4 + 3] = v.w * sv.w;
    }
    for (int i = tid; i < 32 * SSTR; i += 256) Ss[i] = 0.f;
    __syncthreads();

    {
        const int cg = tid >> 6;
        const int r8 = (tid >> 3) & 7;
        const int cl = tid & 7;
        float acc[4][4] = {};
        const int c0 = cg * (CFEAT / 4), c1 = c0 + (CFEAT / 4);
        for (int c = c0; c < c1; c++) {
            float qv[4], kv[4];
#pragma unroll
            for (int i = 0; i < 4; i++) qv[i] = Ys[(r8 * 4 + i) * SDIM + c];
#pragma unroll
            for (int j = 0; j < 4; j++) kv[j] = Ys[(cl * 4 + j) * SDIM + c];
#pragma unroll
            for (int i = 0; i < 4; i++)
#pragma unroll
                for (int j = 0; j < 4; j++)
                    acc[i][j] = fmaf(qv[i], kv[j], acc[i][j]);
        }
#pragma unroll
        for (int i = 0; i < 4; i++)
#pragma unroll
            for (int j = 0; j < 4; j++)
                atomicAdd(&Ss[(r8 * 4 + i) * SSTR + (cl * 4 + j)], acc[i][j]);
    }
    __syncthreads();

    {
        const int warp = tid >> 5, lane = tid & 31;
        const float scale = 1.0f / sqrtf((float)CFEAT);
        for (int q = warp; q < 32; q += 8) {
            float v = Ss[q * SSTR + lane] * scale;
            float m = v;
#pragma unroll
            for (int o = 16; o > 0; o >>= 1) m = fmaxf(m, __shfl_xor_sync(0xffffffffu, m, o));
            float e = expf(v - m);
            float sum = e;
#pragma unroll
            for (int o = 16; o > 0; o >>= 1) sum += __shfl_xor_sync(0xffffffffu, sum, o);
            Ss[q * SSTR + lane] = e / sum;
        }
    }
    __syncthreads();

    {
        const int qg = tid >> 6;
        const int ct = tid & 63;
        for (int gIdx = 0; gIdx < 3; gIdx++) {
            float acc[8][6];
#pragma unroll
            for (int i = 0; i < 8; i++)
#pragma unroll
                for (int u = 0; u < 6; u++) acc[i][u] = 0.f;
            for (int k = 0; k < 32; k++) {
                float sv[8];
#pragma unroll
                for (int i = 0; i < 8; i++) sv[i] = Ss[(qg * 8 + i) * SSTR + k];
#pragma unroll
                for (int u = 0; u < 6; u++) {
                    const int c = ct + ((gIdx * 6 + u) << 6);
                    const float yv = Ys[k * SDIM + c];
#pragma unroll
                    for (int i = 0; i < 8; i++) acc[i][u] = fmaf(sv[i], yv, acc[i][u]);
                }
            }
#pragma unroll
            for (int i = 0; i < 8; i++) {
                const size_t row = base + qg * 8 + i;
#pragma unroll
                for (int u = 0; u < 6; u++) {
                    const int c = ct + ((gIdx * 6 + u) << 6);
                    out[row * CFEAT + c] = acc[i][u];
                }
            }
        }
    }
}

// ---------------- launch ----------------
extern "C" void kernel_launch(void* const* d_in, const int* in_sizes, int n_in,
                              void* d_out, int out_size)
{
    const float* x    = (const float*)d_in[0];
    const float* W1   = (const float*)d_in[1];
    const float* b1   = (const float*)d_in[2];
    const float* g1   = (const float*)d_in[3];
    const float* be1  = (const float*)d_in[4];
    const float* W2   = (const float*)d_in[5];
    const float* b2   = (const float*)d_in[6];
    const float* g2   = (const float*)d_in[7];
    const float* be2  = (const float*)d_in[8];
    const float* W3   = (const float*)d_in[9];
    const float* b3   = (const float*)d_in[10];
    const float* g3   = (const float*)d_in[11];
    const float* be3  = (const float*)d_in[12];
    const float* Wo   = (const float*)d_in[13];
    const float* bo   = (const float*)d_in[14];
    const float* caw1 = (const float*)d_in[15];
    const float* cab1 = (const float*)d_in[16];
    const float* caw2 = (const float*)d_in[17];
    const float* cab2 = (const float*)d_in[18];
    float* out = (float*)d_out;

    float *h1p, *h2p, *h3p, *yp, *poolp, *sp;
    float *w1r, *w2r, *w3r, *wor;
    cudaGetSymbolAddress((void**)&h1p, g_h1);
    cudaGetSymbolAddress((void**)&h2p, g_h2);
    cudaGetSymbolAddress((void**)&h3p, g_h3);
    cudaGetSymbolAddress((void**)&yp,  g_y);
    cudaGetSymbolAddress((void**)&poolp, g_pool);
    cudaGetSymbolAddress((void**)&sp,  g_s);
    cudaGetSymbolAddress((void**)&w1r, g_w1r);
    cudaGetSymbolAddress((void**)&w2r, g_w2r);
    cudaGetSymbolAddress((void**)&w3r, g_w3r);
    cudaGetSymbolAddress((void**)&wor, g_wor);

    cudaFuncSetAttribute((const void*)mma_gemm<true, true, false>,
                         cudaFuncAttributeMaxDynamicSharedMemorySize, GEMM_SMEM_BYTES);
    cudaFuncSetAttribute((const void*)mma_gemm<true, false, false>,
                         cudaFuncAttributeMaxDynamicSharedMemorySize, GEMM_SMEM_BYTES);
    cudaFuncSetAttribute((const void*)mma_gemm<false, false, true>,
                         cudaFuncAttributeMaxDynamicSharedMemorySize, GEMM_SMEM_BYTES);
    cudaFuncSetAttribute((const void*)attn_kernel,
                         cudaFuncAttributeMaxDynamicSharedMemorySize, ATTN_SMEM_BYTES);

    cudaMemsetAsync(poolp, 0, NBATCH * CFEAT * sizeof(float));

    // prep: round weights to tf32 once per launch
    round_kernel<<<(CFEAT * HD1) / 256, 256>>>(W1, w1r, CFEAT * HD1);
    round_kernel<<<(HD1 * HD2) / 256, 256>>>(W2, w2r, HD1 * HD2);
    round_kernel<<<(HD2 * HD3) / 256, 256>>>(W3, w3r, HD2 * HD3);
    round_kernel<<<(HD3 * CFEAT) / 256, 256>>>(Wo, wor, HD3 * CFEAT);

    dim3 blk(256);
    // layer 1: LN(GELU(x @ W1 + b1)) — A needs in-loop tf32 rounding
    mma_gemm<true, true, false><<<dim3(HD1 / BN, MTOT / BM), blk, GEMM_SMEM_BYTES>>>(
        x, w1r, b1, h1p, MTOT, HD1, CFEAT, nullptr);
    ln_kernel<HD1><<<MTOT / 8, 256>>>(h1p, g1, be1, MTOT);
    // layer 2
    mma_gemm<true, false, false><<<dim3(HD2 / BN, MTOT / BM), blk, GEMM_SMEM_BYTES>>>(
        h1p, w2r, b2, h2p, MTOT, HD2, HD1, nullptr);
    ln_kernel<HD2><<<MTOT / 8, 256>>>(h2p, g2, be2, MTOT);
    // layer 3
    mma_gemm<true, false, false><<<dim3(HD3 / BN, MTOT / BM), blk, GEMM_SMEM_BYTES>>>(
        h2p, w3r, b3, h3p, MTOT, HD3, HD2, nullptr);
    ln_kernel<HD3><<<MTOT / 8, 256>>>(h3p, g3, be3, MTOT);
    // output projection + fused pooled column sums
    mma_gemm<false, false, true><<<dim3(CFEAT / BN, MTOT / BM), blk, GEMM_SMEM_BYTES>>>(
        h3p, wor, bo, yp, MTOT, CFEAT, HD3, poolp);
    // SE gate
    se_kernel<<<NBATCH, 256>>>(poolp, caw1, cab1, caw2, cab2, sp);
    // fused SE-scale + windowed attention -> final output
    attn_kernel<<<NWIN, 256, ATTN_SMEM_BYTES>>>(yp, sp, out);
}

// round 5
// speedup vs baseline: 2.5627x; 1.1140x over previous
#include <cuda_runtime.h>
#include <math.h>
#include <stdint.h>

// ---------------- problem constants ----------------
#define MTOT   73728          // B*N = 8*9216 rows
#define CFEAT  1152
#define HD1    768
#define HD2    512
#define HD3    256
#define RED    144            // 1152/8
#define NSEQ   9216
#define NBATCH 8
#define WS     32
#define NWIN   2304           // 8 * 9216/32

// ---------------- scratch (no cudaMalloc allowed) ----------------
__device__ float g_h1[(size_t)MTOT * HD1];
__device__ float g_h2[(size_t)MTOT * HD2];
__device__ float g_h3[(size_t)MTOT * HD3];
__device__ float g_y [(size_t)MTOT * CFEAT];
__device__ float g_pool[NBATCH * CFEAT];
__device__ float g_s   [NBATCH * CFEAT];
// transposed + tf32-rounded weights: [N][K]
__device__ float g_w1t[HD1 * CFEAT];
__device__ float g_w2t[HD2 * HD1];
__device__ float g_w3t[HD3 * HD2];
__device__ float g_wot[CFEAT * HD3];

__device__ __forceinline__ float gelu_exact(float x) {
    return 0.5f * x * (1.0f + erff(x * 0.70710678118654752f));
}
__device__ __forceinline__ uint32_t tf32_rna(float x) {
    uint32_t r;
    asm("cvt.rna.tf32.f32 %0, %1;" : "=r"(r) : "f"(x));
    return r;
}

__device__ __forceinline__ uint32_t smem_u32(const void* p) {
    uint32_t a;
    asm("{ .reg .u64 t; cvta.to.shared.u64 t, %1; cvt.u32.u64 %0, t; }" : "=r"(a) : "l"(p));
    return a;
}
__device__ __forceinline__ void cp16(uint32_t dst, const float* src) {
    asm volatile("cp.async.cg.shared.global [%0], [%1], 16;" :: "r"(dst), "l"(src));
}
#define CP_COMMIT() asm volatile("cp.async.commit_group;")
#define CP_WAIT0()  asm volatile("cp.async.wait_group 0;")
#define CP_WAIT1()  asm volatile("cp.async.wait_group 1;")

#define LDSM_X4(r, a) \
    asm volatile("ldmatrix.sync.aligned.m8n8.x4.shared.b16 {%0,%1,%2,%3}, [%4];" \
                 : "=r"((r)[0]), "=r"((r)[1]), "=r"((r)[2]), "=r"((r)[3]) : "r"(a))

__device__ __forceinline__ void mma_tf32(float* c, const uint32_t* a, const uint32_t* b) {
    asm volatile(
        "mma.sync.aligned.m16n8k8.row.col.f32.tf32.tf32.f32 "
        "{%0,%1,%2,%3}, {%4,%5,%6,%7}, {%8,%9}, {%0,%1,%2,%3};"
        : "+f"(c[0]), "+f"(c[1]), "+f"(c[2]), "+f"(c[3])
        : "r"(a[0]), "r"(a[1]), "r"(a[2]), "r"(a[3]), "r"(b[0]), "r"(b[1]));
}

// ---------------- prep: transpose + tf32-round weights ----------------
// dst[n][k] = rna(src[k][n]); src: K x N. grid (K/32, N/32), 256 thr.
__global__ void transpose_round(const float* __restrict__ src, float* __restrict__ dst,
                                int K, int N) {
    __shared__ float t[32][33];
    const int k0 = blockIdx.x * 32, n0 = blockIdx.y * 32;
    const int x = threadIdx.x & 31, y = threadIdx.x >> 5;
#pragma unroll
    for (int i = y; i < 32; i += 8)
        t[i][x] = src[(size_t)(k0 + i) * N + n0 + x];
    __syncthreads();
#pragma unroll
    for (int i = y; i < 32; i += 8)
        dst[(size_t)(n0 + i) * K + k0 + x] = __uint_as_float(tf32_rna(t[x][i]));
}

// ---------------- tf32 tensor-core GEMM (mma.sync + ldmatrix) ----------------
// C[M,N] = act(A @ Bt^T + bias); A: MxK row-major, Bt: NxK row-major (prerounded
// unless ROUND_A for A). Block 128x128x32, 8 warps (4x2), warp tile 32x64.
// Smem: 16B-chunk XOR swizzle (chunk u at row r stored at u^(r&7)); conflict-free
// for both cp.async stores and ldmatrix reads.
#define BM 128
#define BN 128
#define BK 32
#define STAGE_BYTES (128 * 128)        // 128 rows x 128B
#define GEMM_SMEM_BYTES (4 * STAGE_BYTES)   // A[2] + B[2] = 64KB

template<bool DO_GELU, bool ROUND_A, bool DO_POOL>
__global__ void __launch_bounds__(256, 2)
mma_gemm(const float* __restrict__ A, const float* __restrict__ Bt,
         const float* __restrict__ bias, float* __restrict__ Cout,
         int N, int K, float* __restrict__ pool)
{
    extern __shared__ __align__(128) char smem[];
    const uint32_t sb = smem_u32(smem);
    // stage s: A at sb + s*16KB, B at sb + 32KB + s*16KB

    const int tid = threadIdx.x;
    const int warp = tid >> 5, lane = tid & 31;
    const int wy = warp >> 1, wx = warp & 1;       // warp grid 4x2 -> 32x64 tile
    const int lr = lane & 7;

    // ldmatrix per-thread row/chunk selectors
    const int aRow0 = wy * 32 + ((lane >> 3) & 1) * 8 + lr;   // im=0 rows
    const int aCo   = lane >> 4;                              // 0/1 -> k-chunk +0/+1
    const int bCo   = (lane >> 3) & 1;
    const int bRowB = wx * 64 + ((lane >> 4) & 1) * 8 + lr;   // + p*16

    // gmem loader mapping: i = tid + j*256 -> row i>>3, 16B chunk i&7
    const int gr = tid >> 3, gu = tid & 7;
    const float* Abase = A  + (size_t)(blockIdx.y * BM) * K;
    const float* Bbase = Bt + (size_t)(blockIdx.x * BN) * K;

    float acc[2][8][4];
#pragma unroll
    for (int im = 0; im < 2; im++)
#pragma unroll
        for (int in = 0; in < 8; in++)
#pragma unroll
            for (int c = 0; c < 4; c++) acc[im][in][c] = 0.f;

    const int nk = K >> 5;

    // prologue: stage 0
    {
        const uint32_t ad = sb, bd = sb + 2 * STAGE_BYTES;
#pragma unroll
        for (int j = 0; j < 4; j++) {
            const int r = gr + j * 32;
            const uint32_t off = ((uint32_t)r << 7) + (uint32_t)((gu ^ (r & 7)) << 4);
            cp16(ad + off, Abase + (size_t)r * K + (gu << 2));
            cp16(bd + off, Bbase + (size_t)r * K + (gu << 2));
        }
        CP_COMMIT();
    }

    for (int kt = 0; kt < nk; kt++) {
        const int buf = kt & 1;
        if (kt + 1 < nk) {
            const int k0 = (kt + 1) << 5;
            const uint32_t ad = sb + (buf ^ 1) * STAGE_BYTES;
            const uint32_t bd = sb + (2 + (buf ^ 1)) * STAGE_BYTES;
#pragma unroll
            for (int j = 0; j < 4; j++) {
                const int r = gr + j * 32;
                const uint32_t off = ((uint32_t)r << 7) + (uint32_t)((gu ^ (r & 7)) << 4);
                cp16(ad + off, Abase + (size_t)r * K + k0 + (gu << 2));
                cp16(bd + off, Bbase + (size_t)r * K + k0 + (gu << 2));
            }
            CP_COMMIT();
            CP_WAIT1();
        } else {
            CP_WAIT0();
        }
        __syncthreads();

        const uint32_t aB = sb + buf * STAGE_BYTES;
        const uint32_t bB = sb + (2 + buf) * STAGE_BYTES;
#pragma unroll
        for (int ks = 0; ks < 4; ks++) {
            const uint32_t ca = aB + (uint32_t)(((2 * ks + aCo) ^ lr) << 4);
            const uint32_t cb = bB + (uint32_t)(((2 * ks + bCo) ^ lr) << 4);
            uint32_t af[2][4];
            LDSM_X4(af[0], ca + ((uint32_t)aRow0 << 7));
            LDSM_X4(af[1], ca + ((uint32_t)(aRow0 + 16) << 7));
            if (ROUND_A) {
#pragma unroll
                for (int im = 0; im < 2; im++)
#pragma unroll
                    for (int q = 0; q < 4; q++)
                        af[im][q] = tf32_rna(__uint_as_float(af[im][q]));
            }
            uint32_t bf[4][4];
#pragma unroll
            for (int p = 0; p < 4; p++)
                LDSM_X4(bf[p], cb + ((uint32_t)(bRowB + p * 16) << 7));
#pragma unroll
            for (int im = 0; im < 2; im++)
#pragma unroll
                for (int p = 0; p < 4; p++) {
                    mma_tf32(acc[im][2 * p],     af[im], &bf[p][0]);
                    mma_tf32(acc[im][2 * p + 1], af[im], &bf[p][2]);
                }
        }
        __syncthreads();
    }

    // ---- epilogue: bias (+gelu), store; optional pooled column sums ----
    const int g = lane >> 2, t = lane & 3;
    float* csum = (float*)smem;
    if (DO_POOL) {
        if (tid < 128) csum[tid] = 0.f;
        __syncthreads();
    }

#pragma unroll
    for (int im = 0; im < 2; im++) {
        const int r0 = blockIdx.y * BM + wy * 32 + im * 16 + g;
#pragma unroll
        for (int in = 0; in < 8; in++) {
            const int col = blockIdx.x * BN + wx * 64 + in * 8 + 2 * t;
            const float bv0 = bias[col], bv1 = bias[col + 1];
            float v00 = acc[im][in][0] + bv0;
            float v01 = acc[im][in][1] + bv1;
            float v10 = acc[im][in][2] + bv0;
            float v11 = acc[im][in][3] + bv1;
            if (DO_GELU) {
                v00 = gelu_exact(v00); v01 = gelu_exact(v01);
                v10 = gelu_exact(v10); v11 = gelu_exact(v11);
            }
            *(float2*)(Cout + (size_t)r0 * N + col)       = make_float2(v00, v01);
            *(float2*)(Cout + (size_t)(r0 + 8) * N + col) = make_float2(v10, v11);
            if (DO_POOL) {
                const int lc = wx * 64 + in * 8 + 2 * t;
                atomicAdd(&csum[lc],     v00 + v10);
                atomicAdd(&csum[lc + 1], v01 + v11);
            }
        }
    }

    if (DO_POOL) {
        __syncthreads();
        if (tid < 128) {
            const int batch = (blockIdx.y * BM) / NSEQ;   // 9216 % 128 == 0
            atomicAdd(&pool[batch * CFEAT + blockIdx.x * BN + tid], csum[tid]);
        }
    }
}

// ---------------- LayerNorm (warp per row), tf32-rounded out ----------------
template<int H>
__global__ void ln_kernel(float* __restrict__ x, const float* __restrict__ g,
                          const float* __restrict__ be, int M)
{
    const int warp = threadIdx.x >> 5, lane = threadIdx.x & 31;
    const int row = blockIdx.x * (blockDim.x >> 5) + warp;
    if (row >= M) return;
    float* p = x + (size_t)row * H;
    constexpr int NV = H / 32;
    float v[NV];
    float s = 0.f;
#pragma unroll
    for (int i = 0; i < NV; i++) { v[i] = p[lane + (i << 5)]; s += v[i]; }
#pragma unroll
    for (int o = 16; o > 0; o >>= 1) s += __shfl_xor_sync(0xffffffffu, s, o);
    const float mu = s * (1.0f / H);
    float var = 0.f;
#pragma unroll
    for (int i = 0; i < NV; i++) { float d = v[i] - mu; var += d * d; }
#pragma unroll
    for (int o = 16; o > 0; o >>= 1) var += __shfl_xor_sync(0xffffffffu, var, o);
    const float rstd = rsqrtf(var * (1.0f / H) + 1e-5f);
#pragma unroll
    for (int i = 0; i < NV; i++) {
        const int c = lane + (i << 5);
        const float o = (v[i] - mu) * rstd * g[c] + be[c];
        p[c] = __uint_as_float(tf32_rna(o));   // pre-round for next tf32 GEMM
    }
}

// ---------------- SE channel attention ----------------
__global__ void se_kernel(const float* __restrict__ pool,
                          const float* __restrict__ w1, const float* __restrict__ b1,
                          const float* __restrict__ w2, const float* __restrict__ b2,
                          float* __restrict__ s)
{
    __shared__ float p[CFEAT];
    __shared__ float hid[RED];
    const int b = blockIdx.x, t = threadIdx.x;
    for (int i = t; i < CFEAT; i += 256) p[i] = pool[b * CFEAT + i] * (1.0f / NSEQ);
    __syncthreads();
    if (t < RED) {
        float a = b1[t];
        for (int c = 0; c < CFEAT; c++) a = fmaf(p[c], w1[c * RED + t], a);
        hid[t] = fmaxf(a, 0.f);
    }
    __syncthreads();
    for (int c = t; c < CFEAT; c += 256) {
        float a = b2[c];
        for (int h = 0; h < RED; h++) a = fmaf(hid[h], w2[h * CFEAT + c], a);
        s[b * CFEAT + c] = 1.0f / (1.0f + expf(-a));
    }
}

// ---------------- fused SE-scale + windowed self-attention ----------------
#define SDIM 1153
#define SSTR 33
#define ATTN_SMEM_BYTES ((32 * SDIM + 32 * SSTR) * (int)sizeof(float))

__global__ void __launch_bounds__(256)
attn_kernel(const float* __restrict__ y, const float* __restrict__ s,
            float* __restrict__ out)
{
    extern __shared__ float sm[];
    float* Ys = sm;                  // [32][SDIM]
    float* Ss = sm + 32 * SDIM;      // [32][SSTR]

    const int win = blockIdx.x;
    const int b = win / (NSEQ / WS);
    const size_t base = (size_t)win * 32;
    const int tid = threadIdx.x;
    const float* sb = s + b * CFEAT;

    for (int idx = tid; idx < 32 * (CFEAT / 4); idx += 256) {
        const int r = idx / (CFEAT / 4);
        const int c4 = (idx % (CFEAT / 4)) * 4;
        float4 v  = *(const float4*)(y + (base + r) * CFEAT + c4);
        float4 sv = *(const float4*)(sb + c4);
        Ys[r * SDIM + c4 + 0] = v.x * sv.x;
        Ys[r * SDIM + c4 + 1] = v.y * sv.y;
        Ys[r * SDIM + c4 + 2] = v.z * sv.z;
        Ys[r * SDIM + c4 + 3] = v.w * sv.w;
    }
    for (int i = tid; i < 32 * SSTR; i += 256) Ss[i] = 0.f;
    __syncthreads();

    {
        const int cg = tid >> 6;
        const int r8 = (tid >> 3) & 7;
        const int cl = tid & 7;
        float acc[4][4] = {};
        const int c0 = cg * (CFEAT / 4), c1 = c0 + (CFEAT / 4);
        for (int c = c0; c < c1; c++) {
            float qv[4], kv[4];
#pragma unroll
            for (int i = 0; i < 4; i++) qv[i] = Ys[(r8 * 4 + i) * SDIM + c];
#pragma unroll
            for (int j = 0; j < 4; j++) kv[j] = Ys[(cl * 4 + j) * SDIM + c];
#pragma unroll
            for (int i = 0; i < 4; i++)
#pragma unroll
                for (int j = 0; j < 4; j++)
                    acc[i][j] = fmaf(qv[i], kv[j], acc[i][j]);
        }
#pragma unroll
        for (int i = 0; i < 4; i++)
#pragma unroll
            for (int j = 0; j < 4; j++)
                atomicAdd(&Ss[(r8 * 4 + i) * SSTR + (cl * 4 + j)], acc[i][j]);
    }
    __syncthreads();

    {
        const int warp = tid >> 5, lane = tid & 31;
        const float scale = 1.0f / sqrtf((float)CFEAT);
        for (int q = warp; q < 32; q += 8) {
            float v = Ss[q * SSTR + lane] * scale;
            float m = v;
#pragma unroll
            for (int o = 16; o > 0; o >>= 1) m = fmaxf(m, __shfl_xor_sync(0xffffffffu, m, o));
            float e = expf(v - m);
            float sum = e;
#pragma unroll
            for (int o = 16; o > 0; o >>= 1) sum += __shfl_xor_sync(0xffffffffu, sum, o);
            Ss[q * SSTR + lane] = e / sum;
        }
    }
    __syncthreads();

    {
        const int qg = tid >> 6;
        const int ct = tid & 63;
        for (int gIdx = 0; gIdx < 3; gIdx++) {
            float acc[8][6];
#pragma unroll
            for (int i = 0; i < 8; i++)
#pragma unroll
                for (int u = 0; u < 6; u++) acc[i][u] = 0.f;
            for (int k = 0; k < 32; k++) {
                float sv[8];
#pragma unroll
                for (int i = 0; i < 8; i++) sv[i] = Ss[(qg * 8 + i) * SSTR + k];
#pragma unroll
                for (int u = 0; u < 6; u++) {
                    const int c = ct + ((gIdx * 6 + u) << 6);
                    const float yv = Ys[k * SDIM + c];
#pragma unroll
                    for (int i = 0; i < 8; i++) acc[i][u] = fmaf(sv[i], yv, acc[i][u]);
                }
            }
#pragma unroll
            for (int i = 0; i < 8; i++) {
                const size_t row = base + qg * 8 + i;
#pragma unroll
                for (int u = 0; u < 6; u++) {
                    const int c = ct + ((gIdx * 6 + u) << 6);
                    out[row * CFEAT + c] = acc[i][u];
                }
            }
        }
    }
}

// ---------------- launch ----------------
extern "C" void kernel_launch(void* const* d_in, const int* in_sizes, int n_in,
                              void* d_out, int out_size)
{
    const float* x    = (const float*)d_in[0];
    const float* W1   = (const float*)d_in[1];
    const float* b1   = (const float*)d_in[2];
    const float* g1   = (const float*)d_in[3];
    const float* be1  = (const float*)d_in[4];
    const float* W2   = (const float*)d_in[5];
    const float* b2   = (const float*)d_in[6];
    const float* g2   = (const float*)d_in[7];
    const float* be2  = (const float*)d_in[8];
    const float* W3   = (const float*)d_in[9];
    const float* b3   = (const float*)d_in[10];
    const float* g3   = (const float*)d_in[11];
    const float* be3  = (const float*)d_in[12];
    const float* Wo   = (const float*)d_in[13];
    const float* bo   = (const float*)d_in[14];
    const float* caw1 = (const float*)d_in[15];
    const float* cab1 = (const float*)d_in[16];
    const float* caw2 = (const float*)d_in[17];
    const float* cab2 = (const float*)d_in[18];
    float* out = (float*)d_out;

    float *h1p, *h2p, *h3p, *yp, *poolp, *sp;
    float *w1t, *w2t, *w3t, *wot;
    cudaGetSymbolAddress((void**)&h1p, g_h1);
    cudaGetSymbolAddress((void**)&h2p, g_h2);
    cudaGetSymbolAddress((void**)&h3p, g_h3);
    cudaGetSymbolAddress((void**)&yp,  g_y);
    cudaGetSymbolAddress((void**)&poolp, g_pool);
    cudaGetSymbolAddress((void**)&sp,  g_s);
    cudaGetSymbolAddress((void**)&w1t, g_w1t);
    cudaGetSymbolAddress((void**)&w2t, g_w2t);
    cudaGetSymbolAddress((void**)&w3t, g_w3t);
    cudaGetSymbolAddress((void**)&wot, g_wot);

    cudaFuncSetAttribute((const void*)mma_gemm<true, true, false>,
                         cudaFuncAttributeMaxDynamicSharedMemorySize, GEMM_SMEM_BYTES);
    cudaFuncSetAttribute((const void*)mma_gemm<true, false, false>,
                         cudaFuncAttributeMaxDynamicSharedMemorySize, GEMM_SMEM_BYTES);
    cudaFuncSetAttribute((const void*)mma_gemm<false, false, true>,
                         cudaFuncAttributeMaxDynamicSharedMemorySize, GEMM_SMEM_BYTES);
    cudaFuncSetAttribute((const void*)attn_kernel,
                         cudaFuncAttributeMaxDynamicSharedMemorySize, ATTN_SMEM_BYTES);

    cudaMemsetAsync(poolp, 0, NBATCH * CFEAT * sizeof(float));

    // prep: transpose + tf32-round weights into [N][K]
    transpose_round<<<dim3(CFEAT / 32, HD1 / 32), 256>>>(W1, w1t, CFEAT, HD1);
    transpose_round<<<dim3(HD1 / 32, HD2 / 32), 256>>>(W2, w2t, HD1, HD2);
    transpose_round<<<dim3(HD2 / 32, HD3 / 32), 256>>>(W3, w3t, HD2, HD3);
    transpose_round<<<dim3(HD3 / 32, CFEAT / 32), 256>>>(Wo, wot, HD3, CFEAT);

    dim3 blk(256);
    // layer 1: LN(GELU(x @ W1 + b1)) — A rounded in-register
    mma_gemm<true, true, false><<<dim3(HD1 / BN, MTOT / BM), blk, GEMM_SMEM_BYTES>>>(
        x, w1t, b1, h1p, HD1, CFEAT, nullptr);
    ln_kernel<HD1><<<MTOT / 8, 256>>>(h1p, g1, be1, MTOT);
    // layer 2
    mma_gemm<true, false, false><<<dim3(HD2 / BN, MTOT / BM), blk, GEMM_SMEM_BYTES>>>(
        h1p, w2t, b2, h2p, HD2, HD1, nullptr);
    ln_kernel<HD2><<<MTOT / 8, 256>>>(h2p, g2, be2, MTOT);
    // layer 3
    mma_gemm<true, false, false><<<dim3(HD3 / BN, MTOT / BM), blk, GEMM_SMEM_BYTES>>>(
        h2p, w3t, b3, h3p, HD3, HD2, nullptr);
    ln_kernel<HD3><<<MTOT / 8, 256>>>(h3p, g3, be3, MTOT);
    // output projection + fused pooled column sums
    mma_gemm<false, false, true><<<dim3(CFEAT / BN, MTOT / BM), blk, GEMM_SMEM_BYTES>>>(
        h3p, wot, bo, yp, CFEAT, HD3, poolp);
    // SE gate
    se_kernel<<<NBATCH, 256>>>(poolp, caw1, cab1, caw2, cab2, sp);
    // fused SE-scale + windowed attention -> final output
    attn_kernel<<<NWIN, 256, ATTN_SMEM_BYTES>>>(yp, sp, out);
}

// round 6
// speedup vs baseline: 3.2965x; 1.2863x over previous
#include <cuda_runtime.h>
#include <cuda_fp16.h>
#include <math.h>
#include <stdint.h>

// ---------------- problem constants ----------------
#define MTOT   73728          // B*N = 8*9216 rows
#define CFEAT  1152
#define HD1    768
#define HD2    512
#define HD3    256
#define RED    144            // 1152/8
#define NSEQ   9216
#define NBATCH 8
#define WS     32
#define NWIN   2304           // 8 * 9216/32

// ---------------- scratch (no cudaMalloc allowed) ----------------
__device__ float  g_h1[(size_t)MTOT * HD1];     // GEMM1 out (fp32, LN input)
__device__ float  g_h2[(size_t)MTOT * HD2];
__device__ float  g_h3[(size_t)MTOT * HD3];
__device__ float  g_y [(size_t)MTOT * CFEAT];   // GEMM4 out
__device__ float  g_pool[NBATCH * CFEAT];
__device__ float  g_s   [NBATCH * CFEAT];
// fp16 GEMM inputs
__device__ __half g_xh [(size_t)MTOT * CFEAT];
__device__ __half g_h1h[(size_t)MTOT * HD1];
__device__ __half g_h2h[(size_t)MTOT * HD2];
__device__ __half g_h3h[(size_t)MTOT * HD3];
// transposed fp16 weights: [N][K]
__device__ __half g_w1h[HD1 * CFEAT];
__device__ __half g_w2h[HD2 * HD1];
__device__ __half g_w3h[HD3 * HD2];
__device__ __half g_woh[CFEAT * HD3];

__device__ __forceinline__ float gelu_exact(float x) {
    return 0.5f * x * (1.0f + erff(x * 0.70710678118654752f));
}

__device__ __forceinline__ uint32_t smem_u32(const void* p) {
    uint32_t a;
    asm("{ .reg .u64 t; cvta.to.shared.u64 t, %1; cvt.u32.u64 %0, t; }" : "=r"(a) : "l"(p));
    return a;
}
__device__ __forceinline__ void cp16(uint32_t dst, const void* src) {
    asm volatile("cp.async.cg.shared.global [%0], [%1], 16;" :: "r"(dst), "l"(src));
}
#define CP_COMMIT() asm volatile("cp.async.commit_group;")
#define CP_WAIT0()  asm volatile("cp.async.wait_group 0;")
#define CP_WAIT1()  asm volatile("cp.async.wait_group 1;")

#define LDSM_X4(r, a) \
    asm volatile("ldmatrix.sync.aligned.m8n8.x4.shared.b16 {%0,%1,%2,%3}, [%4];" \
                 : "=r"((r)[0]), "=r"((r)[1]), "=r"((r)[2]), "=r"((r)[3]) : "r"(a))

__device__ __forceinline__ void mma_f16(float* c, const uint32_t* a,
                                        uint32_t b0, uint32_t b1) {
    asm volatile(
        "mma.sync.aligned.m16n8k16.row.col.f32.f16.f16.f32 "
        "{%0,%1,%2,%3}, {%4,%5,%6,%7}, {%8,%9}, {%0,%1,%2,%3};"
        : "+f"(c[0]), "+f"(c[1]), "+f"(c[2]), "+f"(c[3])
        : "r"(a[0]), "r"(a[1]), "r"(a[2]), "r"(a[3]), "r"(b0), "r"(b1));
}

// ---------------- prep: fp32 -> fp16 convert ----------------
__global__ void f2h_kernel(const float4* __restrict__ src, uint4* __restrict__ dst, int n8) {
    const int i = blockIdx.x * 256 + threadIdx.x;
    if (i < n8) {
        float4 a = src[2 * i], b = src[2 * i + 1];
        __half2 h0 = __floats2half2_rn(a.x, a.y);
        __half2 h1 = __floats2half2_rn(a.z, a.w);
        __half2 h2 = __floats2half2_rn(b.x, b.y);
        __half2 h3 = __floats2half2_rn(b.z, b.w);
        uint4 o;
        o.x = *(uint32_t*)&h0; o.y = *(uint32_t*)&h1;
        o.z = *(uint32_t*)&h2; o.w = *(uint32_t*)&h3;
        dst[i] = o;
    }
}

// prep: dst[n][k] = (half)src[k][n]; src: K x N fp32. grid (K/32, N/32), 256 thr.
__global__ void transpose_half(const float* __restrict__ src, __half* __restrict__ dst,
                               int K, int N) {
    __shared__ float t[32][33];
    const int k0 = blockIdx.x * 32, n0 = blockIdx.y * 32;
    const int x = threadIdx.x & 31, y = threadIdx.x >> 5;
#pragma unroll
    for (int i = y; i < 32; i += 8)
        t[i][x] = src[(size_t)(k0 + i) * N + n0 + x];
    __syncthreads();
#pragma unroll
    for (int i = y; i < 32; i += 8)
        dst[(size_t)(n0 + i) * K + k0 + x] = __float2half_rn(t[x][i]);
}

// ---------------- fp16 tensor-core GEMM (mma.sync m16n8k16 + ldmatrix) --------
// C[M,N] = act(A @ Bt^T + bias); A: MxK fp16 row-major, Bt: NxK fp16 row-major.
// Block 128x128, BK=64 (128B rows), 8 warps (4x2), warp tile 32x64, 2 stages.
// Smem 16B-chunk XOR swizzle: chunk u of row r at u^(r&7). Conflict-free for
// cp.async stores and ldmatrix reads.
#define BM 128
#define BN 128
#define BK 64
#define STAGE_BYTES (128 * 128)            // 128 rows x 128B (64 fp16)
#define GEMM_SMEM_BYTES (4 * STAGE_BYTES)  // A[2] + B[2] = 64KB

template<bool DO_GELU, bool DO_POOL>
__global__ void __launch_bounds__(256, 2)
mma_gemm(const __half* __restrict__ A, const __half* __restrict__ Bt,
         const float* __restrict__ bias, float* __restrict__ Cout,
         int N, int K, float* __restrict__ pool)
{
    extern __shared__ __align__(128) char smem[];
    const uint32_t sb = smem_u32(smem);

    const int tid = threadIdx.x;
    const int warp = tid >> 5, lane = tid & 31;
    const int wy = warp >> 1, wx = warp & 1;       // 4x2 warp grid, 32x64 tile

    // ldmatrix per-thread selectors
    const int aRow0 = wy * 32 + (lane & 7) + 8 * ((lane >> 3) & 1); // +16 for im=1
    const int aCsel = lane >> 4;                                    // chunk +0/+1
    const int bRow0 = wx * 64 + (lane & 7) + 8 * ((lane >> 4) & 1); // +16*p
    const int bCsel = (lane >> 3) & 1;

    // gmem loader: row gr, 16B chunk gu (8 fp16)
    const int gr = tid >> 3, gu = tid & 7;
    const __half* Abase = A  + (size_t)(blockIdx.y * BM) * K;
    const __half* Bbase = Bt + (size_t)(blockIdx.x * BN) * K;

    float acc[2][8][4];
#pragma unroll
    for (int im = 0; im < 2; im++)
#pragma unroll
        for (int in = 0; in < 8; in++)
#pragma unroll
            for (int c = 0; c < 4; c++) acc[im][in][c] = 0.f;

    const int nk = K >> 6;   // BK=64

    // prologue: stage 0
    {
        const uint32_t ad = sb, bd = sb + 2 * STAGE_BYTES;
#pragma unroll
        for (int j = 0; j < 4; j++) {
            const int r = gr + j * 32;
            const uint32_t off = ((uint32_t)r << 7) + (uint32_t)((gu ^ (r & 7)) << 4);
            cp16(ad + off, Abase + (size_t)r * K + (gu << 3));
            cp16(bd + off, Bbase + (size_t)r * K + (gu << 3));
        }
        CP_COMMIT();
    }

    for (int kt = 0; kt < nk; kt++) {
        const int buf = kt & 1;
        if (kt + 1 < nk) {
            const int k0 = (kt + 1) << 6;
            const uint32_t ad = sb + (buf ^ 1) * STAGE_BYTES;
            const uint32_t bd = sb + (2 + (buf ^ 1)) * STAGE_BYTES;
#pragma unroll
            for (int j = 0; j < 4; j++) {
                const int r = gr + j * 32;
                const uint32_t off = ((uint32_t)r << 7) + (uint32_t)((gu ^ (r & 7)) << 4);
                cp16(ad + off, Abase + (size_t)r * K + k0 + (gu << 3));
                cp16(bd + off, Bbase + (size_t)r * K + k0 + (gu << 3));
            }
            CP_COMMIT();
            CP_WAIT1();
        } else {
            CP_WAIT0();
        }
        __syncthreads();

        const uint32_t aB = sb + buf * STAGE_BYTES;
        const uint32_t bB = sb + (2 + buf) * STAGE_BYTES;
#pragma unroll
        for (int j = 0; j < 4; j++) {           // 4 k16 steps per BK=64
            const int c0 = 2 * j;
            uint32_t af[2][4];
#pragma unroll
            for (int im = 0; im < 2; im++) {
                const int row = aRow0 + im * 16;
                const uint32_t addr = aB + ((uint32_t)row << 7)
                                    + (uint32_t)(((c0 + aCsel) ^ (row & 7)) << 4);
                LDSM_X4(af[im], addr);
            }
            uint32_t bf[4][4];
#pragma unroll
            for (int p = 0; p < 4; p++) {
                const int row = bRow0 + p * 16;
                const uint32_t addr = bB + ((uint32_t)row << 7)
                                    + (uint32_t)(((c0 + bCsel) ^ (row & 7)) << 4);
                LDSM_X4(bf[p], addr);
            }
#pragma unroll
            for (int im = 0; im < 2; im++)
#pragma unroll
                for (int p = 0; p < 4; p++) {
                    mma_f16(acc[im][2 * p],     af[im], bf[p][0], bf[p][1]);
                    mma_f16(acc[im][2 * p + 1], af[im], bf[p][2], bf[p][3]);
                }
        }
        __syncthreads();
    }

    // ---- epilogue: bias (+gelu), fp32 store; optional pooled column sums ----
    const int g = lane >> 2, t = lane & 3;
    float* csum = (float*)smem;
    if (DO_POOL) {
        if (tid < 128) csum[tid] = 0.f;
        __syncthreads();
    }

#pragma unroll
    for (int im = 0; im < 2; im++) {
        const int r0 = blockIdx.y * BM + wy * 32 + im * 16 + g;
#pragma unroll
        for (int in = 0; in < 8; in++) {
            const int col = blockIdx.x * BN + wx * 64 + in * 8 + 2 * t;
            const float bv0 = bias[col], bv1 = bias[col + 1];
            float v00 = acc[im][in][0] + bv0;
            float v01 = acc[im][in][1] + bv1;
            float v10 = acc[im][in][2] + bv0;
            float v11 = acc[im][in][3] + bv1;
            if (DO_GELU) {
                v00 = gelu_exact(v00); v01 = gelu_exact(v01);
                v10 = gelu_exact(v10); v11 = gelu_exact(v11);
            }
            *(float2*)(Cout + (size_t)r0 * N + col)       = make_float2(v00, v01);
            *(float2*)(Cout + (size_t)(r0 + 8) * N + col) = make_float2(v10, v11);
            if (DO_POOL) {
                const int lc = wx * 64 + in * 8 + 2 * t;
                atomicAdd(&csum[lc],     v00 + v10);
                atomicAdd(&csum[lc + 1], v01 + v11);
            }
        }
    }

    if (DO_POOL) {
        __syncthreads();
        if (tid < 128) {
            const int batch = (blockIdx.y * BM) / NSEQ;   // 9216 % 128 == 0
            atomicAdd(&pool[batch * CFEAT + blockIdx.x * BN + tid], csum[tid]);
        }
    }
}

// ---------------- LayerNorm (warp per row): fp32 in -> fp16 out ----------------
template<int H>
__global__ void ln_kernel(const float* __restrict__ x, __half* __restrict__ xo,
                          const float* __restrict__ g, const float* __restrict__ be,
                          int M)
{
    const int warp = threadIdx.x >> 5, lane = threadIdx.x & 31;
    const int row = blockIdx.x * (blockDim.x >> 5) + warp;
    if (row >= M) return;
    const float* p = x + (size_t)row * H;
    __half* po = xo + (size_t)row * H;
    constexpr int NV = H / 32;
    float v[NV];
    float s = 0.f;
#pragma unroll
    for (int i = 0; i < NV; i++) { v[i] = p[lane + (i << 5)]; s += v[i]; }
#pragma unroll
    for (int o = 16; o > 0; o >>= 1) s += __shfl_xor_sync(0xffffffffu, s, o);
    const float mu = s * (1.0f / H);
    float var = 0.f;
#pragma unroll
    for (int i = 0; i < NV; i++) { float d = v[i] - mu; var += d * d; }
#pragma unroll
    for (int o = 16; o > 0; o >>= 1) var += __shfl_xor_sync(0xffffffffu, var, o);
    const float rstd = rsqrtf(var * (1.0f / H) + 1e-5f);
#pragma unroll
    for (int i = 0; i < NV; i++) {
        const int c = lane + (i << 5);
        po[c] = __float2half_rn((v[i] - mu) * rstd * g[c] + be[c]);
    }
}

// ---------------- SE channel attention ----------------
__global__ void se_kernel(const float* __restrict__ pool,
                          const float* __restrict__ w1, const float* __restrict__ b1,
                          const float* __restrict__ w2, const float* __restrict__ b2,
                          float* __restrict__ s)
{
    __shared__ float p[CFEAT];
    __shared__ float hid[RED];
    const int b = blockIdx.x, t = threadIdx.x;
    for (int i = t; i < CFEAT; i += 256) p[i] = pool[b * CFEAT + i] * (1.0f / NSEQ);
    __syncthreads();
    if (t < RED) {
        float a = b1[t];
        for (int c = 0; c < CFEAT; c++) a = fmaf(p[c], w1[c * RED + t], a);
        hid[t] = fmaxf(a, 0.f);
    }
    __syncthreads();
    for (int c = t; c < CFEAT; c += 256) {
        float a = b2[c];
        for (int h = 0; h < RED; h++) a = fmaf(hid[h], w2[h * CFEAT + c], a);
        s[b * CFEAT + c] = 1.0f / (1.0f + expf(-a));
    }
}

// ---------------- fused SE-scale + windowed self-attention ----------------
#define SDIM 1153
#define SSTR 33
#define ATTN_SMEM_BYTES ((32 * SDIM + 32 * SSTR) * (int)sizeof(float))

__global__ void __launch_bounds__(256)
attn_kernel(const float* __restrict__ y, const float* __restrict__ s,
            float* __restrict__ out)
{
    extern __shared__ float sm[];
    float* Ys = sm;                  // [32][SDIM]
    float* Ss = sm + 32 * SDIM;      // [32][SSTR]

    const int win = blockIdx.x;
    const int b = win / (NSEQ / WS);
    const size_t base = (size_t)win * 32;
    const int tid = threadIdx.x;
    const float* sb = s + b * CFEAT;

    for (int idx = tid; idx < 32 * (CFEAT / 4); idx += 256) {
        const int r = idx / (CFEAT / 4);
        const int c4 = (idx % (CFEAT / 4)) * 4;
        float4 v  = *(const float4*)(y + (base + r) * CFEAT + c4);
        float4 sv = *(const float4*)(sb + c4);
        Ys[r * SDIM + c4 + 0] = v.x * sv.x;
        Ys[r * SDIM + c4 + 1] = v.y * sv.y;
        Ys[r * SDIM + c4 + 2] = v.z * sv.z;
        Ys[r * SDIM + c4 + 3] = v.w * sv.w;
    }
    for (int i = tid; i < 32 * SSTR; i += 256) Ss[i] = 0.f;
    __syncthreads();

    {
        const int cg = tid >> 6;
        const int r8 = (tid >> 3) & 7;
        const int cl = tid & 7;
        float acc[4][4] = {};
        const int c0 = cg * (CFEAT / 4), c1 = c0 + (CFEAT / 4);
        for (int c = c0; c < c1; c++) {
            float qv[4], kv[4];
#pragma unroll
            for (int i = 0; i < 4; i++) qv[i] = Ys[(r8 * 4 + i) * SDIM + c];
#pragma unroll
            for (int j = 0; j < 4; j++) kv[j] = Ys[(cl * 4 + j) * SDIM + c];
#pragma unroll
            for (int i = 0; i < 4; i++)
#pragma unroll
                for (int j = 0; j < 4; j++)
                    acc[i][j] = fmaf(qv[i], kv[j], acc[i][j]);
        }
#pragma unroll
        for (int i = 0; i < 4; i++)
#pragma unroll
            for (int j = 0; j < 4; j++)
                atomicAdd(&Ss[(r8 * 4 + i) * SSTR + (cl * 4 + j)], acc[i][j]);
    }
    __syncthreads();

    {
        const int warp = tid >> 5, lane = tid & 31;
        const float scale = 1.0f / sqrtf((float)CFEAT);
        for (int q = warp; q < 32; q += 8) {
            float v = Ss[q * SSTR + lane] * scale;
            float m = v;
#pragma unroll
            for (int o = 16; o > 0; o >>= 1) m = fmaxf(m, __shfl_xor_sync(0xffffffffu, m, o));
            float e = expf(v - m);
            float sum = e;
#pragma unroll
            for (int o = 16; o > 0; o >>= 1) sum += __shfl_xor_sync(0xffffffffu, sum, o);
            Ss[q * SSTR + lane] = e / sum;
        }
    }
    __syncthreads();

    {
        const int qg = tid >> 6;
        const int ct = tid & 63;
        for (int gIdx = 0; gIdx < 3; gIdx++) {
            float acc[8][6];
#pragma unroll
            for (int i = 0; i < 8; i++)
#pragma unroll
                for (int u = 0; u < 6; u++) acc[i][u] = 0.f;
            for (int k = 0; k < 32; k++) {
                float sv[8];
#pragma unroll
                for (int i = 0; i < 8; i++) sv[i] = Ss[(qg * 8 + i) * SSTR + k];
#pragma unroll
                for (int u = 0; u < 6; u++) {
                    const int c = ct + ((gIdx * 6 + u) << 6);
                    const float yv = Ys[k * SDIM + c];
#pragma unroll
                    for (int i = 0; i < 8; i++) acc[i][u] = fmaf(sv[i], yv, acc[i][u]);
                }
            }
#pragma unroll
            for (int i = 0; i < 8; i++) {
                const size_t row = base + qg * 8 + i;
#pragma unroll
                for (int u = 0; u < 6; u++) {
                    const int c = ct + ((gIdx * 6 + u) << 6);
                    out[row * CFEAT + c] = acc[i][u];
                }
            }
        }
    }
}

// ---------------- launch ----------------
extern "C" void kernel_launch(void* const* d_in, const int* in_sizes, int n_in,
                              void* d_out, int out_size)
{
    const float* x    = (const float*)d_in[0];
    const float* W1   = (const float*)d_in[1];
    const float* b1   = (const float*)d_in[2];
    const float* g1   = (const float*)d_in[3];
    const float* be1  = (const float*)d_in[4];
    const float* W2   = (const float*)d_in[5];
    const float* b2   = (const float*)d_in[6];
    const float* g2   = (const float*)d_in[7];
    const float* be2  = (const float*)d_in[8];
    const float* W3   = (const float*)d_in[9];
    const float* b3   = (const float*)d_in[10];
    const float* g3   = (const float*)d_in[11];
    const float* be3  = (const float*)d_in[12];
    const float* Wo   = (const float*)d_in[13];
    const float* bo   = (const float*)d_in[14];
    const float* caw1 = (const float*)d_in[15];
    const float* cab1 = (const float*)d_in[16];
    const float* caw2 = (const float*)d_in[17];
    const float* cab2 = (const float*)d_in[18];
    float* out = (float*)d_out;

    float *h1p, *h2p, *h3p, *yp, *poolp, *sp;
    __half *xh, *h1h, *h2h, *h3h, *w1h, *w2h, *w3h, *woh;
    cudaGetSymbolAddress((void**)&h1p, g_h1);
    cudaGetSymbolAddress((void**)&h2p, g_h2);
    cudaGetSymbolAddress((void**)&h3p, g_h3);
    cudaGetSymbolAddress((void**)&yp,  g_y);
    cudaGetSymbolAddress((void**)&poolp, g_pool);
    cudaGetSymbolAddress((void**)&sp,  g_s);
    cudaGetSymbolAddress((void**)&xh,  g_xh);
    cudaGetSymbolAddress((void**)&h1h, g_h1h);
    cudaGetSymbolAddress((void**)&h2h, g_h2h);
    cudaGetSymbolAddress((void**)&h3h, g_h3h);
    cudaGetSymbolAddress((void**)&w1h, g_w1h);
    cudaGetSymbolAddress((void**)&w2h, g_w2h);
    cudaGetSymbolAddress((void**)&w3h, g_w3h);
    cudaGetSymbolAddress((void**)&woh, g_woh);

    cudaFuncSetAttribute((const void*)mma_gemm<true, false>,
                         cudaFuncAttributeMaxDynamicSharedMemorySize, GEMM_SMEM_BYTES);
    cudaFuncSetAttribute((const void*)mma_gemm<false, true>,
                         cudaFuncAttributeMaxDynamicSharedMemorySize, GEMM_SMEM_BYTES);
    cudaFuncSetAttribute((const void*)attn_kernel,
                         cudaFuncAttributeMaxDynamicSharedMemorySize, ATTN_SMEM_BYTES);

    cudaMemsetAsync(poolp, 0, NBATCH * CFEAT * sizeof(float));

    // prep: x -> fp16; weights -> transposed fp16 [N][K]
    f2h_kernel<<<(MTOT * CFEAT / 8 + 255) / 256, 256>>>(
        (const float4*)x, (uint4*)xh, MTOT * CFEAT / 8);
    transpose_half<<<dim3(CFEAT / 32, HD1 / 32), 256>>>(W1, w1h, CFEAT, HD1);
    transpose_half<<<dim3(HD1 / 32, HD2 / 32), 256>>>(W2, w2h, HD1, HD2);
    transpose_half<<<dim3(HD2 / 32, HD3 / 32), 256>>>(W3, w3h, HD2, HD3);
    transpose_half<<<dim3(HD3 / 32, CFEAT / 32), 256>>>(Wo, woh, HD3, CFEAT);

    dim3 blk(256);
    // layer 1: LN(GELU(x @ W1 + b1))
    mma_gemm<true, false><<<dim3(HD1 / BN, MTOT / BM), blk, GEMM_SMEM_BYTES>>>(
        xh, w1h, b1, h1p, HD1, CFEAT, nullptr);
    ln_kernel<HD1><<<MTOT / 8, 256>>>(h1p, h1h, g1, be1, MTOT);
    // layer 2
    mma_gemm<true, false><<<dim3(HD2 / BN, MTOT / BM), blk, GEMM_SMEM_BYTES>>>(
        h1h, w2h, b2, h2p, HD2, HD1, nullptr);
    ln_kernel<HD2><<<MTOT / 8, 256>>>(h2p, h2h, g2, be2, MTOT);
    // layer 3
    mma_gemm<true, false><<<dim3(HD3 / BN, MTOT / BM), blk, GEMM_SMEM_BYTES>>>(
        h2h, w3h, b3, h3p, HD3, HD1 == 0 ? 0 : HD2, nullptr);
    ln_kernel<HD3><<<MTOT / 8, 256>>>(h3p, h3h, g3, be3, MTOT);
    // output projection + fused pooled column sums
    mma_gemm<false, true><<<dim3(CFEAT / BN, MTOT / BM), blk, GEMM_SMEM_BYTES>>>(
        h3h, woh, bo, yp, CFEAT, HD3, poolp);
    // SE gate
    se_kernel<<<NBATCH, 256>>>(poolp, caw1, cab1, caw2, cab2, sp);
    // fused SE-scale + windowed attention -> final output
    attn_kernel<<<NWIN, 256, ATTN_SMEM_BYTES>>>(yp, sp, out);
}

// round 8
// speedup vs baseline: 4.0083x; 1.2159x over previous
#include <cuda_runtime.h>
#include <cuda_fp16.h>
#include <math.h>
#include <stdint.h>

// ---------------- problem constants ----------------
#define MTOT   73728          // B*N = 8*9216 rows
#define CFEAT  1152
#define HD1    768
#define HD2    512
#define HD3    256
#define RED    144            // 1152/8
#define NSEQ   9216
#define NBATCH 8
#define WS     32
#define NWIN   2304           // 8 * 9216/32

// ---------------- scratch (no cudaMalloc allowed) ----------------
__device__ float  g_h1[(size_t)MTOT * HD1];     // GEMM outs (fp32, LN inputs)
__device__ float  g_h2[(size_t)MTOT * HD2];
__device__ float  g_h3[(size_t)MTOT * HD3];
__device__ float  g_pool[NBATCH * CFEAT];
__device__ float  g_s   [NBATCH * CFEAT];
// fp16 GEMM inputs / outputs
__device__ __half g_xh [(size_t)MTOT * CFEAT];
__device__ __half g_h1h[(size_t)MTOT * HD1];
__device__ __half g_h2h[(size_t)MTOT * HD2];
__device__ __half g_h3h[(size_t)MTOT * HD3];
__device__ __half g_yh [(size_t)MTOT * CFEAT];  // GEMM4 out (fp16)
// transposed fp16 weights: [N][K]
__device__ __half g_w1h[HD1 * CFEAT];
__device__ __half g_w2h[HD2 * HD1];
__device__ __half g_w3h[HD3 * HD2];
__device__ __half g_woh[CFEAT * HD3];

__device__ __forceinline__ float gelu_exact(float x) {
    return 0.5f * x * (1.0f + erff(x * 0.70710678118654752f));
}

__device__ __forceinline__ uint32_t smem_u32(const void* p) {
    uint32_t a;
    asm("{ .reg .u64 t; cvta.to.shared.u64 t, %1; cvt.u32.u64 %0, t; }" : "=r"(a) : "l"(p));
    return a;
}
__device__ __forceinline__ void cp16(uint32_t dst, const void* src) {
    asm volatile("cp.async.cg.shared.global [%0], [%1], 16;" :: "r"(dst), "l"(src));
}
#define CP_COMMIT() asm volatile("cp.async.commit_group;")
#define CP_WAIT0()  asm volatile("cp.async.wait_group 0;")
#define CP_WAIT1()  asm volatile("cp.async.wait_group 1;")

#define LDSM_X4(r, a) \
    asm volatile("ldmatrix.sync.aligned.m8n8.x4.shared.b16 {%0,%1,%2,%3}, [%4];" \
                 : "=r"((r)[0]), "=r"((r)[1]), "=r"((r)[2]), "=r"((r)[3]) : "r"(a))
#define LDSM_X4_T(r, a) \
    asm volatile("ldmatrix.sync.aligned.m8n8.x4.trans.shared.b16 {%0,%1,%2,%3}, [%4];" \
                 : "=r"((r)[0]), "=r"((r)[1]), "=r"((r)[2]), "=r"((r)[3]) : "r"(a))

__device__ __forceinline__ void mma_f16(float* c, const uint32_t* a,
                                        uint32_t b0, uint32_t b1) {
    asm volatile(
        "mma.sync.aligned.m16n8k16.row.col.f32.f16.f16.f32 "
        "{%0,%1,%2,%3}, {%4,%5,%6,%7}, {%8,%9}, {%0,%1,%2,%3};"
        : "+f"(c[0]), "+f"(c[1]), "+f"(c[2]), "+f"(c[3])
        : "r"(a[0]), "r"(a[1]), "r"(a[2]), "r"(a[3]), "r"(b0), "r"(b1));
}

// ---------------- prep ----------------
__global__ void f2h_kernel(const float4* __restrict__ src, uint4* __restrict__ dst, int n8) {
    const int i = blockIdx.x * 256 + threadIdx.x;
    if (i < n8) {
        float4 a = src[2 * i], b = src[2 * i + 1];
        __half2 h0 = __floats2half2_rn(a.x, a.y);
        __half2 h1 = __floats2half2_rn(a.z, a.w);
        __half2 h2 = __floats2half2_rn(b.x, b.y);
        __half2 h3 = __floats2half2_rn(b.z, b.w);
        uint4 o;
        o.x = *(uint32_t*)&h0; o.y = *(uint32_t*)&h1;
        o.z = *(uint32_t*)&h2; o.w = *(uint32_t*)&h3;
        dst[i] = o;
    }
}

__global__ void transpose_half(const float* __restrict__ src, __half* __restrict__ dst,
                               int K, int N) {
    __shared__ float t[32][33];
    const int k0 = blockIdx.x * 32, n0 = blockIdx.y * 32;
    const int x = threadIdx.x & 31, y = threadIdx.x >> 5;
#pragma unroll
    for (int i = y; i < 32; i += 8)
        t[i][x] = src[(size_t)(k0 + i) * N + n0 + x];
    __syncthreads();
#pragma unroll
    for (int i = y; i < 32; i += 8)
        dst[(size_t)(n0 + i) * K + k0 + x] = __float2half_rn(t[x][i]);
}

// ---------------- fp16 tensor-core GEMM (mma.sync m16n8k16 + ldmatrix) --------
#define BM 128
#define BN 128
#define BK 64
#define STAGE_BYTES (128 * 128)
#define GEMM_SMEM_BYTES (4 * STAGE_BYTES)

template<bool DO_GELU, bool DO_POOL, bool HOUT>
__global__ void __launch_bounds__(256, 2)
mma_gemm(const __half* __restrict__ A, const __half* __restrict__ Bt,
         const float* __restrict__ bias, void* __restrict__ CoutV,
         int N, int K, float* __restrict__ pool)
{
    extern __shared__ __align__(128) char smem[];
    const uint32_t sb = smem_u32(smem);

    const int tid = threadIdx.x;
    const int warp = tid >> 5, lane = tid & 31;
    const int wy = warp >> 1, wx = warp & 1;

    const int aRow0 = wy * 32 + (lane & 7) + 8 * ((lane >> 3) & 1);
    const int aCsel = lane >> 4;
    const int bRow0 = wx * 64 + (lane & 7) + 8 * ((lane >> 4) & 1);
    const int bCsel = (lane >> 3) & 1;

    const int gr = tid >> 3, gu = tid & 7;
    const __half* Abase = A  + (size_t)(blockIdx.y * BM) * K;
    const __half* Bbase = Bt + (size_t)(blockIdx.x * BN) * K;

    float acc[2][8][4];
#pragma unroll
    for (int im = 0; im < 2; im++)
#pragma unroll
        for (int in = 0; in < 8; in++)
#pragma unroll
            for (int c = 0; c < 4; c++) acc[im][in][c] = 0.f;

    const int nk = K >> 6;

    {
        const uint32_t ad = sb, bd = sb + 2 * STAGE_BYTES;
#pragma unroll
        for (int j = 0; j < 4; j++) {
            const int r = gr + j * 32;
            const uint32_t off = ((uint32_t)r << 7) + (uint32_t)((gu ^ (r & 7)) << 4);
            cp16(ad + off, Abase + (size_t)r * K + (gu << 3));
            cp16(bd + off, Bbase + (size_t)r * K + (gu << 3));
        }
        CP_COMMIT();
    }

    for (int kt = 0; kt < nk; kt++) {
        const int buf = kt & 1;
        if (kt + 1 < nk) {
            const int k0 = (kt + 1) << 6;
            const uint32_t ad = sb + (buf ^ 1) * STAGE_BYTES;
            const uint32_t bd = sb + (2 + (buf ^ 1)) * STAGE_BYTES;
#pragma unroll
            for (int j = 0; j < 4; j++) {
                const int r = gr + j * 32;
                const uint32_t off = ((uint32_t)r << 7) + (uint32_t)((gu ^ (r & 7)) << 4);
                cp16(ad + off, Abase + (size_t)r * K + k0 + (gu << 3));
                cp16(bd + off, Bbase + (size_t)r * K + k0 + (gu << 3));
            }
            CP_COMMIT();
            CP_WAIT1();
        } else {
            CP_WAIT0();
        }
        __syncthreads();

        const uint32_t aB = sb + buf * STAGE_BYTES;
        const uint32_t bB = sb + (2 + buf) * STAGE_BYTES;
#pragma unroll
        for (int j = 0; j < 4; j++) {
            const int c0 = 2 * j;
            uint32_t af[2][4];
#pragma unroll
            for (int im = 0; im < 2; im++) {
                const int row = aRow0 + im * 16;
                const uint32_t addr = aB + ((uint32_t)row << 7)
                                    + (uint32_t)(((c0 + aCsel) ^ (row & 7)) << 4);
                LDSM_X4(af[im], addr);
            }
            uint32_t bf[4][4];
#pragma unroll
            for (int p = 0; p < 4; p++) {
                const int row = bRow0 + p * 16;
                const uint32_t addr = bB + ((uint32_t)row << 7)
                                    + (uint32_t)(((c0 + bCsel) ^ (row & 7)) << 4);
                LDSM_X4(bf[p], addr);
            }
#pragma unroll
            for (int im = 0; im < 2; im++)
#pragma unroll
                for (int p = 0; p < 4; p++) {
                    mma_f16(acc[im][2 * p],     af[im], bf[p][0], bf[p][1]);
                    mma_f16(acc[im][2 * p + 1], af[im], bf[p][2], bf[p][3]);
                }
        }
        __syncthreads();
    }

    // ---- epilogue ----
    const int g = lane >> 2, t = lane & 3;
    float* csum = (float*)smem;
    if (DO_POOL) {
        if (tid < 128) csum[tid] = 0.f;
        __syncthreads();
    }

#pragma unroll
    for (int im = 0; im < 2; im++) {
        const int r0 = blockIdx.y * BM + wy * 32 + im * 16 + g;
#pragma unroll
        for (int in = 0; in < 8; in++) {
            const int col = blockIdx.x * BN + wx * 64 + in * 8 + 2 * t;
            const float bv0 = bias[col], bv1 = bias[col + 1];
            float v00 = acc[im][in][0] + bv0;
            float v01 = acc[im][in][1] + bv1;
            float v10 = acc[im][in][2] + bv0;
            float v11 = acc[im][in][3] + bv1;
            if (DO_GELU) {
                v00 = gelu_exact(v00); v01 = gelu_exact(v01);
                v10 = gelu_exact(v10); v11 = gelu_exact(v11);
            }
            if (HOUT) {
                __half* Ch = (__half*)CoutV;
                *(__half2*)(Ch + (size_t)r0 * N + col)       = __floats2half2_rn(v00, v01);
                *(__half2*)(Ch + (size_t)(r0 + 8) * N + col) = __floats2half2_rn(v10, v11);
            } else {
                float* Cf = (float*)CoutV;
                *(float2*)(Cf + (size_t)r0 * N + col)       = make_float2(v00, v01);
                *(float2*)(Cf + (size_t)(r0 + 8) * N + col) = make_float2(v10, v11);
            }
            if (DO_POOL) {
                const int lc = wx * 64 + in * 8 + 2 * t;
                atomicAdd(&csum[lc],     v00 + v10);
                atomicAdd(&csum[lc + 1], v01 + v11);
            }
        }
    }

    if (DO_POOL) {
        __syncthreads();
        if (tid < 128) {
            const int batch = (blockIdx.y * BM) / NSEQ;
            atomicAdd(&pool[batch * CFEAT + blockIdx.x * BN + tid], csum[tid]);
        }
    }
}

// ---------------- LayerNorm (warp per row): fp32 in -> fp16 out ----------------
template<int H>
__global__ void ln_kernel(const float* __restrict__ x, __half* __restrict__ xo,
                          const float* __restrict__ g, const float* __restrict__ be,
                          int M)
{
    const int warp = threadIdx.x >> 5, lane = threadIdx.x & 31;
    const int row = blockIdx.x * (blockDim.x >> 5) + warp;
    if (row >= M) return;
    const float* p = x + (size_t)row * H;
    __half* po = xo + (size_t)row * H;
    constexpr int NV = H / 32;
    float v[NV];
    float s = 0.f;
#pragma unroll
    for (int i = 0; i < NV; i++) { v[i] = p[lane + (i << 5)]; s += v[i]; }
#pragma unroll
    for (int o = 16; o > 0; o >>= 1) s += __shfl_xor_sync(0xffffffffu, s, o);
    const float mu = s * (1.0f / H);
    float var = 0.f;
#pragma unroll
    for (int i = 0; i < NV; i++) { float d = v[i] - mu; var += d * d; }
#pragma unroll
    for (int o = 16; o > 0; o >>= 1) var += __shfl_xor_sync(0xffffffffu, var, o);
    const float rstd = rsqrtf(var * (1.0f / H) + 1e-5f);
#pragma unroll
    for (int i = 0; i < NV; i++) {
        const int c = lane + (i << 5);
        po[c] = __float2half_rn((v[i] - mu) * rstd * g[c] + be[c]);
    }
}

// ---------------- SE channel attention ----------------
__global__ void se_kernel(const float* __restrict__ pool,
                          const float* __restrict__ w1, const float* __restrict__ b1,
                          const float* __restrict__ w2, const float* __restrict__ b2,
                          float* __restrict__ s)
{
    __shared__ float p[CFEAT];
    __shared__ float hid[RED];
    const int b = blockIdx.x, t = threadIdx.x;
    for (int i = t; i < CFEAT; i += 256) p[i] = pool[b * CFEAT + i] * (1.0f / NSEQ);
    __syncthreads();
    if (t < RED) {
        float a = b1[t];
        for (int c = 0; c < CFEAT; c++) a = fmaf(p[c], w1[c * RED + t], a);
        hid[t] = fmaxf(a, 0.f);
    }
    __syncthreads();
    for (int c = t; c < CFEAT; c += 256) {
        float a = b2[c];
        for (int h = 0; h < RED; h++) a = fmaf(hid[h], w2[h * CFEAT + c], a);
        s[b * CFEAT + c] = 1.0f / (1.0f + expf(-a));
    }
}

// ---------------- tensor-core windowed attention ----------------
// One block per 32-token window. Y tile fp16 in smem (rows padded to 1160 halves
// = 145 chunks, odd -> conflict-free ldmatrix). S = Y@Y^T K-split across 8 warps
// (fp32 smem-atomic reduce), softmax fp32, P fp16, PV via ldmatrix.trans.
#define YROWH 1160
#define YROWB 2320
#define PROWH 40
#define ATTN_SS_OFF  (32 * YROWH * 2)                 // 74240
#define ATTN_PS_OFF  (ATTN_SS_OFF + 32 * 33 * 4)      // 78464
#define ATTN_SMEM_BYTES (ATTN_PS_OFF + 32 * PROWH * 2) // 81024

__global__ void __launch_bounds__(256, 2)
attn_kernel(const __half* __restrict__ y, const float* __restrict__ s,
            float* __restrict__ out)
{
    extern __shared__ __align__(128) char smem[];
    __half* Ys = (__half*)smem;
    float*  Ss = (float*)(smem + ATTN_SS_OFF);
    __half* Ps = (__half*)(smem + ATTN_PS_OFF);
    const uint32_t ysb = smem_u32(smem);
    const uint32_t psb = ysb + ATTN_PS_OFF;

    const int win = blockIdx.x;
    const int b = win / (NSEQ / WS);
    const size_t base = (size_t)win * 32;
    const int tid = threadIdx.x;
    const int warp = tid >> 5, lane = tid & 31;
    const float* sb = s + b * CFEAT;

    // phase 1: load fp16 y, scale by s, store padded rows
    for (int idx = tid; idx < 32 * 144; idx += 256) {
        const int r = idx / 144, u = idx - r * 144;
        uint4 raw = *(const uint4*)(y + (base + r) * CFEAT + u * 8);
        const float4 s0 = *(const float4*)(sb + u * 8);
        const float4 s1 = *(const float4*)(sb + u * 8 + 4);
        __half2* hp = (__half2*)&raw;
        float2 f0 = __half22float2(hp[0]);
        float2 f1 = __half22float2(hp[1]);
        float2 f2 = __half22float2(hp[2]);
        float2 f3 = __half22float2(hp[3]);
        uint4 o;
        __half2 t0 = __floats2half2_rn(f0.x * s0.x, f0.y * s0.y);
        __half2 t1 = __floats2half2_rn(f1.x * s0.z, f1.y * s0.w);
        __half2 t2 = __floats2half2_rn(f2.x * s1.x, f2.y * s1.y);
        __half2 t3 = __floats2half2_rn(f3.x * s1.z, f3.y * s1.w);
        o.x = *(uint32_t*)&t0; o.y = *(uint32_t*)&t1;
        o.z = *(uint32_t*)&t2; o.w = *(uint32_t*)&t3;
        *(uint4*)(Ys + r * YROWH + u * 8) = o;
    }
    for (int i = tid; i < 32 * 33; i += 256) Ss[i] = 0.f;
    __syncthreads();

    // ldmatrix selectors
    const int aRow = (lane & 7) + 8 * ((lane >> 3) & 1);
    const int aC   = lane >> 4;
    const int bRow = (lane & 7) + 8 * ((lane >> 4) & 1);
    const int bC   = (lane >> 3) & 1;

    // phase 2: S partials, warp covers channels [warp*144, +144)
    {
        float acc[2][4][4];
#pragma unroll
        for (int im = 0; im < 2; im++)
#pragma unroll
            for (int in = 0; in < 4; in++)
#pragma unroll
                for (int c = 0; c < 4; c++) acc[im][in][c] = 0.f;
        const int kch0 = warp * 18;
#pragma unroll
        for (int ks = 0; ks < 9; ks++) {
            const int c0 = kch0 + 2 * ks;
            uint32_t af[2][4], bf[2][4];
#pragma unroll
            for (int im = 0; im < 2; im++)
                LDSM_X4(af[im], ysb + (uint32_t)(im * 16 + aRow) * YROWB
                                    + (uint32_t)(c0 + aC) * 16);
#pragma unroll
            for (int jn = 0; jn < 2; jn++)
                LDSM_X4(bf[jn], ysb + (uint32_t)(jn * 16 + bRow) * YROWB
                                    + (uint32_t)(c0 + bC) * 16);
#pragma unroll
            for (int im = 0; im < 2; im++)
#pragma unroll
                for (int jn = 0; jn < 2; jn++) {
                    mma_f16(acc[im][2 * jn],     af[im], bf[jn][0], bf[jn][1]);
                    mma_f16(acc[im][2 * jn + 1], af[im], bf[jn][2], bf[jn][3]);
                }
        }
        const int g = lane >> 2, t2 = lane & 3;
#pragma unroll
        for (int im = 0; im < 2; im++)
#pragma unroll
            for (int in = 0; in < 4; in++) {
                const int r0 = im * 16 + g, c0 = in * 8 + 2 * t2;
                atomicAdd(&Ss[r0 * 33 + c0],           acc[im][in][0]);
                atomicAdd(&Ss[r0 * 33 + c0 + 1],       acc[im][in][1]);
                atomicAdd(&Ss[(r0 + 8) * 33 + c0],     acc[im][in][2]);
                atomicAdd(&Ss[(r0 + 8) * 33 + c0 + 1], acc[im][in][3]);
            }
    }
    __syncthreads();

    // phase 3: softmax (fp32) -> P fp16
    {
        const float scale = 1.0f / sqrtf((float)CFEAT);
        for (int q = warp; q < 32; q += 8) {
            float v = Ss[q * 33 + lane] * scale;
            float m = v;
#pragma unroll
            for (int o = 16; o > 0; o >>= 1) m = fmaxf(m, __shfl_xor_sync(0xffffffffu, m, o));
            float e = expf(v - m);
            float sum = e;
#pragma unroll
            for (int o = 16; o > 0; o >>= 1) sum += __shfl_xor_sync(0xffffffffu, sum, o);
            Ps[q * PROWH + lane] = __float2half_rn(e / sum);
        }
    }
    __syncthreads();

    // phase 4: out = P @ Y (warp covers channels [warp*144, +144))
    {
        uint32_t af[2][2][4];     // [k16 step][m16 block]
#pragma unroll
        for (int kk = 0; kk < 2; kk++)
#pragma unroll
            for (int im = 0; im < 2; im++)
                LDSM_X4(af[kk][im], psb + (uint32_t)(im * 16 + aRow) * (PROWH * 2)
                                        + (uint32_t)(kk * 2 + aC) * 16);
        const int cch0 = warp * 18;
        const int g = lane >> 2, t2 = lane & 3;
#pragma unroll
        for (int jn = 0; jn < 9; jn++) {
            float acc[2][2][4];
#pragma unroll
            for (int im = 0; im < 2; im++)
#pragma unroll
                for (int in = 0; in < 2; in++)
#pragma unroll
                    for (int c = 0; c < 4; c++) acc[im][in][c] = 0.f;
#pragma unroll
            for (int kk = 0; kk < 2; kk++) {
                uint32_t bt[4];
                // .trans x4: matrices stack k-first -> lane->row uses the A
                // pattern (8*((lane>>3)&1)), column chunk = lane>>4.
                LDSM_X4_T(bt, ysb + (uint32_t)(kk * 16 + aRow) * YROWB
                                  + (uint32_t)(cch0 + 2 * jn + aC) * 16);
#pragma unroll
                for (int im = 0; im < 2; im++) {
                    mma_f16(acc[im][0], af[kk][im], bt[0], bt[1]);
                    mma_f16(acc[im][1], af[kk][im], bt[2], bt[3]);
                }
            }
#pragma unroll
            for (int im = 0; im < 2; im++) {
                const int row = im * 16 + g;
#pragma unroll
                for (int in = 0; in < 2; in++) {
                    const int col = warp * 144 + jn * 16 + in * 8 + 2 * t2;
                    *(float2*)(out + (base + row) * CFEAT + col) =
                        make_float2(acc[im][in][0], acc[im][in][1]);
                    *(float2*)(out + (base + row + 8) * CFEAT + col) =
                        make_float2(acc[im][in][2], acc[im][in][3]);
                }
            }
        }
    }
}

// ---------------- launch ----------------
extern "C" void kernel_launch(void* const* d_in, const int* in_sizes, int n_in,
                              void* d_out, int out_size)
{
    const float* x    = (const float*)d_in[0];
    const float* W1   = (const float*)d_in[1];
    const float* b1   = (const float*)d_in[2];
    const float* g1   = (const float*)d_in[3];
    const float* be1  = (const float*)d_in[4];
    const float* W2   = (const float*)d_in[5];
    const float* b2   = (const float*)d_in[6];
    const float* g2   = (const float*)d_in[7];
    const float* be2  = (const float*)d_in[8];
    const float* W3   = (const float*)d_in[9];
    const float* b3   = (const float*)d_in[10];
    const float* g3   = (const float*)d_in[11];
    const float* be3  = (const float*)d_in[12];
    const float* Wo   = (const float*)d_in[13];
    const float* bo   = (const float*)d_in[14];
    const float* caw1 = (const float*)d_in[15];
    const float* cab1 = (const float*)d_in[16];
    const float* caw2 = (const float*)d_in[17];
    const float* cab2 = (const float*)d_in[18];
    float* out = (float*)d_out;

    float *h1p, *h2p, *h3p, *poolp, *sp;
    __half *xh, *h1h, *h2h, *h3h, *yh, *w1h, *w2h, *w3h, *woh;
    cudaGetSymbolAddress((void**)&h1p, g_h1);
    cudaGetSymbolAddress((void**)&h2p, g_h2);
    cudaGetSymbolAddress((void**)&h3p, g_h3);
    cudaGetSymbolAddress((void**)&poolp, g_pool);
    cudaGetSymbolAddress((void**)&sp,  g_s);
    cudaGetSymbolAddress((void**)&xh,  g_xh);
    cudaGetSymbolAddress((void**)&h1h, g_h1h);
    cudaGetSymbolAddress((void**)&h2h, g_h2h);
    cudaGetSymbolAddress((void**)&h3h, g_h3h);
    cudaGetSymbolAddress((void**)&yh,  g_yh);
    cudaGetSymbolAddress((void**)&w1h, g_w1h);
    cudaGetSymbolAddress((void**)&w2h, g_w2h);
    cudaGetSymbolAddress((void**)&w3h, g_w3h);
    cudaGetSymbolAddress((void**)&woh, g_woh);

    cudaFuncSetAttribute((const void*)mma_gemm<true, false, false>,
                         cudaFuncAttributeMaxDynamicSharedMemorySize, GEMM_SMEM_BYTES);
    cudaFuncSetAttribute((const void*)mma_gemm<false, true, true>,
                         cudaFuncAttributeMaxDynamicSharedMemorySize, GEMM_SMEM_BYTES);
    cudaFuncSetAttribute((const void*)attn_kernel,
                         cudaFuncAttributeMaxDynamicSharedMemorySize, ATTN_SMEM_BYTES);

    cudaMemsetAsync(poolp, 0, NBATCH * CFEAT * sizeof(float));

    // prep: x -> fp16; weights -> transposed fp16 [N][K]
    f2h_kernel<<<(MTOT * CFEAT / 8 + 255) / 256, 256>>>(
        (const float4*)x, (uint4*)xh, MTOT * CFEAT / 8);
    transpose_half<<<dim3(CFEAT / 32, HD1 / 32), 256>>>(W1, w1h, CFEAT, HD1);
    transpose_half<<<dim3(HD1 / 32, HD2 / 32), 256>>>(W2, w2h, HD1, HD2);
    transpose_half<<<dim3(HD2 / 32, HD3 / 32), 256>>>(W3, w3h, HD2, HD3);
    transpose_half<<<dim3(HD3 / 32, CFEAT / 32), 256>>>(Wo, woh, HD3, CFEAT);

    dim3 blk(256);
    // layer 1: LN(GELU(x @ W1 + b1))
    mma_gemm<true, false, false><<<dim3(HD1 / BN, MTOT / BM), blk, GEMM_SMEM_BYTES>>>(
        xh, w1h, b1, h1p, HD1, CFEAT, nullptr);
    ln_kernel<HD1><<<MTOT / 8, 256>>>(h1p, h1h, g1, be1, MTOT);
    // layer 2
    mma_gemm<true, false, false><<<dim3(HD2 / BN, MTOT / BM), blk, GEMM_SMEM_BYTES>>>(
        h1h, w2h, b2, h2p, HD2, HD1, nullptr);
    ln_kernel<HD2><<<MTOT / 8, 256>>>(h2p, h2h, g2, be2, MTOT);
    // layer 3
    mma_gemm<true, false, false><<<dim3(HD3 / BN, MTOT / BM), blk, GEMM_SMEM_BYTES>>>(
        h2h, w3h, b3, h3p, HD3, HD2, nullptr);
    ln_kernel<HD3><<<MTOT / 8, 256>>>(h3p, h3h, g3, be3, MTOT);
    // output projection (fp16 out) + fused pooled column sums
    mma_gemm<false, true, true><<<dim3(CFEAT / BN, MTOT / BM), blk, GEMM_SMEM_BYTES>>>(
        h3h, woh, bo, yh, CFEAT, HD3, poolp);
    // SE gate
    se_kernel<<<NBATCH, 256>>>(poolp, caw1, cab1, caw2, cab2, sp);
    // tensor-core SE-scale + windowed attention -> final output
    attn_kernel<<<NWIN, 256, ATTN_SMEM_BYTES>>>(yh, sp, out);
}

// round 9
// speedup vs baseline: 4.0482x; 1.0100x over previous
#include <cuda_runtime.h>
#include <cuda_fp16.h>
#include <math.h>
#include <stdint.h>

// ---------------- problem constants ----------------
#define MTOT   73728          // B*N = 8*9216 rows
#define CFEAT  1152
#define HD1    768
#define HD2    512
#define HD3    256
#define RED    144            // 1152/8
#define NSEQ   9216
#define NBATCH 8
#define WS     32
#define NWIN   2304           // 8 * 9216/32

// ---------------- scratch (no cudaMalloc allowed) ----------------
__device__ float  g_pool[NBATCH * CFEAT];
__device__ float  g_s   [NBATCH * CFEAT];
// fp16 activations (GEMM outputs / LN in-place / GEMM inputs)
__device__ __half g_xh [(size_t)MTOT * CFEAT];
__device__ __half g_h1h[(size_t)MTOT * HD1];
__device__ __half g_h2h[(size_t)MTOT * HD2];
__device__ __half g_h3h[(size_t)MTOT * HD3];
__device__ __half g_yh [(size_t)MTOT * CFEAT];  // GEMM4 out (fp16)
// transposed fp16 weights: [N][K]
__device__ __half g_w1h[HD1 * CFEAT];
__device__ __half g_w2h[HD2 * HD1];
__device__ __half g_w3h[HD3 * HD2];
__device__ __half g_woh[CFEAT * HD3];

__device__ __forceinline__ float gelu_exact(float x) {
    return 0.5f * x * (1.0f + erff(x * 0.70710678118654752f));
}

__device__ __forceinline__ uint32_t smem_u32(const void* p) {
    uint32_t a;
    asm("{ .reg .u64 t; cvta.to.shared.u64 t, %1; cvt.u32.u64 %0, t; }" : "=r"(a) : "l"(p));
    return a;
}
__device__ __forceinline__ void cp16(uint32_t dst, const void* src) {
    asm volatile("cp.async.cg.shared.global [%0], [%1], 16;" :: "r"(dst), "l"(src));
}
#define CP_COMMIT() asm volatile("cp.async.commit_group;")
#define CP_WAIT0()  asm volatile("cp.async.wait_group 0;")
#define CP_WAIT1()  asm volatile("cp.async.wait_group 1;")

#define LDSM_X4(r, a) \
    asm volatile("ldmatrix.sync.aligned.m8n8.x4.shared.b16 {%0,%1,%2,%3}, [%4];" \
                 : "=r"((r)[0]), "=r"((r)[1]), "=r"((r)[2]), "=r"((r)[3]) : "r"(a))
#define LDSM_X4_T(r, a) \
    asm volatile("ldmatrix.sync.aligned.m8n8.x4.trans.shared.b16 {%0,%1,%2,%3}, [%4];" \
                 : "=r"((r)[0]), "=r"((r)[1]), "=r"((r)[2]), "=r"((r)[3]) : "r"(a))

__device__ __forceinline__ void mma_f16(float* c, const uint32_t* a,
                                        uint32_t b0, uint32_t b1) {
    asm volatile(
        "mma.sync.aligned.m16n8k16.row.col.f32.f16.f16.f32 "
        "{%0,%1,%2,%3}, {%4,%5,%6,%7}, {%8,%9}, {%0,%1,%2,%3};"
        : "+f"(c[0]), "+f"(c[1]), "+f"(c[2]), "+f"(c[3])
        : "r"(a[0]), "r"(a[1]), "r"(a[2]), "r"(a[3]), "r"(b0), "r"(b1));
}

// ---------------- prep ----------------
__global__ void f2h_kernel(const float4* __restrict__ src, uint4* __restrict__ dst, int n8) {
    const int i = blockIdx.x * 256 + threadIdx.x;
    if (i < n8) {
        float4 a = src[2 * i], b = src[2 * i + 1];
        __half2 h0 = __floats2half2_rn(a.x, a.y);
        __half2 h1 = __floats2half2_rn(a.z, a.w);
        __half2 h2 = __floats2half2_rn(b.x, b.y);
        __half2 h3 = __floats2half2_rn(b.z, b.w);
        uint4 o;
        o.x = *(uint32_t*)&h0; o.y = *(uint32_t*)&h1;
        o.z = *(uint32_t*)&h2; o.w = *(uint32_t*)&h3;
        dst[i] = o;
    }
}

__global__ void transpose_half(const float* __restrict__ src, __half* __restrict__ dst,
                               int K, int N) {
    __shared__ float t[32][33];
    const int k0 = blockIdx.x * 32, n0 = blockIdx.y * 32;
    const int x = threadIdx.x & 31, y = threadIdx.x >> 5;
#pragma unroll
    for (int i = y; i < 32; i += 8)
        t[i][x] = src[(size_t)(k0 + i) * N + n0 + x];
    __syncthreads();
#pragma unroll
    for (int i = y; i < 32; i += 8)
        dst[(size_t)(n0 + i) * K + k0 + x] = __float2half_rn(t[x][i]);
}

// ---------------- fp16 tensor-core GEMM (m16n8k16 + ldmatrix, 3-stage) --------
#define BM 128
#define BN 128
#define BK 64
#define STAGE_BYTES (128 * 128)
#define NSTAGE 3
#define GEMM_SMEM_BYTES (2 * NSTAGE * STAGE_BYTES)   // 98304

template<bool DO_GELU, bool DO_POOL>
__global__ void __launch_bounds__(256, 2)
mma_gemm(const __half* __restrict__ A, const __half* __restrict__ Bt,
         const float* __restrict__ bias, __half* __restrict__ Cout,
         int N, int K, float* __restrict__ pool)
{
    extern __shared__ __align__(128) char smem[];
    const uint32_t sb = smem_u32(smem);
    // stage s: A at sb + s*16KB, B at sb + NSTAGE*16KB + s*16KB

    const int tid = threadIdx.x;
    const int warp = tid >> 5, lane = tid & 31;
    const int wy = warp >> 1, wx = warp & 1;

    const int aRow0 = wy * 32 + (lane & 7) + 8 * ((lane >> 3) & 1);
    const int aCsel = lane >> 4;
    const int bRow0 = wx * 64 + (lane & 7) + 8 * ((lane >> 4) & 1);
    const int bCsel = (lane >> 3) & 1;

    const int gr = tid >> 3, gu = tid & 7;
    const __half* Abase = A  + (size_t)(blockIdx.y * BM) * K;
    const __half* Bbase = Bt + (size_t)(blockIdx.x * BN) * K;

    float acc[2][8][4];
#pragma unroll
    for (int im = 0; im < 2; im++)
#pragma unroll
        for (int in = 0; in < 8; in++)
#pragma unroll
            for (int c = 0; c < 4; c++) acc[im][in][c] = 0.f;

    const int nk = K >> 6;

    // gmem offsets precomputed for the loader
    const uint32_t soff = ((uint32_t)gr << 7) + (uint32_t)((gu ^ (gr & 7)) << 4);

    // prologue: issue stages 0 and 1
#pragma unroll
    for (int s = 0; s < 2; s++) {
        const int k0 = s << 6;
        const uint32_t ad = sb + s * STAGE_BYTES;
        const uint32_t bd = sb + (NSTAGE + s) * STAGE_BYTES;
#pragma unroll
        for (int j = 0; j < 4; j++) {
            const int r = gr + j * 32;
            const uint32_t off = soff + (uint32_t)(j * 32) * 128;
            cp16(ad + off, Abase + (size_t)r * K + k0 + (gu << 3));
            cp16(bd + off, Bbase + (size_t)r * K + k0 + (gu << 3));
        }
        CP_COMMIT();
    }

    for (int kt = 0; kt < nk; kt++) {
        const int buf = kt % NSTAGE;
        if (kt == nk - 1) { CP_WAIT0(); } else { CP_WAIT1(); }
        __syncthreads();   // stage kt visible to all; prev compute retired

        if (kt + 2 < nk) {
            const int s = (kt + 2) % NSTAGE;
            const int k0 = (kt + 2) << 6;
            const uint32_t ad = sb + s * STAGE_BYTES;
            const uint32_t bd = sb + (NSTAGE + s) * STAGE_BYTES;
#pragma unroll
            for (int j = 0; j < 4; j++) {
                const int r = gr + j * 32;
                const uint32_t off = soff + (uint32_t)(j * 32) * 128;
                cp16(ad + off, Abase + (size_t)r * K + k0 + (gu << 3));
                cp16(bd + off, Bbase + (size_t)r * K + k0 + (gu << 3));
            }
            CP_COMMIT();
        }

        const uint32_t aB = sb + buf * STAGE_BYTES;
        const uint32_t bB = sb + (NSTAGE + buf) * STAGE_BYTES;
#pragma unroll
        for (int j = 0; j < 4; j++) {
            const int c0 = 2 * j;
            uint32_t af[2][4];
#pragma unroll
            for (int im = 0; im < 2; im++) {
                const int row = aRow0 + im * 16;
                const uint32_t addr = aB + ((uint32_t)row << 7)
                                    + (uint32_t)(((c0 + aCsel) ^ (row & 7)) << 4);
                LDSM_X4(af[im], addr);
            }
            uint32_t bf[4][4];
#pragma unroll
            for (int p = 0; p < 4; p++) {
                const int row = bRow0 + p * 16;
                const uint32_t addr = bB + ((uint32_t)row << 7)
                                    + (uint32_t)(((c0 + bCsel) ^ (row & 7)) << 4);
                LDSM_X4(bf[p], addr);
            }
#pragma unroll
            for (int im = 0; im < 2; im++)
#pragma unroll
                for (int p = 0; p < 4; p++) {
                    mma_f16(acc[im][2 * p],     af[im], bf[p][0], bf[p][1]);
                    mma_f16(acc[im][2 * p + 1], af[im], bf[p][2], bf[p][3]);
                }
        }
    }
    __syncthreads();   // retire last compute before smem reuse

    // ---- epilogue: bias (+gelu), fp16 store; optional pooled column sums ----
    const int g = lane >> 2, t = lane & 3;
    float* csum = (float*)smem;
    if (DO_POOL) {
        if (tid < 128) csum[tid] = 0.f;
        __syncthreads();
    }

#pragma unroll
    for (int im = 0; im < 2; im++) {
        const int r0 = blockIdx.y * BM + wy * 32 + im * 16 + g;
#pragma unroll
        for (int in = 0; in < 8; in++) {
            const int col = blockIdx.x * BN + wx * 64 + in * 8 + 2 * t;
            const float bv0 = bias[col], bv1 = bias[col + 1];
            float v00 = acc[im][in][0] + bv0;
            float v01 = acc[im][in][1] + bv1;
            float v10 = acc[im][in][2] + bv0;
            float v11 = acc[im][in][3] + bv1;
            if (DO_GELU) {
                v00 = gelu_exact(v00); v01 = gelu_exact(v01);
                v10 = gelu_exact(v10); v11 = gelu_exact(v11);
            }
            *(__half2*)(Cout + (size_t)r0 * N + col)       = __floats2half2_rn(v00, v01);
            *(__half2*)(Cout + (size_t)(r0 + 8) * N + col) = __floats2half2_rn(v10, v11);
            if (DO_POOL) {
                const int lc = wx * 64 + in * 8 + 2 * t;
                atomicAdd(&csum[lc],     v00 + v10);
                atomicAdd(&csum[lc + 1], v01 + v11);
            }
        }
    }

    if (DO_POOL) {
        __syncthreads();
        if (tid < 128) {
            const int batch = (blockIdx.y * BM) / NSEQ;
            atomicAdd(&pool[batch * CFEAT + blockIdx.x * BN + tid], csum[tid]);
        }
    }
}

// ---------------- LayerNorm (warp per row): fp16 in-place, fp32 stats --------
template<int H>
__global__ void ln_kernel(__half* __restrict__ xio, const float* __restrict__ g,
                          const float* __restrict__ be, int M)
{
    const int warp = threadIdx.x >> 5, lane = threadIdx.x & 31;
    const int row = blockIdx.x * (blockDim.x >> 5) + warp;
    if (row >= M) return;
    __half2* p = (__half2*)(xio + (size_t)row * H);
    constexpr int NV = H / 64;   // half2 per lane
    float2 v[NV];
    float s = 0.f;
#pragma unroll
    for (int i = 0; i < NV; i++) {
        v[i] = __half22float2(p[lane + (i << 5)]);
        s += v[i].x + v[i].y;
    }
#pragma unroll
    for (int o = 16; o > 0; o >>= 1) s += __shfl_xor_sync(0xffffffffu, s, o);
    const float mu = s * (1.0f / H);
    float var = 0.f;
#pragma unroll
    for (int i = 0; i < NV; i++) {
        float d0 = v[i].x - mu, d1 = v[i].y - mu;
        var += d0 * d0 + d1 * d1;
    }
#pragma unroll
    for (int o = 16; o > 0; o >>= 1) var += __shfl_xor_sync(0xffffffffu, var, o);
    const float rstd = rsqrtf(var * (1.0f / H) + 1e-5f);
#pragma unroll
    for (int i = 0; i < NV; i++) {
        const int c = 2 * (lane + (i << 5));
        const float y0 = (v[i].x - mu) * rstd * g[c]     + be[c];
        const float y1 = (v[i].y - mu) * rstd * g[c + 1] + be[c + 1];
        p[lane + (i << 5)] = __floats2half2_rn(y0, y1);
    }
}

// ---------------- SE channel attention ----------------
__global__ void se_kernel(const float* __restrict__ pool,
                          const float* __restrict__ w1, const float* __restrict__ b1,
                          const float* __restrict__ w2, const float* __restrict__ b2,
                          float* __restrict__ s)
{
    __shared__ float p[CFEAT];
    __shared__ float hid[RED];
    const int b = blockIdx.x, t = threadIdx.x;
    for (int i = t; i < CFEAT; i += 256) p[i] = pool[b * CFEAT + i] * (1.0f / NSEQ);
    __syncthreads();
    if (t < RED) {
        float a = b1[t];
        for (int c = 0; c < CFEAT; c++) a = fmaf(p[c], w1[c * RED + t], a);
        hid[t] = fmaxf(a, 0.f);
    }
    __syncthreads();
    for (int c = t; c < CFEAT; c += 256) {
        float a = b2[c];
        for (int h = 0; h < RED; h++) a = fmaf(hid[h], w2[h * CFEAT + c], a);
        s[b * CFEAT + c] = 1.0f / (1.0f + expf(-a));
    }
}

// ---------------- tensor-core windowed attention ----------------
#define YROWH 1160
#define YROWB 2320
#define PROWH 40
#define ATTN_SS_OFF  (32 * YROWH * 2)                 // 74240
#define ATTN_PS_OFF  (ATTN_SS_OFF + 32 * 33 * 4)      // 78464
#define ATTN_SMEM_BYTES (ATTN_PS_OFF + 32 * PROWH * 2) // 81024

__global__ void __launch_bounds__(256, 2)
attn_kernel(const __half* __restrict__ y, const float* __restrict__ s,
            float* __restrict__ out)
{
    extern __shared__ __align__(128) char smem[];
    __half* Ys = (__half*)smem;
    float*  Ss = (float*)(smem + ATTN_SS_OFF);
    __half* Ps = (__half*)(smem + ATTN_PS_OFF);
    const uint32_t ysb = smem_u32(smem);
    const uint32_t psb = ysb + ATTN_PS_OFF;

    const int win = blockIdx.x;
    const int b = win / (NSEQ / WS);
    const size_t base = (size_t)win * 32;
    const int tid = threadIdx.x;
    const int warp = tid >> 5, lane = tid & 31;
    const float* sb = s + b * CFEAT;

    // phase 1: load fp16 y, scale by s, store padded rows
    for (int idx = tid; idx < 32 * 144; idx += 256) {
        const int r = idx / 144, u = idx - r * 144;
        uint4 raw = *(const uint4*)(y + (base + r) * CFEAT + u * 8);
        const float4 s0 = *(const float4*)(sb + u * 8);
        const float4 s1 = *(const float4*)(sb + u * 8 + 4);
        __half2* hp = (__half2*)&raw;
        float2 f0 = __half22float2(hp[0]);
        float2 f1 = __half22float2(hp[1]);
        float2 f2 = __half22float2(hp[2]);
        float2 f3 = __half22float2(hp[3]);
        uint4 o;
        __half2 t0 = __floats2half2_rn(f0.x * s0.x, f0.y * s0.y);
        __half2 t1 = __floats2half2_rn(f1.x * s0.z, f1.y * s0.w);
        __half2 t2 = __floats2half2_rn(f2.x * s1.x, f2.y * s1.y);
        __half2 t3 = __floats2half2_rn(f3.x * s1.z, f3.y * s1.w);
        o.x = *(uint32_t*)&t0; o.y = *(uint32_t*)&t1;
        o.z = *(uint32_t*)&t2; o.w = *(uint32_t*)&t3;
        *(uint4*)(Ys + r * YROWH + u * 8) = o;
    }
    for (int i = tid; i < 32 * 33; i += 256) Ss[i] = 0.f;
    __syncthreads();

    // ldmatrix selectors
    const int aRow = (lane & 7) + 8 * ((lane >> 3) & 1);
    const int aC   = lane >> 4;
    const int bRow = (lane & 7) + 8 * ((lane >> 4) & 1);
    const int bC   = (lane >> 3) & 1;

    // phase 2: S partials, warp covers channels [warp*144, +144)
    {
        float acc[2][4][4];
#pragma unroll
        for (int im = 0; im < 2; im++)
#pragma unroll
            for (int in = 0; in < 4; in++)
#pragma unroll
                for (int c = 0; c < 4; c++) acc[im][in][c] = 0.f;
        const int kch0 = warp * 18;
#pragma unroll
        for (int ks = 0; ks < 9; ks++) {
            const int c0 = kch0 + 2 * ks;
            uint32_t af[2][4], bf[2][4];
#pragma unroll
            for (int im = 0; im < 2; im++)
                LDSM_X4(af[im], ysb + (uint32_t)(im * 16 + aRow) * YROWB
                                    + (uint32_t)(c0 + aC) * 16);
#pragma unroll
            for (int jn = 0; jn < 2; jn++)
                LDSM_X4(bf[jn], ysb + (uint32_t)(jn * 16 + bRow) * YROWB
                                    + (uint32_t)(c0 + bC) * 16);
#pragma unroll
            for (int im = 0; im < 2; im++)
#pragma unroll
                for (int jn = 0; jn < 2; jn++) {
                    mma_f16(acc[im][2 * jn],     af[im], bf[jn][0], bf[jn][1]);
                    mma_f16(acc[im][2 * jn + 1], af[im], bf[jn][2], bf[jn][3]);
                }
        }
        const int g = lane >> 2, t2 = lane & 3;
#pragma unroll
        for (int im = 0; im < 2; im++)
#pragma unroll
            for (int in = 0; in < 4; in++) {
                const int r0 = im * 16 + g, c0 = in * 8 + 2 * t2;
                atomicAdd(&Ss[r0 * 33 + c0],           acc[im][in][0]);
                atomicAdd(&Ss[r0 * 33 + c0 + 1],       acc[im][in][1]);
                atomicAdd(&Ss[(r0 + 8) * 33 + c0],     acc[im][in][2]);
                atomicAdd(&Ss[(r0 + 8) * 33 + c0 + 1], acc[im][in][3]);
            }
    }
    __syncthreads();

    // phase 3: softmax (fp32) -> P fp16
    {
        const float scale = 1.0f / sqrtf((float)CFEAT);
        for (int q = warp; q < 32; q += 8) {
            float v = Ss[q * 33 + lane] * scale;
            float m = v;
#pragma unroll
            for (int o = 16; o > 0; o >>= 1) m = fmaxf(m, __shfl_xor_sync(0xffffffffu, m, o));
            float e = expf(v - m);
            float sum = e;
#pragma unroll
            for (int o = 16; o > 0; o >>= 1) sum += __shfl_xor_sync(0xffffffffu, sum, o);
            Ps[q * PROWH + lane] = __float2half_rn(e / sum);
        }
    }
    __syncthreads();

    // phase 4: out = P @ Y (warp covers channels [warp*144, +144))
    {
        uint32_t af[2][2][4];     // [k16 step][m16 block]
#pragma unroll
        for (int kk = 0; kk < 2; kk++)
#pragma unroll
            for (int im = 0; im < 2; im++)
                LDSM_X4(af[kk][im], psb + (uint32_t)(im * 16 + aRow) * (PROWH * 2)
                                        + (uint32_t)(kk * 2 + aC) * 16);
        const int cch0 = warp * 18;
        const int g = lane >> 2, t2 = lane & 3;
#pragma unroll
        for (int jn = 0; jn < 9; jn++) {
            float acc[2][2][4];
#pragma unroll
            for (int im = 0; im < 2; im++)
#pragma unroll
                for (int in = 0; in < 2; in++)
#pragma unroll
                    for (int c = 0; c < 4; c++) acc[im][in][c] = 0.f;
#pragma unroll
            for (int kk = 0; kk < 2; kk++) {
                uint32_t bt[4];
                LDSM_X4_T(bt, ysb + (uint32_t)(kk * 16 + aRow) * YROWB
                                  + (uint32_t)(cch0 + 2 * jn + aC) * 16);
#pragma unroll
                for (int im = 0; im < 2; im++) {
                    mma_f16(acc[im][0], af[kk][im], bt[0], bt[1]);
                    mma_f16(acc[im][1], af[kk][im], bt[2], bt[3]);
                }
            }
#pragma unroll
            for (int im = 0; im < 2; im++) {
                const int row = im * 16 + g;
#pragma unroll
                for (int in = 0; in < 2; in++) {
                    const int col = warp * 144 + jn * 16 + in * 8 + 2 * t2;
                    *(float2*)(out + (base + row) * CFEAT + col) =
                        make_float2(acc[im][in][0], acc[im][in][1]);
                    *(float2*)(out + (base + row + 8) * CFEAT + col) =
                        make_float2(acc[im][in][2], acc[im][in][3]);
                }
            }
        }
    }
}

// ---------------- launch ----------------
extern "C" void kernel_launch(void* const* d_in, const int* in_sizes, int n_in,
                              void* d_out, int out_size)
{
    const float* x    = (const float*)d_in[0];
    const float* W1   = (const float*)d_in[1];
    const float* b1   = (const float*)d_in[2];
    const float* g1   = (const float*)d_in[3];
    const float* be1  = (const float*)d_in[4];
    const float* W2   = (const float*)d_in[5];
    const float* b2   = (const float*)d_in[6];
    const float* g2   = (const float*)d_in[7];
    const float* be2  = (const float*)d_in[8];
    const float* W3   = (const float*)d_in[9];
    const float* b3   = (const float*)d_in[10];
    const float* g3   = (const float*)d_in[11];
    const float* be3  = (const float*)d_in[12];
    const float* Wo   = (const float*)d_in[13];
    const float* bo   = (const float*)d_in[14];
    const float* caw1 = (const float*)d_in[15];
    const float* cab1 = (const float*)d_in[16];
    const float* caw2 = (const float*)d_in[17];
    const float* cab2 = (const float*)d_in[18];
    float* out = (float*)d_out;

    float *poolp, *sp;
    __half *xh, *h1h, *h2h, *h3h, *yh, *w1h, *w2h, *w3h, *woh;
    cudaGetSymbolAddress((void**)&poolp, g_pool);
    cudaGetSymbolAddress((void**)&sp,  g_s);
    cudaGetSymbolAddress((void**)&xh,  g_xh);
    cudaGetSymbolAddress((void**)&h1h, g_h1h);
    cudaGetSymbolAddress((void**)&h2h, g_h2h);
    cudaGetSymbolAddress((void**)&h3h, g_h3h);
    cudaGetSymbolAddress((void**)&yh,  g_yh);
    cudaGetSymbolAddress((void**)&w1h, g_w1h);
    cudaGetSymbolAddress((void**)&w2h, g_w2h);
    cudaGetSymbolAddress((void**)&w3h, g_w3h);
    cudaGetSymbolAddress((void**)&woh, g_woh);

    cudaFuncSetAttribute((const void*)mma_gemm<true, false>,
                         cudaFuncAttributeMaxDynamicSharedMemorySize, GEMM_SMEM_BYTES);
    cudaFuncSetAttribute((const void*)mma_gemm<false, true>,
                         cudaFuncAttributeMaxDynamicSharedMemorySize, GEMM_SMEM_BYTES);
    cudaFuncSetAttribute((const void*)attn_kernel,
                         cudaFuncAttributeMaxDynamicSharedMemorySize, ATTN_SMEM_BYTES);

    cudaMemsetAsync(poolp, 0, NBATCH * CFEAT * sizeof(float));

    // prep: x -> fp16; weights -> transposed fp16 [N][K]
    f2h_kernel<<<(MTOT * CFEAT / 8 + 255) / 256, 256>>>(
        (const float4*)x, (uint4*)xh, MTOT * CFEAT / 8);
    transpose_half<<<dim3(CFEAT / 32, HD1 / 32), 256>>>(W1, w1h, CFEAT, HD1);
    transpose_half<<<dim3(HD1 / 32, HD2 / 32), 256>>>(W2, w2h, HD1, HD2);
    transpose_half<<<dim3(HD2 / 32, HD3 / 32), 256>>>(W3, w3h, HD2, HD3);
    transpose_half<<<dim3(HD3 / 32, CFEAT / 32), 256>>>(Wo, woh, HD3, CFEAT);

    dim3 blk(256);
    // layer 1: LN(GELU(x @ W1 + b1)), LN in-place on fp16
    mma_gemm<true, false><<<dim3(HD1 / BN, MTOT / BM), blk, GEMM_SMEM_BYTES>>>(
        xh, w1h, b1, h1h, HD1, CFEAT, nullptr);
    ln_kernel<HD1><<<MTOT / 8, 256>>>(h1h, g1, be1, MTOT);
    // layer 2
    mma_gemm<true, false><<<dim3(HD2 / BN, MTOT / BM), blk, GEMM_SMEM_BYTES>>>(
        h1h, w2h, b2, h2h, HD2, HD1, nullptr);
    ln_kernel<HD2><<<MTOT / 8, 256>>>(h2h, g2, be2, MTOT);
    // layer 3
    mma_gemm<true, false><<<dim3(HD3 / BN, MTOT / BM), blk, GEMM_SMEM_BYTES>>>(
        h2h, w3h, b3, h3h, HD3, HD2, nullptr);
    ln_kernel<HD3><<<MTOT / 8, 256>>>(h3h, g3, be3, MTOT);
    // output projection (fp16 out) + fused pooled column sums
    mma_gemm<false, true><<<dim3(CFEAT / BN, MTOT / BM), blk, GEMM_SMEM_BYTES>>>(
        h3h, woh, bo, yh, CFEAT, HD3, poolp);
    // SE gate
    se_kernel<<<NBATCH, 256>>>(poolp, caw1, cab1, caw2, cab2, sp);
    // tensor-core SE-scale + windowed attention -> final output
    attn_kernel<<<NWIN, 256, ATTN_SMEM_BYTES>>>(yh, sp, out);
}

// round 10
// speedup vs baseline: 4.3074x; 1.0640x over previous
#include <cuda_runtime.h>
#include <cuda_fp16.h>
#include <math.h>
#include <stdint.h>

// ---------------- problem constants ----------------
#define MTOT   73728          // B*N = 8*9216 rows
#define CFEAT  1152
#define HD1    768
#define HD2    512
#define HD3    256
#define RED    144            // 1152/8
#define NSEQ   9216
#define NBATCH 8
#define WS     32
#define NWIN   2304           // 8 * 9216/32

// ---------------- scratch (no cudaMalloc allowed) ----------------
__device__ float  g_pool[NBATCH * CFEAT];
__device__ float  g_s   [NBATCH * CFEAT];
// fp16 activations (GEMM outputs / LN in-place / GEMM inputs)
__device__ __half g_xh [(size_t)MTOT * CFEAT];
__device__ __half g_h1h[(size_t)MTOT * HD1];
__device__ __half g_h2h[(size_t)MTOT * HD2];
__device__ __half g_h3h[(size_t)MTOT * HD3];
__device__ __half g_yh [(size_t)MTOT * CFEAT];  // GEMM4 out (fp16)
// transposed fp16 weights: [N][K]
__device__ __half g_w1h[HD1 * CFEAT];
__device__ __half g_w2h[HD2 * HD1];
__device__ __half g_w3h[HD3 * HD2];
__device__ __half g_woh[CFEAT * HD3];

__device__ __forceinline__ float gelu_exact(float x) {
    return 0.5f * x * (1.0f + erff(x * 0.70710678118654752f));
}

__device__ __forceinline__ uint32_t smem_u32(const void* p) {
    uint32_t a;
    asm("{ .reg .u64 t; cvta.to.shared.u64 t, %1; cvt.u32.u64 %0, t; }" : "=r"(a) : "l"(p));
    return a;
}
__device__ __forceinline__ void cp16(uint32_t dst, const void* src) {
    asm volatile("cp.async.cg.shared.global [%0], [%1], 16;" :: "r"(dst), "l"(src));
}
#define CP_COMMIT() asm volatile("cp.async.commit_group;")
#define CP_WAIT0()  asm volatile("cp.async.wait_group 0;")
#define CP_WAIT1()  asm volatile("cp.async.wait_group 1;")

#define LDSM_X4(r, a) \
    asm volatile("ldmatrix.sync.aligned.m8n8.x4.shared.b16 {%0,%1,%2,%3}, [%4];" \
                 : "=r"((r)[0]), "=r"((r)[1]), "=r"((r)[2]), "=r"((r)[3]) : "r"(a))
#define LDSM_X4_T(r, a) \
    asm volatile("ldmatrix.sync.aligned.m8n8.x4.trans.shared.b16 {%0,%1,%2,%3}, [%4];" \
                 : "=r"((r)[0]), "=r"((r)[1]), "=r"((r)[2]), "=r"((r)[3]) : "r"(a))

__device__ __forceinline__ void mma_f16(float* c, const uint32_t* a,
                                        uint32_t b0, uint32_t b1) {
    asm volatile(
        "mma.sync.aligned.m16n8k16.row.col.f32.f16.f16.f32 "
        "{%0,%1,%2,%3}, {%4,%5,%6,%7}, {%8,%9}, {%0,%1,%2,%3};"
        : "+f"(c[0]), "+f"(c[1]), "+f"(c[2]), "+f"(c[3])
        : "r"(a[0]), "r"(a[1]), "r"(a[2]), "r"(a[3]), "r"(b0), "r"(b1));
}

// ---------------- prep: x -> fp16 ----------------
__global__ void f2h_kernel(const float4* __restrict__ src, uint4* __restrict__ dst, int n8) {
    const int i = blockIdx.x * 256 + threadIdx.x;
    if (i < n8) {
        float4 a = src[2 * i], b = src[2 * i + 1];
        __half2 h0 = __floats2half2_rn(a.x, a.y);
        __half2 h1 = __floats2half2_rn(a.z, a.w);
        __half2 h2 = __floats2half2_rn(b.x, b.y);
        __half2 h3 = __floats2half2_rn(b.z, b.w);
        uint4 o;
        o.x = *(uint32_t*)&h0; o.y = *(uint32_t*)&h1;
        o.z = *(uint32_t*)&h2; o.w = *(uint32_t*)&h3;
        dst[i] = o;
    }
}

// ---------------- prep: all 4 weight transposes in ONE kernel ----------------
// blockIdx.y selects the weight; blockIdx.x is a linear tile id over (K/32, N/32).
__global__ void transpose_all(const float* __restrict__ W1, const float* __restrict__ W2,
                              const float* __restrict__ W3, const float* __restrict__ Wo,
                              __half* __restrict__ w1h, __half* __restrict__ w2h,
                              __half* __restrict__ w3h, __half* __restrict__ woh)
{
    __shared__ float t[32][33];
    const float* src; __half* dst; int K, N;
    switch (blockIdx.y) {
        case 0: src = W1; dst = w1h; K = CFEAT; N = HD1;  break;   // 36x24 tiles
        case 1: src = W2; dst = w2h; K = HD1;  N = HD2;   break;   // 24x16
        case 2: src = W3; dst = w3h; K = HD2;  N = HD3;   break;   // 16x8
        default: src = Wo; dst = woh; K = HD3; N = CFEAT; break;   // 8x36
    }
    const int ktiles = K / 32;
    const int tile = blockIdx.x;
    if (tile >= ktiles * (N / 32)) return;
    const int k0 = (tile % ktiles) * 32, n0 = (tile / ktiles) * 32;
    const int x = threadIdx.x & 31, y = threadIdx.x >> 5;
#pragma unroll
    for (int i = y; i < 32; i += 8)
        t[i][x] = src[(size_t)(k0 + i) * N + n0 + x];
    __syncthreads();
#pragma unroll
    for (int i = y; i < 32; i += 8)
        dst[(size_t)(n0 + i) * K + k0 + x] = __float2half_rn(t[x][i]);
}

// ---------------- fp16 tensor-core GEMM (m16n8k16 + ldmatrix, 3-stage) --------
// K is compile-time: fully unrolled/predictable mainloop.
#define BM 128
#define BN 128
#define BK 64
#define STAGE_BYTES (128 * 128)
#define NSTAGE 3
#define GEMM_SMEM_BYTES (2 * NSTAGE * STAGE_BYTES)   // 98304

template<int KDIM, bool DO_GELU, bool DO_POOL>
__global__ void __launch_bounds__(256, 2)
mma_gemm(const __half* __restrict__ A, const __half* __restrict__ Bt,
         const float* __restrict__ bias, __half* __restrict__ Cout,
         int N, float* __restrict__ pool)
{
    extern __shared__ __align__(128) char smem[];
    const uint32_t sb = smem_u32(smem);

    const int tid = threadIdx.x;
    const int warp = tid >> 5, lane = tid & 31;
    const int wy = warp >> 1, wx = warp & 1;

    const int aRow0 = wy * 32 + (lane & 7) + 8 * ((lane >> 3) & 1);
    const int aCsel = lane >> 4;
    const int bRow0 = wx * 64 + (lane & 7) + 8 * ((lane >> 4) & 1);
    const int bCsel = (lane >> 3) & 1;

    const int gr = tid >> 3, gu = tid & 7;
    const __half* Abase = A  + (size_t)(blockIdx.y * BM) * KDIM;
    const __half* Bbase = Bt + (size_t)(blockIdx.x * BN) * KDIM;

    float acc[2][8][4];
#pragma unroll
    for (int im = 0; im < 2; im++)
#pragma unroll
        for (int in = 0; in < 8; in++)
#pragma unroll
            for (int c = 0; c < 4; c++) acc[im][in][c] = 0.f;

    constexpr int nk = KDIM >> 6;   // BK=64

    const uint32_t soff = ((uint32_t)gr << 7) + (uint32_t)((gu ^ (gr & 7)) << 4);

    // prologue: issue stages 0 and 1
#pragma unroll
    for (int s = 0; s < 2 && s < nk; s++) {
        const int k0 = s << 6;
        const uint32_t ad = sb + s * STAGE_BYTES;
        const uint32_t bd = sb + (NSTAGE + s) * STAGE_BYTES;
#pragma unroll
        for (int j = 0; j < 4; j++) {
            const int r = gr + j * 32;
            const uint32_t off = soff + (uint32_t)(j * 32) * 128;
            cp16(ad + off, Abase + (size_t)r * KDIM + k0 + (gu << 3));
            cp16(bd + off, Bbase + (size_t)r * KDIM + k0 + (gu << 3));
        }
        CP_COMMIT();
    }

#pragma unroll
    for (int kt = 0; kt < nk; kt++) {
        const int buf = kt % NSTAGE;
        if (kt == nk - 1) { CP_WAIT0(); } else { CP_WAIT1(); }
        __syncthreads();

        if (kt + 2 < nk) {
            const int s = (kt + 2) % NSTAGE;
            const int k0 = (kt + 2) << 6;
            const uint32_t ad = sb + s * STAGE_BYTES;
            const uint32_t bd = sb + (NSTAGE + s) * STAGE_BYTES;
#pragma unroll
            for (int j = 0; j < 4; j++) {
                const int r = gr + j * 32;
                const uint32_t off = soff + (uint32_t)(j * 32) * 128;
                cp16(ad + off, Abase + (size_t)r * KDIM + k0 + (gu << 3));
                cp16(bd + off, Bbase + (size_t)r * KDIM + k0 + (gu << 3));
            }
            CP_COMMIT();
        }

        const uint32_t aB = sb + buf * STAGE_BYTES;
        const uint32_t bB = sb + (NSTAGE + buf) * STAGE_BYTES;
#pragma unroll
        for (int j = 0; j < 4; j++) {
            const int c0 = 2 * j;
            uint32_t af[2][4];
#pragma unroll
            for (int im = 0; im < 2; im++) {
                const int row = aRow0 + im * 16;
                const uint32_t addr = aB + ((uint32_t)row << 7)
                                    + (uint32_t)(((c0 + aCsel) ^ (row & 7)) << 4);
                LDSM_X4(af[im], addr);
            }
            uint32_t bf[4][4];
#pragma unroll
            for (int p = 0; p < 4; p++) {
                const int row = bRow0 + p * 16;
                const uint32_t addr = bB + ((uint32_t)row << 7)
                                    + (uint32_t)(((c0 + bCsel) ^ (row & 7)) << 4);
                LDSM_X4(bf[p], addr);
            }
#pragma unroll
            for (int im = 0; im < 2; im++)
#pragma unroll
                for (int p = 0; p < 4; p++) {
                    mma_f16(acc[im][2 * p],     af[im], bf[p][0], bf[p][1]);
                    mma_f16(acc[im][2 * p + 1], af[im], bf[p][2], bf[p][3]);
                }
        }
    }
    __syncthreads();

    // ---- epilogue: bias (+gelu), fp16 store; optional pooled column sums ----
    const int g = lane >> 2, t = lane & 3;
    float* csum = (float*)smem;
    if (DO_POOL) {
        if (tid < 128) csum[tid] = 0.f;
        __syncthreads();
    }

#pragma unroll
    for (int im = 0; im < 2; im++) {
        const int r0 = blockIdx.y * BM + wy * 32 + im * 16 + g;
#pragma unroll
        for (int in = 0; in < 8; in++) {
            const int col = blockIdx.x * BN + wx * 64 + in * 8 + 2 * t;
            const float bv0 = bias[col], bv1 = bias[col + 1];
            float v00 = acc[im][in][0] + bv0;
            float v01 = acc[im][in][1] + bv1;
            float v10 = acc[im][in][2] + bv0;
            float v11 = acc[im][in][3] + bv1;
            if (DO_GELU) {
                v00 = gelu_exact(v00); v01 = gelu_exact(v01);
                v10 = gelu_exact(v10); v11 = gelu_exact(v11);
            }
            *(__half2*)(Cout + (size_t)r0 * N + col)       = __floats2half2_rn(v00, v01);
            *(__half2*)(Cout + (size_t)(r0 + 8) * N + col) = __floats2half2_rn(v10, v11);
            if (DO_POOL) {
                const int lc = wx * 64 + in * 8 + 2 * t;
                atomicAdd(&csum[lc],     v00 + v10);
                atomicAdd(&csum[lc + 1], v01 + v11);
            }
        }
    }

    if (DO_POOL) {
        __syncthreads();
        if (tid < 128) {
            const int batch = (blockIdx.y * BM) / NSEQ;
            atomicAdd(&pool[batch * CFEAT + blockIdx.x * BN + tid], csum[tid]);
        }
    }
}

// ---------------- LayerNorm (warp per row): fp16 in-place, fp32 stats --------
template<int H>
__global__ void ln_kernel(__half* __restrict__ xio, const float* __restrict__ g,
                          const float* __restrict__ be, int M)
{
    const int warp = threadIdx.x >> 5, lane = threadIdx.x & 31;
    const int row = blockIdx.x * (blockDim.x >> 5) + warp;
    if (row >= M) return;
    __half2* p = (__half2*)(xio + (size_t)row * H);
    constexpr int NV = H / 64;   // half2 per lane
    float2 v[NV];
    float s = 0.f;
#pragma unroll
    for (int i = 0; i < NV; i++) {
        v[i] = __half22float2(p[lane + (i << 5)]);
        s += v[i].x + v[i].y;
    }
#pragma unroll
    for (int o = 16; o > 0; o >>= 1) s += __shfl_xor_sync(0xffffffffu, s, o);
    const float mu = s * (1.0f / H);
    float var = 0.f;
#pragma unroll
    for (int i = 0; i < NV; i++) {
        float d0 = v[i].x - mu, d1 = v[i].y - mu;
        var += d0 * d0 + d1 * d1;
    }
#pragma unroll
    for (int o = 16; o > 0; o >>= 1) var += __shfl_xor_sync(0xffffffffu, var, o);
    const float rstd = rsqrtf(var * (1.0f / H) + 1e-5f);
#pragma unroll
    for (int i = 0; i < NV; i++) {
        const int c = 2 * (lane + (i << 5));
        const float y0 = (v[i].x - mu) * rstd * g[c]     + be[c];
        const float y1 = (v[i].y - mu) * rstd * g[c + 1] + be[c + 1];
        p[lane + (i << 5)] = __floats2half2_rn(y0, y1);
    }
}

// ---------------- SE channel attention ----------------
__global__ void se_kernel(const float* __restrict__ pool,
                          const float* __restrict__ w1, const float* __restrict__ b1,
                          const float* __restrict__ w2, const float* __restrict__ b2,
                          float* __restrict__ s)
{
    __shared__ float p[CFEAT];
    __shared__ float hid[RED];
    const int b = blockIdx.x, t = threadIdx.x;
    for (int i = t; i < CFEAT; i += 256) p[i] = pool[b * CFEAT + i] * (1.0f / NSEQ);
    __syncthreads();
    if (t < RED) {
        float a = b1[t];
        for (int c = 0; c < CFEAT; c++) a = fmaf(p[c], w1[c * RED + t], a);
        hid[t] = fmaxf(a, 0.f);
    }
    __syncthreads();
    for (int c = t; c < CFEAT; c += 256) {
        float a = b2[c];
        for (int h = 0; h < RED; h++) a = fmaf(hid[h], w2[h * CFEAT + c], a);
        s[b * CFEAT + c] = 1.0f / (1.0f + expf(-a));
    }
}

// ---------------- tensor-core windowed attention ----------------
#define YROWH 1160
#define YROWB 2320
#define PROWH 40
#define ATTN_SS_OFF  (32 * YROWH * 2)                 // 74240
#define ATTN_PS_OFF  (ATTN_SS_OFF + 32 * 33 * 4)      // 78464
#define ATTN_SMEM_BYTES (ATTN_PS_OFF + 32 * PROWH * 2) // 81024

__global__ void __launch_bounds__(256, 2)
attn_kernel(const __half* __restrict__ y, const float* __restrict__ s,
            float* __restrict__ out)
{
    extern __shared__ __align__(128) char smem[];
    __half* Ys = (__half*)smem;
    float*  Ss = (float*)(smem + ATTN_SS_OFF);
    __half* Ps = (__half*)(smem + ATTN_PS_OFF);
    const uint32_t ysb = smem_u32(smem);
    const uint32_t psb = ysb + ATTN_PS_OFF;

    const int win = blockIdx.x;
    const int b = win / (NSEQ / WS);
    const size_t base = (size_t)win * 32;
    const int tid = threadIdx.x;
    const int warp = tid >> 5, lane = tid & 31;
    const float* sb = s + b * CFEAT;

    // phase 1: load fp16 y, scale by s, store padded rows
    for (int idx = tid; idx < 32 * 144; idx += 256) {
        const int r = idx / 144, u = idx - r * 144;
        uint4 raw = *(const uint4*)(y + (base + r) * CFEAT + u * 8);
        const float4 s0 = *(const float4*)(sb + u * 8);
        const float4 s1 = *(const float4*)(sb + u * 8 + 4);
        __half2* hp = (__half2*)&raw;
        float2 f0 = __half22float2(hp[0]);
        float2 f1 = __half22float2(hp[1]);
        float2 f2 = __half22float2(hp[2]);
        float2 f3 = __half22float2(hp[3]);
        uint4 o;
        __half2 t0 = __floats2half2_rn(f0.x * s0.x, f0.y * s0.y);
        __half2 t1 = __floats2half2_rn(f1.x * s0.z, f1.y * s0.w);
        __half2 t2 = __floats2half2_rn(f2.x * s1.x, f2.y * s1.y);
        __half2 t3 = __floats2half2_rn(f3.x * s1.z, f3.y * s1.w);
        o.x = *(uint32_t*)&t0; o.y = *(uint32_t*)&t1;
        o.z = *(uint32_t*)&t2; o.w = *(uint32_t*)&t3;
        *(uint4*)(Ys + r * YROWH + u * 8) = o;
    }
    for (int i = tid; i < 32 * 33; i += 256) Ss[i] = 0.f;
    __syncthreads();

    // ldmatrix selectors
    const int aRow = (lane & 7) + 8 * ((lane >> 3) & 1);
    const int aC   = lane >> 4;
    const int bRow = (lane & 7) + 8 * ((lane >> 4) & 1);
    const int bC   = (lane >> 3) & 1;

    // phase 2: S partials, warp covers channels [warp*144, +144)
    {
        float acc[2][4][4];
#pragma unroll
        for (int im = 0; im < 2; im++)
#pragma unroll
            for (int in = 0; in < 4; in++)
#pragma unroll
                for (int c = 0; c < 4; c++) acc[im][in][c] = 0.f;
        const int kch0 = warp * 18;
#pragma unroll
        for (int ks = 0; ks < 9; ks++) {
            const int c0 = kch0 + 2 * ks;
            uint32_t af[2][4], bf[2][4];
#pragma unroll
            for (int im = 0; im < 2; im++)
                LDSM_X4(af[im], ysb + (uint32_t)(im * 16 + aRow) * YROWB
                                    + (uint32_t)(c0 + aC) * 16);
#pragma unroll
            for (int jn = 0; jn < 2; jn++)
                LDSM_X4(bf[jn], ysb + (uint32_t)(jn * 16 + bRow) * YROWB
                                    + (uint32_t)(c0 + bC) * 16);
#pragma unroll
            for (int im = 0; im < 2; im++)
#pragma unroll
                for (int jn = 0; jn < 2; jn++) {
                    mma_f16(acc[im][2 * jn],     af[im], bf[jn][0], bf[jn][1]);
                    mma_f16(acc[im][2 * jn + 1], af[im], bf[jn][2], bf[jn][3]);
                }
        }
        const int g = lane >> 2, t2 = lane & 3;
#pragma unroll
        for (int im = 0; im < 2; im++)
#pragma unroll
            for (int in = 0; in < 4; in++) {
                const int r0 = im * 16 + g, c0 = in * 8 + 2 * t2;
                atomicAdd(&Ss[r0 * 33 + c0],           acc[im][in][0]);
                atomicAdd(&Ss[r0 * 33 + c0 + 1],       acc[im][in][1]);
                atomicAdd(&Ss[(r0 + 8) * 33 + c0],     acc[im][in][2]);
                atomicAdd(&Ss[(r0 + 8) * 33 + c0 + 1], acc[im][in][3]);
            }
    }
    __syncthreads();

    // phase 3: softmax (fp32) -> P fp16
    {
        const float scale = 1.0f / sqrtf((float)CFEAT);
        for (int q = warp; q < 32; q += 8) {
            float v = Ss[q * 33 + lane] * scale;
            float m = v;
#pragma unroll
            for (int o = 16; o > 0; o >>= 1) m = fmaxf(m, __shfl_xor_sync(0xffffffffu, m, o));
            float e = expf(v - m);
            float sum = e;
#pragma unroll
            for (int o = 16; o > 0; o >>= 1) sum += __shfl_xor_sync(0xffffffffu, sum, o);
            Ps[q * PROWH + lane] = __float2half_rn(e / sum);
        }
    }
    __syncthreads();

    // phase 4: out = P @ Y (warp covers channels [warp*144, +144))
    {
        uint32_t af[2][2][4];     // [k16 step][m16 block]
#pragma unroll
        for (int kk = 0; kk < 2; kk++)
#pragma unroll
            for (int im = 0; im < 2; im++)
                LDSM_X4(af[kk][im], psb + (uint32_t)(im * 16 + aRow) * (PROWH * 2)
                                        + (uint32_t)(kk * 2 + aC) * 16);
        const int cch0 = warp * 18;
        const int g = lane >> 2, t2 = lane & 3;
#pragma unroll
        for (int jn = 0; jn < 9; jn++) {
            float acc[2][2][4];
#pragma unroll
            for (int im = 0; im < 2; im++)
#pragma unroll
                for (int in = 0; in < 2; in++)
#pragma unroll
                    for (int c = 0; c < 4; c++) acc[im][in][c] = 0.f;
#pragma unroll
            for (int kk = 0; kk < 2; kk++) {
                uint32_t bt[4];
                LDSM_X4_T(bt, ysb + (uint32_t)(kk * 16 + aRow) * YROWB
                                  + (uint32_t)(cch0 + 2 * jn + aC) * 16);
#pragma unroll
                for (int im = 0; im < 2; im++) {
                    mma_f16(acc[im][0], af[kk][im], bt[0], bt[1]);
                    mma_f16(acc[im][1], af[kk][im], bt[2], bt[3]);
                }
            }
#pragma unroll
            for (int im = 0; im < 2; im++) {
                const int row = im * 16 + g;
#pragma unroll
                for (int in = 0; in < 2; in++) {
                    const int col = warp * 144 + jn * 16 + in * 8 + 2 * t2;
                    *(float2*)(out + (base + row) * CFEAT + col) =
                        make_float2(acc[im][in][0], acc[im][in][1]);
                    *(float2*)(out + (base + row + 8) * CFEAT + col) =
                        make_float2(acc[im][in][2], acc[im][in][3]);
                }
            }
        }
    }
}

// ---------------- launch ----------------
extern "C" void kernel_launch(void* const* d_in, const int* in_sizes, int n_in,
                              void* d_out, int out_size)
{
    const float* x    = (const float*)d_in[0];
    const float* W1   = (const float*)d_in[1];
    const float* b1   = (const float*)d_in[2];
    const float* g1   = (const float*)d_in[3];
    const float* be1  = (const float*)d_in[4];
    const float* W2   = (const float*)d_in[5];
    const float* b2   = (const float*)d_in[6];
    const float* g2   = (const float*)d_in[7];
    const float* be2  = (const float*)d_in[8];
    const float* W3   = (const float*)d_in[9];
    const float* b3   = (const float*)d_in[10];
    const float* g3   = (const float*)d_in[11];
    const float* be3  = (const float*)d_in[12];
    const float* Wo   = (const float*)d_in[13];
    const float* bo   = (const float*)d_in[14];
    const float* caw1 = (const float*)d_in[15];
    const float* cab1 = (const float*)d_in[16];
    const float* caw2 = (const float*)d_in[17];
    const float* cab2 = (const float*)d_in[18];
    float* out = (float*)d_out;

    float *poolp, *sp;
    __half *xh, *h1h, *h2h, *h3h, *yh, *w1h, *w2h, *w3h, *woh;
    cudaGetSymbolAddress((void**)&poolp, g_pool);
    cudaGetSymbolAddress((void**)&sp,  g_s);
    cudaGetSymbolAddress((void**)&xh,  g_xh);
    cudaGetSymbolAddress((void**)&h1h, g_h1h);
    cudaGetSymbolAddress((void**)&h2h, g_h2h);
    cudaGetSymbolAddress((void**)&h3h, g_h3h);
    cudaGetSymbolAddress((void**)&yh,  g_yh);
    cudaGetSymbolAddress((void**)&w1h, g_w1h);
    cudaGetSymbolAddress((void**)&w2h, g_w2h);
    cudaGetSymbolAddress((void**)&w3h, g_w3h);
    cudaGetSymbolAddress((void**)&woh, g_woh);

    cudaFuncSetAttribute((const void*)mma_gemm<CFEAT, true, false>,
                         cudaFuncAttributeMaxDynamicSharedMemorySize, GEMM_SMEM_BYTES);
    cudaFuncSetAttribute((const void*)mma_gemm<HD1, true, false>,
                         cudaFuncAttributeMaxDynamicSharedMemorySize, GEMM_SMEM_BYTES);
    cudaFuncSetAttribute((const void*)mma_gemm<HD2, true, false>,
                         cudaFuncAttributeMaxDynamicSharedMemorySize, GEMM_SMEM_BYTES);
    cudaFuncSetAttribute((const void*)mma_gemm<HD3, false, true>,
                         cudaFuncAttributeMaxDynamicSharedMemorySize, GEMM_SMEM_BYTES);
    cudaFuncSetAttribute((const void*)attn_kernel,
                         cudaFuncAttributeMaxDynamicSharedMemorySize, ATTN_SMEM_BYTES);

    // Launch order chosen so ncu (-s 5 -c 1) profiles launch #6 = GEMM2:
    //   1:f2h  2:transpose_all  3:memset  4:GEMM1  5:LN1  6:GEMM2
    f2h_kernel<<<(MTOT * CFEAT / 8 + 255) / 256, 256>>>(
        (const float4*)x, (uint4*)xh, MTOT * CFEAT / 8);
    {
        // max tiles over the 4 weights: W1 has (1152/32)*(768/32) = 864
        transpose_all<<<dim3(864, 4), 256>>>(W1, W2, W3, Wo, w1h, w2h, w3h, woh);
    }
    cudaMemsetAsync(poolp, 0, NBATCH * CFEAT * sizeof(float));

    dim3 blk(256);
    // layer 1: LN(GELU(x @ W1 + b1)), LN in-place on fp16
    mma_gemm<CFEAT, true, false><<<dim3(HD1 / BN, MTOT / BM), blk, GEMM_SMEM_BYTES>>>(
        xh, w1h, b1, h1h, HD1, nullptr);
    ln_kernel<HD1><<<MTOT / 8, 256>>>(h1h, g1, be1, MTOT);
    // layer 2  (profiled by ncu)
    mma_gemm<HD1, true, false><<<dim3(HD2 / BN, MTOT / BM), blk, GEMM_SMEM_BYTES>>>(
        h1h, w2h, b2, h2h, HD2, nullptr);
    ln_kernel<HD2><<<MTOT / 8, 256>>>(h2h, g2, be2, MTOT);
    // layer 3
    mma_gemm<HD2, true, false><<<dim3(HD3 / BN, MTOT / BM), blk, GEMM_SMEM_BYTES>>>(
        h2h, w3h, b3, h3h, HD3, nullptr);
    ln_kernel<HD3><<<MTOT / 8, 256>>>(h3h, g3, be3, MTOT);
    // output projection (fp16 out) + fused pooled column sums
    mma_gemm<HD3, false, true><<<dim3(CFEAT / BN, MTOT / BM), blk, GEMM_SMEM_BYTES>>>(
        h3h, woh, bo, yh, CFEAT, poolp);
    // SE gate
    se_kernel<<<NBATCH, 256>>>(poolp, caw1, cab1, caw2, cab2, sp);
    // tensor-core SE-scale + windowed attention -> final output
    attn_kernel<<<NWIN, 256, ATTN_SMEM_BYTES>>>(yh, sp, out);
}

// round 13
// speedup vs baseline: 4.3347x; 1.0063x over previous
#include <cuda_runtime.h>
#include <cuda_fp16.h>
#include <math.h>
#include <stdint.h>

// ---------------- problem constants ----------------
#define MTOT   73728          // B*N = 8*9216 rows
#define CFEAT  1152
#define HD1    768
#define HD2    512
#define HD3    256
#define RED    144            // 1152/8
#define NSEQ   9216
#define NBATCH 8
#define WS     32
#define NWIN   2304           // 8 * 9216/32

// ---------------- scratch (no cudaMalloc allowed) ----------------
__device__ float  g_pool[NBATCH * CFEAT];
__device__ float  g_s   [NBATCH * CFEAT];
// fp16 activations (GEMM outputs / LN in-place / GEMM inputs)
__device__ __half g_xh [(size_t)MTOT * CFEAT];
__device__ __half g_h1h[(size_t)MTOT * HD1];
__device__ __half g_h2h[(size_t)MTOT * HD2];
__device__ __half g_h3h[(size_t)MTOT * HD3];
__device__ __half g_yh [(size_t)MTOT * CFEAT];  // GEMM4 out (fp16)
// transposed fp16 weights: [N][K]
__device__ __half g_w1h[HD1 * CFEAT];
__device__ __half g_w2h[HD2 * HD1];
__device__ __half g_w3h[HD3 * HD2];
__device__ __half g_woh[CFEAT * HD3];

__device__ __forceinline__ float gelu_exact(float x) {
    return 0.5f * x * (1.0f + erff(x * 0.70710678118654752f));
}

__device__ __forceinline__ uint32_t smem_u32(const void* p) {
    uint32_t a;
    asm("{ .reg .u64 t; cvta.to.shared.u64 t, %1; cvt.u32.u64 %0, t; }" : "=r"(a) : "l"(p));
    return a;
}
__device__ __forceinline__ void cp16(uint32_t dst, const void* src) {
    asm volatile("cp.async.cg.shared.global [%0], [%1], 16;" :: "r"(dst), "l"(src));
}
#define CP_COMMIT() asm volatile("cp.async.commit_group;")
#define CP_WAIT0()  asm volatile("cp.async.wait_group 0;")
#define CP_WAIT1()  asm volatile("cp.async.wait_group 1;")

#define LDSM_X4(r, a) \
    asm volatile("ldmatrix.sync.aligned.m8n8.x4.shared.b16 {%0,%1,%2,%3}, [%4];" \
                 : "=r"((r)[0]), "=r"((r)[1]), "=r"((r)[2]), "=r"((r)[3]) : "r"(a))
#define LDSM_X4_T(r, a) \
    asm volatile("ldmatrix.sync.aligned.m8n8.x4.trans.shared.b16 {%0,%1,%2,%3}, [%4];" \
                 : "=r"((r)[0]), "=r"((r)[1]), "=r"((r)[2]), "=r"((r)[3]) : "r"(a))

__device__ __forceinline__ void mma_f16(float* c, const uint32_t* a,
                                        uint32_t b0, uint32_t b1) {
    asm volatile(
        "mma.sync.aligned.m16n8k16.row.col.f32.f16.f16.f32 "
        "{%0,%1,%2,%3}, {%4,%5,%6,%7}, {%8,%9}, {%0,%1,%2,%3};"
        : "+f"(c[0]), "+f"(c[1]), "+f"(c[2]), "+f"(c[3])
        : "r"(a[0]), "r"(a[1]), "r"(a[2]), "r"(a[3]), "r"(b0), "r"(b1));
}

// ---------------- prep: x -> fp16 ----------------
__global__ void f2h_kernel(const float4* __restrict__ src, uint4* __restrict__ dst, int n8) {
    const int i = blockIdx.x * 256 + threadIdx.x;
    if (i < n8) {
        float4 a = src[2 * i], b = src[2 * i + 1];
        __half2 h0 = __floats2half2_rn(a.x, a.y);
        __half2 h1 = __floats2half2_rn(a.z, a.w);
        __half2 h2 = __floats2half2_rn(b.x, b.y);
        __half2 h3 = __floats2half2_rn(b.z, b.w);
        uint4 o;
        o.x = *(uint32_t*)&h0; o.y = *(uint32_t*)&h1;
        o.z = *(uint32_t*)&h2; o.w = *(uint32_t*)&h3;
        dst[i] = o;
    }
}

// ---------------- prep: all 4 weight transposes in ONE kernel ----------------
__global__ void transpose_all(const float* __restrict__ W1, const float* __restrict__ W2,
                              const float* __restrict__ W3, const float* __restrict__ Wo,
                              __half* __restrict__ w1h, __half* __restrict__ w2h,
                              __half* __restrict__ w3h, __half* __restrict__ woh)
{
    __shared__ float t[32][33];
    const float* src; __half* dst; int K, N;
    switch (blockIdx.y) {
        case 0: src = W1; dst = w1h; K = CFEAT; N = HD1;  break;   // 36x24 tiles
        case 1: src = W2; dst = w2h; K = HD1;  N = HD2;   break;   // 24x16
        case 2: src = W3; dst = w3h; K = HD2;  N = HD3;   break;   // 16x8
        default: src = Wo; dst = woh; K = HD3; N = CFEAT; break;   // 8x36
    }
    const int ktiles = K / 32;
    const int tile = blockIdx.x;
    if (tile >= ktiles * (N / 32)) return;
    const int k0 = (tile % ktiles) * 32, n0 = (tile / ktiles) * 32;
    const int x = threadIdx.x & 31, y = threadIdx.x >> 5;
#pragma unroll
    for (int i = y; i < 32; i += 8)
        t[i][x] = src[(size_t)(k0 + i) * N + n0 + x];
    __syncthreads();
#pragma unroll
    for (int i = y; i < 32; i += 8)
        dst[(size_t)(n0 + i) * K + k0 + x] = __float2half_rn(t[x][i]);
}

// ---------------- fp16 tensor-core GEMM (m16n8k16 + ldmatrix, 3-stage) --------
#define BM 128
#define BN 128
#define BK 64
#define STAGE_BYTES (128 * 128)
#define NSTAGE 3
#define GEMM_SMEM_BYTES (2 * NSTAGE * STAGE_BYTES)   // 98304

template<int KDIM, bool DO_GELU, bool DO_POOL>
__global__ void __launch_bounds__(256, 2)
mma_gemm(const __half* __restrict__ A, const __half* __restrict__ Bt,
         const float* __restrict__ bias, __half* __restrict__ Cout,
         int N, float* __restrict__ pool)
{
    extern __shared__ __align__(128) char smem[];
    const uint32_t sb = smem_u32(smem);

    const int tid = threadIdx.x;
    const int warp = tid >> 5, lane = tid & 31;
    const int wy = warp >> 1, wx = warp & 1;

    const int aRow0 = wy * 32 + (lane & 7) + 8 * ((lane >> 3) & 1);
    const int aCsel = lane >> 4;
    const int bRow0 = wx * 64 + (lane & 7) + 8 * ((lane >> 4) & 1);
    const int bCsel = (lane >> 3) & 1;

    const int gr = tid >> 3, gu = tid & 7;
    const __half* Abase = A  + (size_t)(blockIdx.y * BM) * KDIM;
    const __half* Bbase = Bt + (size_t)(blockIdx.x * BN) * KDIM;

    float acc[2][8][4];
#pragma unroll
    for (int im = 0; im < 2; im++)
#pragma unroll
        for (int in = 0; in < 8; in++)
#pragma unroll
            for (int c = 0; c < 4; c++) acc[im][in][c] = 0.f;

    constexpr int nk = KDIM >> 6;   // BK=64

    const uint32_t soff = ((uint32_t)gr << 7) + (uint32_t)((gu ^ (gr & 7)) << 4);

    // prologue: issue stages 0 and 1
#pragma unroll
    for (int s = 0; s < 2 && s < nk; s++) {
        const int k0 = s << 6;
        const uint32_t ad = sb + s * STAGE_BYTES;
        const uint32_t bd = sb + (NSTAGE + s) * STAGE_BYTES;
#pragma unroll
        for (int j = 0; j < 4; j++) {
            const int r = gr + j * 32;
            const uint32_t off = soff + (uint32_t)(j * 32) * 128;
            cp16(ad + off, Abase + (size_t)r * KDIM + k0 + (gu << 3));
            cp16(bd + off, Bbase + (size_t)r * KDIM + k0 + (gu << 3));
        }
        CP_COMMIT();
    }

#pragma unroll
    for (int kt = 0; kt < nk; kt++) {
        const int buf = kt % NSTAGE;
        if (kt == nk - 1) { CP_WAIT0(); } else { CP_WAIT1(); }
        __syncthreads();

        if (kt + 2 < nk) {
            const int s = (kt + 2) % NSTAGE;
            const int k0 = (kt + 2) << 6;
            const uint32_t ad = sb + s * STAGE_BYTES;
            const uint32_t bd = sb + (NSTAGE + s) * STAGE_BYTES;
#pragma unroll
            for (int j = 0; j < 4; j++) {
                const int r = gr + j * 32;
                const uint32_t off = soff + (uint32_t)(j * 32) * 128;
                cp16(ad + off, Abase + (size_t)r * KDIM + k0 + (gu << 3));
                cp16(bd + off, Bbase + (size_t)r * KDIM + k0 + (gu << 3));
            }
            CP_COMMIT();
        }

        const uint32_t aB = sb + buf * STAGE_BYTES;
        const uint32_t bB = sb + (NSTAGE + buf) * STAGE_BYTES;
#pragma unroll
        for (int j = 0; j < 4; j++) {
            const int c0 = 2 * j;
            uint32_t af[2][4];
#pragma unroll
            for (int im = 0; im < 2; im++) {
                const int row = aRow0 + im * 16;
                const uint32_t addr = aB + ((uint32_t)row << 7)
                                    + (uint32_t)(((c0 + aCsel) ^ (row & 7)) << 4);
                LDSM_X4(af[im], addr);
            }
            uint32_t bf[4][4];
#pragma unroll
            for (int p = 0; p < 4; p++) {
                const int row = bRow0 + p * 16;
                const uint32_t addr = bB + ((uint32_t)row << 7)
                                    + (uint32_t)(((c0 + bCsel) ^ (row & 7)) << 4);
                LDSM_X4(bf[p], addr);
            }
#pragma unroll
            for (int im = 0; im < 2; im++)
#pragma unroll
                for (int p = 0; p < 4; p++) {
                    mma_f16(acc[im][2 * p],     af[im], bf[p][0], bf[p][1]);
                    mma_f16(acc[im][2 * p + 1], af[im], bf[p][2], bf[p][3]);
                }
        }
    }
    __syncthreads();

    // ---- epilogue: bias (+gelu), fp16 store; optional pooled column sums ----
    const int g = lane >> 2, t = lane & 3;
    float* csum = (float*)smem;
    if (DO_POOL) {
        if (tid < 128) csum[tid] = 0.f;
        __syncthreads();
    }

#pragma unroll
    for (int im = 0; im < 2; im++) {
        const int r0 = blockIdx.y * BM + wy * 32 + im * 16 + g;
#pragma unroll
        for (int in = 0; in < 8; in++) {
            const int col = blockIdx.x * BN + wx * 64 + in * 8 + 2 * t;
            const float bv0 = bias[col], bv1 = bias[col + 1];
            float v00 = acc[im][in][0] + bv0;
            float v01 = acc[im][in][1] + bv1;
            float v10 = acc[im][in][2] + bv0;
            float v11 = acc[im][in][3] + bv1;
            if (DO_GELU) {
                v00 = gelu_exact(v00); v01 = gelu_exact(v01);
                v10 = gelu_exact(v10); v11 = gelu_exact(v11);
            }
            *(__half2*)(Cout + (size_t)r0 * N + col)       = __floats2half2_rn(v00, v01);
            *(__half2*)(Cout + (size_t)(r0 + 8) * N + col) = __floats2half2_rn(v10, v11);
            if (DO_POOL) {
                const int lc = wx * 64 + in * 8 + 2 * t;
                atomicAdd(&csum[lc],     v00 + v10);
                atomicAdd(&csum[lc + 1], v01 + v11);
            }
        }
    }

    if (DO_POOL) {
        __syncthreads();
        if (tid < 128) {
            const int batch = (blockIdx.y * BM) / NSEQ;
            atomicAdd(&pool[batch * CFEAT + blockIdx.x * BN + tid], csum[tid]);
        }
    }
}

// ---------------- LayerNorm (warp per row): fp16 in-place, fp32 stats --------
template<int H>
__global__ void ln_kernel(__half* __restrict__ xio, const float* __restrict__ g,
                          const float* __restrict__ be, int M)
{
    const int warp = threadIdx.x >> 5, lane = threadIdx.x & 31;
    const int row = blockIdx.x * (blockDim.x >> 5) + warp;
    if (row >= M) return;
    __half2* p = (__half2*)(xio + (size_t)row * H);
    constexpr int NV = H / 64;   // half2 per lane
    float2 v[NV];
    float s = 0.f;
#pragma unroll
    for (int i = 0; i < NV; i++) {
        v[i] = __half22float2(p[lane + (i << 5)]);
        s += v[i].x + v[i].y;
    }
#pragma unroll
    for (int o = 16; o > 0; o >>= 1) s += __shfl_xor_sync(0xffffffffu, s, o);
    const float mu = s * (1.0f / H);
    float var = 0.f;
#pragma unroll
    for (int i = 0; i < NV; i++) {
        float d0 = v[i].x - mu, d1 = v[i].y - mu;
        var += d0 * d0 + d1 * d1;
    }
#pragma unroll
    for (int o = 16; o > 0; o >>= 1) var += __shfl_xor_sync(0xffffffffu, var, o);
    const float rstd = rsqrtf(var * (1.0f / H) + 1e-5f);
#pragma unroll
    for (int i = 0; i < NV; i++) {
        const int c = 2 * (lane + (i << 5));
        const float y0 = (v[i].x - mu) * rstd * g[c]     + be[c];
        const float y1 = (v[i].y - mu) * rstd * g[c + 1] + be[c + 1];
        p[lane + (i << 5)] = __floats2half2_rn(y0, y1);
    }
}

// ---------------- SE channel attention ----------------
__global__ void se_kernel(const float* __restrict__ pool,
                          const float* __restrict__ w1, const float* __restrict__ b1,
                          const float* __restrict__ w2, const float* __restrict__ b2,
                          float* __restrict__ s)
{
    __shared__ float p[CFEAT];
    __shared__ float hid[RED];
    const int b = blockIdx.x, t = threadIdx.x;
    for (int i = t; i < CFEAT; i += 256) p[i] = pool[b * CFEAT + i] * (1.0f / NSEQ);
    __syncthreads();
    if (t < RED) {
        float a = b1[t];
        for (int c = 0; c < CFEAT; c++) a = fmaf(p[c], w1[c * RED + t], a);
        hid[t] = fmaxf(a, 0.f);
    }
    __syncthreads();
    for (int c = t; c < CFEAT; c += 256) {
        float a = b2[c];
        for (int h = 0; h < RED; h++) a = fmaf(hid[h], w2[h * CFEAT + c], a);
        s[b * CFEAT + c] = 1.0f / (1.0f + expf(-a));
    }
}

// ---------------- tensor-core windowed attention ----------------
#define YROWH 1160
#define YROWB 2320
#define PROWH 40
#define ATTN_SS_OFF  (32 * YROWH * 2)                 // 74240
#define ATTN_PS_OFF  (ATTN_SS_OFF + 32 * 33 * 4)      // 78464
#define ATTN_SMEM_BYTES (ATTN_PS_OFF + 32 * PROWH * 2) // 81024

__global__ void __launch_bounds__(256, 2)
attn_kernel(const __half* __restrict__ y, const float* __restrict__ s,
            float* __restrict__ out)
{
    extern __shared__ __align__(128) char smem[];
    __half* Ys = (__half*)smem;
    float*  Ss = (float*)(smem + ATTN_SS_OFF);
    __half* Ps = (__half*)(smem + ATTN_PS_OFF);
    const uint32_t ysb = smem_u32(smem);
    const uint32_t psb = ysb + ATTN_PS_OFF;

    const int win = blockIdx.x;
    const int b = win / (NSEQ / WS);
    const size_t base = (size_t)win * 32;
    const int tid = threadIdx.x;
    const int warp = tid >> 5, lane = tid & 31;
    const float* sb = s + b * CFEAT;

    // phase 1: load fp16 y, scale by s, store padded rows
    for (int idx = tid; idx < 32 * 144; idx += 256) {
        const int r = idx / 144, u = idx - r * 144;
        uint4 raw = *(const uint4*)(y + (base + r) * CFEAT + u * 8);
        const float4 s0 = *(const float4*)(sb + u * 8);
        const float4 s1 = *(const float4*)(sb + u * 8 + 4);
        __half2* hp = (__half2*)&raw;
        float2 f0 = __half22float2(hp[0]);
        float2 f1 = __half22float2(hp[1]);
        float2 f2 = __half22float2(hp[2]);
        float2 f3 = __half22float2(hp[3]);
        uint4 o;
        __half2 t0 = __floats2half2_rn(f0.x * s0.x, f0.y * s0.y);
        __half2 t1 = __floats2half2_rn(f1.x * s0.z, f1.y * s0.w);
        __half2 t2 = __floats2half2_rn(f2.x * s1.x, f2.y * s1.y);
        __half2 t3 = __floats2half2_rn(f3.x * s1.z, f3.y * s1.w);
        o.x = *(uint32_t*)&t0; o.y = *(uint32_t*)&t1;
        o.z = *(uint32_t*)&t2; o.w = *(uint32_t*)&t3;
        *(uint4*)(Ys + r * YROWH + u * 8) = o;
    }
    for (int i = tid; i < 32 * 33; i += 256) Ss[i] = 0.f;
    __syncthreads();

    // ldmatrix selectors
    const int aRow = (lane & 7) + 8 * ((lane >> 3) & 1);
    const int aC   = lane >> 4;
    const int bRow = (lane & 7) + 8 * ((lane >> 4) & 1);
    const int bC   = (lane >> 3) & 1;

    // phase 2: S partials, warp covers channels [warp*144, +144)
    {
        float acc[2][4][4];
#pragma unroll
        for (int im = 0; im < 2; im++)
#pragma unroll
            for (int in = 0; in < 4; in++)
#pragma unroll
                for (int c = 0; c < 4; c++) acc[im][in][c] = 0.f;
        const int kch0 = warp * 18;
#pragma unroll
        for (int ks = 0; ks < 9; ks++) {
            const int c0 = kch0 + 2 * ks;
            uint32_t af[2][4], bf[2][4];
#pragma unroll
            for (int im = 0; im < 2; im++)
                LDSM_X4(af[im], ysb + (uint32_t)(im * 16 + aRow) * YROWB
                                    + (uint32_t)(c0 + aC) * 16);
#pragma unroll
            for (int jn = 0; jn < 2; jn++)
                LDSM_X4(bf[jn], ysb + (uint32_t)(jn * 16 + bRow) * YROWB
                                    + (uint32_t)(c0 + bC) * 16);
#pragma unroll
            for (int im = 0; im < 2; im++)
#pragma unroll
                for (int jn = 0; jn < 2; jn++) {
                    mma_f16(acc[im][2 * jn],     af[im], bf[jn][0], bf[jn][1]);
                    mma_f16(acc[im][2 * jn + 1], af[im], bf[jn][2], bf[jn][3]);
                }
        }
        const int g = lane >> 2, t2 = lane & 3;
#pragma unroll
        for (int im = 0; im < 2; im++)
#pragma unroll
            for (int in = 0; in < 4; in++) {
                const int r0 = im * 16 + g, c0 = in * 8 + 2 * t2;
                atomicAdd(&Ss[r0 * 33 + c0],           acc[im][in][0]);
                atomicAdd(&Ss[r0 * 33 + c0 + 1],       acc[im][in][1]);
                atomicAdd(&Ss[(r0 + 8) * 33 + c0],     acc[im][in][2]);
                atomicAdd(&Ss[(r0 + 8) * 33 + c0 + 1], acc[im][in][3]);
            }
    }
    __syncthreads();

    // phase 3: softmax (fp32) -> P fp16
    {
        const float scale = 1.0f / sqrtf((float)CFEAT);
        for (int q = warp; q < 32; q += 8) {
            float v = Ss[q * 33 + lane] * scale;
            float m = v;
#pragma unroll
            for (int o = 16; o > 0; o >>= 1) m = fmaxf(m, __shfl_xor_sync(0xffffffffu, m, o));
            float e = expf(v - m);
            float sum = e;
#pragma unroll
            for (int o = 16; o > 0; o >>= 1) sum += __shfl_xor_sync(0xffffffffu, sum, o);
            Ps[q * PROWH + lane] = __float2half_rn(e / sum);
        }
    }
    __syncthreads();

    // phase 4: out = P @ Y (warp covers channels [warp*144, +144))
    {
        uint32_t af[2][2][4];     // [k16 step][m16 block]
#pragma unroll
        for (int kk = 0; kk < 2; kk++)
#pragma unroll
            for (int im = 0; im < 2; im++)
                LDSM_X4(af[kk][im], psb + (uint32_t)(im * 16 + aRow) * (PROWH * 2)
                                        + (uint32_t)(kk * 2 + aC) * 16);
        const int cch0 = warp * 18;
        const int g = lane >> 2, t2 = lane & 3;
#pragma unroll
        for (int jn = 0; jn < 9; jn++) {
            float acc[2][2][4];
#pragma unroll
            for (int im = 0; im < 2; im++)
#pragma unroll
                for (int in = 0; in < 2; in++)
#pragma unroll
                    for (int c = 0; c < 4; c++) acc[im][in][c] = 0.f;
#pragma unroll
            for (int kk = 0; kk < 2; kk++) {
                uint32_t bt[4];
                LDSM_X4_T(bt, ysb + (uint32_t)(kk * 16 + aRow) * YROWB
                                  + (uint32_t)(cch0 + 2 * jn + aC) * 16);
#pragma unroll
                for (int im = 0; im < 2; im++) {
                    mma_f16(acc[im][0], af[kk][im], bt[0], bt[1]);
                    mma_f16(acc[im][1], af[kk][im], bt[2], bt[3]);
                }
            }
#pragma unroll
            for (int im = 0; im < 2; im++) {
                const int row = im * 16 + g;
#pragma unroll
                for (int in = 0; in < 2; in++) {
                    const int col = warp * 144 + jn * 16 + in * 8 + 2 * t2;
                    *(float2*)(out + (base + row) * CFEAT + col) =
                        make_float2(acc[im][in][0], acc[im][in][1]);
                    *(float2*)(out + (base + row + 8) * CFEAT + col) =
                        make_float2(acc[im][in][2], acc[im][in][3]);
                }
            }
        }
    }
}

// ---------------- launch ----------------
extern "C" void kernel_launch(void* const* d_in, const int* in_sizes, int n_in,
                              void* d_out, int out_size)
{
    const float* x    = (const float*)d_in[0];
    const float* W1   = (const float*)d_in[1];
    const float* b1   = (const float*)d_in[2];
    const float* g1   = (const float*)d_in[3];
    const float* be1  = (const float*)d_in[4];
    const float* W2   = (const float*)d_in[5];
    const float* b2   = (const float*)d_in[6];
    const float* g2   = (const float*)d_in[7];
    const float* be2  = (const float*)d_in[8];
    const float* W3   = (const float*)d_in[9];
    const float* b3   = (const float*)d_in[10];
    const float* g3   = (const float*)d_in[11];
    const float* be3  = (const float*)d_in[12];
    const float* Wo   = (const float*)d_in[13];
    const float* bo   = (const float*)d_in[14];
    const float* caw1 = (const float*)d_in[15];
    const float* cab1 = (const float*)d_in[16];
    const float* caw2 = (const float*)d_in[17];
    const float* cab2 = (const float*)d_in[18];
    float* out = (float*)d_out;

    float *poolp, *sp;
    __half *xh, *h1h, *h2h, *h3h, *yh, *w1h, *w2h, *w3h, *woh;
    cudaGetSymbolAddress((void**)&poolp, g_pool);
    cudaGetSymbolAddress((void**)&sp,  g_s);
    cudaGetSymbolAddress((void**)&xh,  g_xh);
    cudaGetSymbolAddress((void**)&h1h, g_h1h);
    cudaGetSymbolAddress((void**)&h2h, g_h2h);
    cudaGetSymbolAddress((void**)&h3h, g_h3h);
    cudaGetSymbolAddress((void**)&yh,  g_yh);
    cudaGetSymbolAddress((void**)&w1h, g_w1h);
    cudaGetSymbolAddress((void**)&w2h, g_w2h);
    cudaGetSymbolAddress((void**)&w3h, g_w3h);
    cudaGetSymbolAddress((void**)&woh, g_woh);

    cudaFuncSetAttribute((const void*)mma_gemm<CFEAT, true, false>,
                         cudaFuncAttributeMaxDynamicSharedMemorySize, GEMM_SMEM_BYTES);
    cudaFuncSetAttribute((const void*)mma_gemm<HD1, true, false>,
                         cudaFuncAttributeMaxDynamicSharedMemorySize, GEMM_SMEM_BYTES);
    cudaFuncSetAttribute((const void*)mma_gemm<HD2, true, false>,
                         cudaFuncAttributeMaxDynamicSharedMemorySize, GEMM_SMEM_BYTES);
    cudaFuncSetAttribute((const void*)mma_gemm<HD3, false, true>,
                         cudaFuncAttributeMaxDynamicSharedMemorySize, GEMM_SMEM_BYTES);
    cudaFuncSetAttribute((const void*)attn_kernel,
                         cudaFuncAttributeMaxDynamicSharedMemorySize, ATTN_SMEM_BYTES);

    // Launch order chosen so ncu (-s 5 -c 1) profiles launch #6 = GEMM2:
    //   1:f2h  2:transpose_all  3:memset  4:GEMM1  5:LN1  6:GEMM2
    f2h_kernel<<<(MTOT * CFEAT / 8 + 255) / 256, 256>>>(
        (const float4*)x, (uint4*)xh, MTOT * CFEAT / 8);
    transpose_all<<<dim3(864, 4), 256>>>(W1, W2, W3, Wo, w1h, w2h, w3h, woh);
    cudaMemsetAsync(poolp, 0, NBATCH * CFEAT * sizeof(float));

    dim3 blk(256);
    // layer 1: LN(GELU(x @ W1 + b1)), LN in-place on fp16
    mma_gemm<CFEAT, true, false><<<dim3(HD1 / BN, MTOT / BM), blk, GEMM_SMEM_BYTES>>>(
        xh, w1h, b1, h1h, HD1, nullptr);
    ln_kernel<HD1><<<MTOT / 8, 256>>>(h1h, g1, be1, MTOT);
    // layer 2  (profiled by ncu)
    mma_gemm<HD1, true, false><<<dim3(HD2 / BN, MTOT / BM), blk, GEMM_SMEM_BYTES>>>(
        h1h, w2h, b2, h2h, HD2, nullptr);
    ln_kernel<HD2><<<MTOT / 8, 256>>>(h2h, g2, be2, MTOT);
    // layer 3
    mma_gemm<HD2, true, false><<<dim3(HD3 / BN, MTOT / BM), blk, GEMM_SMEM_BYTES>>>(
        h2h, w3h, b3, h3h, HD3, nullptr);
    ln_kernel<HD3><<<MTOT / 8, 256>>>(h3h, g3, be3, MTOT);
    // output projection (fp16 out) + fused pooled column sums
    mma_gemm<HD3, false, true><<<dim3(CFEAT / BN, MTOT / BM), blk, GEMM_SMEM_BYTES>>>(
        h3h, woh, bo, yh, CFEAT, poolp);
    // SE gate
    se_kernel<<<NBATCH, 256>>>(poolp, caw1, cab1, caw2, cab2, sp);
    // tensor-core SE-scale + windowed attention -> final output
    attn_kernel<<<NWIN, 256, ATTN_SMEM_BYTES>>>(yh, sp, out);
}

// round 14
// speedup vs baseline: 4.3429x; 1.0019x over previous
#include <cuda_runtime.h>
#include <cuda_fp16.h>
#include <math.h>
#include <stdint.h>

// ---------------- problem constants ----------------
#define MTOT   73728          // B*N = 8*9216 rows
#define CFEAT  1152
#define HD1    768
#define HD2    512
#define HD3    256
#define RED    144            // 1152/8
#define NSEQ   9216
#define NBATCH 8
#define WS     32
#define NWIN   2304           // 8 * 9216/32

// ---------------- scratch (no cudaMalloc allowed) ----------------
__device__ float  g_pool[NBATCH * CFEAT];
__device__ float  g_s   [NBATCH * CFEAT];
// per-row LN stats: [sum1, sq1, sum2, sq2, sum3, sq3], each MTOT floats
__device__ float  g_stats[6 * (size_t)MTOT];
// LN-fold column vectors: t = sum_k g_k W_kn, u = sum_k be_k W_kn
__device__ float  g_t2[HD2], g_u2[HD2];
__device__ float  g_t3[HD3], g_u3[HD3];
__device__ float  g_t4[CFEAT], g_u4[CFEAT];
// fp16 activations (raw GELU outputs; no LN kernels anymore)
__device__ __half g_xh [(size_t)MTOT * CFEAT];
__device__ __half g_h1h[(size_t)MTOT * HD1];
__device__ __half g_h2h[(size_t)MTOT * HD2];
__device__ __half g_h3h[(size_t)MTOT * HD3];
__device__ __half g_yh [(size_t)MTOT * CFEAT];  // GEMM4 out (fp16)
// transposed fp16 weights [N][K]; layers 2-4 pre-scaled by previous-layer g
__device__ __half g_w1h[HD1 * CFEAT];
__device__ __half g_w2h[HD2 * HD1];
__device__ __half g_w3h[HD3 * HD2];
__device__ __half g_woh[CFEAT * HD3];

__device__ __forceinline__ float gelu_exact(float x) {
    return 0.5f * x * (1.0f + erff(x * 0.70710678118654752f));
}

__device__ __forceinline__ uint32_t smem_u32(const void* p) {
    uint32_t a;
    asm("{ .reg .u64 t; cvta.to.shared.u64 t, %1; cvt.u32.u64 %0, t; }" : "=r"(a) : "l"(p));
    return a;
}
__device__ __forceinline__ void cp16(uint32_t dst, const void* src) {
    asm volatile("cp.async.cg.shared.global [%0], [%1], 16;" :: "r"(dst), "l"(src));
}
#define CP_COMMIT() asm volatile("cp.async.commit_group;")
#define CP_WAIT0()  asm volatile("cp.async.wait_group 0;")
#define CP_WAIT1()  asm volatile("cp.async.wait_group 1;")

#define LDSM_X4(r, a) \
    asm volatile("ldmatrix.sync.aligned.m8n8.x4.shared.b16 {%0,%1,%2,%3}, [%4];" \
                 : "=r"((r)[0]), "=r"((r)[1]), "=r"((r)[2]), "=r"((r)[3]) : "r"(a))
#define LDSM_X4_T(r, a) \
    asm volatile("ldmatrix.sync.aligned.m8n8.x4.trans.shared.b16 {%0,%1,%2,%3}, [%4];" \
                 : "=r"((r)[0]), "=r"((r)[1]), "=r"((r)[2]), "=r"((r)[3]) : "r"(a))

__device__ __forceinline__ void mma_f16(float* c, const uint32_t* a,
                                        uint32_t b0, uint32_t b1) {
    asm volatile(
        "mma.sync.aligned.m16n8k16.row.col.f32.f16.f16.f32 "
        "{%0,%1,%2,%3}, {%4,%5,%6,%7}, {%8,%9}, {%0,%1,%2,%3};"
        : "+f"(c[0]), "+f"(c[1]), "+f"(c[2]), "+f"(c[3])
        : "r"(a[0]), "r"(a[1]), "r"(a[2]), "r"(a[3]), "r"(b0), "r"(b1));
}

// ---------------- prep: x -> fp16 ----------------
__global__ void f2h_kernel(const float4* __restrict__ src, uint4* __restrict__ dst, int n8) {
    const int i = blockIdx.x * 256 + threadIdx.x;
    if (i < n8) {
        float4 a = src[2 * i], b = src[2 * i + 1];
        __half2 h0 = __floats2half2_rn(a.x, a.y);
        __half2 h1 = __floats2half2_rn(a.z, a.w);
        __half2 h2 = __floats2half2_rn(b.x, b.y);
        __half2 h3 = __floats2half2_rn(b.z, b.w);
        uint4 o;
        o.x = *(uint32_t*)&h0; o.y = *(uint32_t*)&h1;
        o.z = *(uint32_t*)&h2; o.w = *(uint32_t*)&h3;
        dst[i] = o;
    }
}

// ---------------- prep: transposes (layers 2-4 scaled by prev-layer g) -------
__global__ void transpose_all(const float* __restrict__ W1, const float* __restrict__ W2,
                              const float* __restrict__ W3, const float* __restrict__ Wo,
                              const float* __restrict__ g1, const float* __restrict__ g2,
                              const float* __restrict__ g3,
                              __half* __restrict__ w1h, __half* __restrict__ w2h,
                              __half* __restrict__ w3h, __half* __restrict__ woh)
{
    __shared__ float t[32][33];
    const float* src; const float* gp; __half* dst; int K, N;
    switch (blockIdx.y) {
        case 0: src = W1; dst = w1h; gp = nullptr; K = CFEAT; N = HD1;  break;
        case 1: src = W2; dst = w2h; gp = g1;      K = HD1;  N = HD2;   break;
        case 2: src = W3; dst = w3h; gp = g2;      K = HD2;  N = HD3;   break;
        default: src = Wo; dst = woh; gp = g3;     K = HD3;  N = CFEAT; break;
    }
    const int ktiles = K / 32;
    const int tile = blockIdx.x;
    if (tile >= ktiles * (N / 32)) return;
    const int k0 = (tile % ktiles) * 32, n0 = (tile / ktiles) * 32;
    const int x = threadIdx.x & 31, y = threadIdx.x >> 5;
#pragma unroll
    for (int i = y; i < 32; i += 8)
        t[i][x] = src[(size_t)(k0 + i) * N + n0 + x];
    __syncthreads();
    const float fac = gp ? gp[k0 + x] : 1.f;   // written element has k = k0 + x
#pragma unroll
    for (int i = y; i < 32; i += 8)
        dst[(size_t)(n0 + i) * K + k0 + x] = __float2half_rn(t[x][i] * fac);
}

// ---------------- prep: LN-fold column sums t_n, u_n ----------------
__global__ void colsums(const float* __restrict__ W2, const float* __restrict__ W3,
                        const float* __restrict__ Wo,
                        const float* __restrict__ g1, const float* __restrict__ be1,
                        const float* __restrict__ g2, const float* __restrict__ be2,
                        const float* __restrict__ g3, const float* __restrict__ be3,
                        float* __restrict__ t2, float* __restrict__ u2,
                        float* __restrict__ t3, float* __restrict__ u3,
                        float* __restrict__ t4, float* __restrict__ u4)
{
    const float *W, *g, *be; float *t, *u; int K, N;
    switch (blockIdx.y) {
        case 0: W = W2; g = g1; be = be1; t = t2; u = u2; K = HD1; N = HD2; break;
        case 1: W = W3; g = g2; be = be2; t = t3; u = u3; K = HD2; N = HD3; break;
        default: W = Wo; g = g3; be = be3; t = t4; u = u4; K = HD3; N = CFEAT; break;
    }
    const int n = blockIdx.x * 256 + threadIdx.x;
    if (n >= N) return;
    float ts = 0.f, us = 0.f;
    for (int k = 0; k < K; k++) {
        const float w = W[(size_t)k * N + n];
        ts = fmaf(g[k], w, ts);
        us = fmaf(be[k], w, us);
    }
    t[n] = ts; u[n] = us;
}

// ---------------- fp16 tensor-core GEMM with fused LN-fold / stats ----------
#define BM 128
#define BN 128
#define BK 64
#define STAGE_BYTES (128 * 128)
#define NSTAGE 3
#define GEMM_SMEM_BYTES (2 * NSTAGE * STAGE_BYTES)   // 98304

template<int KDIM, bool DO_GELU, bool DO_POOL, bool DO_STATS, bool DO_FOLD>
__global__ void __launch_bounds__(256, 2)
mma_gemm(const __half* __restrict__ A, const __half* __restrict__ Bt,
         const float* __restrict__ bias, __half* __restrict__ Cout,
         int N, float* __restrict__ pool,
         float* __restrict__ rsumO, float* __restrict__ rsqO,
         const float* __restrict__ rsumI, const float* __restrict__ rsqI,
         const float* __restrict__ tv, const float* __restrict__ uv)
{
    extern __shared__ __align__(128) char smem[];
    const uint32_t sb = smem_u32(smem);

    const int tid = threadIdx.x;
    const int warp = tid >> 5, lane = tid & 31;
    const int wy = warp >> 1, wx = warp & 1;

    const int aRow0 = wy * 32 + (lane & 7) + 8 * ((lane >> 3) & 1);
    const int aCsel = lane >> 4;
    const int bRow0 = wx * 64 + (lane & 7) + 8 * ((lane >> 4) & 1);
    const int bCsel = (lane >> 3) & 1;

    const int gr = tid >> 3, gu = tid & 7;
    const __half* Abase = A  + (size_t)(blockIdx.y * BM) * KDIM;
    const __half* Bbase = Bt + (size_t)(blockIdx.x * BN) * KDIM;

    float acc[2][8][4];
#pragma unroll
    for (int im = 0; im < 2; im++)
#pragma unroll
        for (int in = 0; in < 8; in++)
#pragma unroll
            for (int c = 0; c < 4; c++) acc[im][in][c] = 0.f;

    constexpr int nk = KDIM >> 6;

    const uint32_t soff = ((uint32_t)gr << 7) + (uint32_t)((gu ^ (gr & 7)) << 4);

#pragma unroll
    for (int s = 0; s < 2 && s < nk; s++) {
        const int k0 = s << 6;
        const uint32_t ad = sb + s * STAGE_BYTES;
        const uint32_t bd = sb + (NSTAGE + s) * STAGE_BYTES;
#pragma unroll
        for (int j = 0; j < 4; j++) {
            const int r = gr + j * 32;
            const uint32_t off = soff + (uint32_t)(j * 32) * 128;
            cp16(ad + off, Abase + (size_t)r * KDIM + k0 + (gu << 3));
            cp16(bd + off, Bbase + (size_t)r * KDIM + k0 + (gu << 3));
        }
        CP_COMMIT();
    }

#pragma unroll
    for (int kt = 0; kt < nk; kt++) {
        const int buf = kt % NSTAGE;
        if (kt == nk - 1) { CP_WAIT0(); } else { CP_WAIT1(); }
        __syncthreads();

        if (kt + 2 < nk) {
            const int s = (kt + 2) % NSTAGE;
            const int k0 = (kt + 2) << 6;
            const uint32_t ad = sb + s * STAGE_BYTES;
            const uint32_t bd = sb + (NSTAGE + s) * STAGE_BYTES;
#pragma unroll
            for (int j = 0; j < 4; j++) {
                const int r = gr + j * 32;
                const uint32_t off = soff + (uint32_t)(j * 32) * 128;
                cp16(ad + off, Abase + (size_t)r * KDIM + k0 + (gu << 3));
                cp16(bd + off, Bbase + (size_t)r * KDIM + k0 + (gu << 3));
            }
            CP_COMMIT();
        }

        const uint32_t aB = sb + buf * STAGE_BYTES;
        const uint32_t bB = sb + (NSTAGE + buf) * STAGE_BYTES;
#pragma unroll
        for (int j = 0; j < 4; j++) {
            const int c0 = 2 * j;
            uint32_t af[2][4];
#pragma unroll
            for (int im = 0; im < 2; im++) {
                const int row = aRow0 + im * 16;
                const uint32_t addr = aB + ((uint32_t)row << 7)
                                    + (uint32_t)(((c0 + aCsel) ^ (row & 7)) << 4);
                LDSM_X4(af[im], addr);
            }
            uint32_t bf[4][4];
#pragma unroll
            for (int p = 0; p < 4; p++) {
                const int row = bRow0 + p * 16;
                const uint32_t addr = bB + ((uint32_t)row << 7)
                                    + (uint32_t)(((c0 + bCsel) ^ (row & 7)) << 4);
                LDSM_X4(bf[p], addr);
            }
#pragma unroll
            for (int im = 0; im < 2; im++)
#pragma unroll
                for (int p = 0; p < 4; p++) {
                    mma_f16(acc[im][2 * p],     af[im], bf[p][0], bf[p][1]);
                    mma_f16(acc[im][2 * p + 1], af[im], bf[p][2], bf[p][3]);
                }
        }
    }
    __syncthreads();

    // ---- epilogue: LN-fold correction, bias, (gelu), fp16 store, stats, pool
    const int g = lane >> 2, t = lane & 3;
    float* csum = (float*)smem;
    if (DO_POOL) {
        if (tid < 128) csum[tid] = 0.f;
        __syncthreads();
    }

#pragma unroll
    for (int im = 0; im < 2; im++) {
        const int r0 = blockIdx.y * BM + wy * 32 + im * 16 + g;
        float mu0 = 0.f, s0 = 1.f, mu1 = 0.f, s1 = 1.f;
        if (DO_FOLD) {
            constexpr float invH = 1.0f / (float)KDIM;
            const float a0 = rsumI[r0],     q0 = rsqI[r0];
            const float a1 = rsumI[r0 + 8], q1 = rsqI[r0 + 8];
            mu0 = a0 * invH; s0 = rsqrtf(q0 * invH - mu0 * mu0 + 1e-5f);
            mu1 = a1 * invH; s1 = rsqrtf(q1 * invH - mu1 * mu1 + 1e-5f);
        }
        float rs0 = 0.f, rq0 = 0.f, rs1 = 0.f, rq1 = 0.f;
#pragma unroll
        for (int in = 0; in < 8; in++) {
            const int col = blockIdx.x * BN + wx * 64 + in * 8 + 2 * t;
            const float bv0 = bias[col], bv1 = bias[col + 1];
            float v00, v01, v10, v11;
            if (DO_FOLD) {
                const float t0 = tv[col], t1 = tv[col + 1];
                const float w0 = uv[col], w1 = uv[col + 1];
                v00 = s0 * (acc[im][in][0] - mu0 * t0) + w0 + bv0;
                v01 = s0 * (acc[im][in][1] - mu0 * t1) + w1 + bv1;
                v10 = s1 * (acc[im][in][2] - mu1 * t0) + w0 + bv0;
                v11 = s1 * (acc[im][in][3] - mu1 * t1) + w1 + bv1;
            } else {
                v00 = acc[im][in][0] + bv0;
                v01 = acc[im][in][1] + bv1;
                v10 = acc[im][in][2] + bv0;
                v11 = acc[im][in][3] + bv1;
            }
            if (DO_GELU) {
                v00 = gelu_exact(v00); v01 = gelu_exact(v01);
                v10 = gelu_exact(v10); v11 = gelu_exact(v11);
            }
            *(__half2*)(Cout + (size_t)r0 * N + col)       = __floats2half2_rn(v00, v01);
            *(__half2*)(Cout + (size_t)(r0 + 8) * N + col) = __floats2half2_rn(v10, v11);
            if (DO_POOL) {
                const int lc = wx * 64 + in * 8 + 2 * t;
                atomicAdd(&csum[lc],     v00 + v10);
                atomicAdd(&csum[lc + 1], v01 + v11);
            }
            if (DO_STATS) {
                rs0 += v00 + v01; rq0 += v00 * v00 + v01 * v01;
                rs1 += v10 + v11; rq1 += v10 * v10 + v11 * v11;
            }
        }
        if (DO_STATS) {
            // reduce across the 4 column lanes (lane = 4g + t)
#pragma unroll
            for (int o = 1; o <= 2; o <<= 1) {
                rs0 += __shfl_xor_sync(0xffffffffu, rs0, o);
                rq0 += __shfl_xor_sync(0xffffffffu, rq0, o);
                rs1 += __shfl_xor_sync(0xffffffffu, rs1, o);
                rq1 += __shfl_xor_sync(0xffffffffu, rq1, o);
            }
            if (t == 0) {
                atomicAdd(&rsumO[r0], rs0);     atomicAdd(&rsqO[r0], rq0);
                atomicAdd(&rsumO[r0 + 8], rs1); atomicAdd(&rsqO[r0 + 8], rq1);
            }
        }
    }

    if (DO_POOL) {
        __syncthreads();
        if (tid < 128) {
            const int batch = (blockIdx.y * BM) / NSEQ;
            atomicAdd(&pool[batch * CFEAT + blockIdx.x * BN + tid], csum[tid]);
        }
    }
}

// ---------------- SE channel attention ----------------
__global__ void se_kernel(const float* __restrict__ pool,
                          const float* __restrict__ w1, const float* __restrict__ b1,
                          const float* __restrict__ w2, const float* __restrict__ b2,
                          float* __restrict__ s)
{
    __shared__ float p[CFEAT];
    __shared__ float hid[RED];
    const int b = blockIdx.x, t = threadIdx.x;
    for (int i = t; i < CFEAT; i += 256) p[i] = pool[b * CFEAT + i] * (1.0f / NSEQ);
    __syncthreads();
    if (t < RED) {
        float a = b1[t];
        for (int c = 0; c < CFEAT; c++) a = fmaf(p[c], w1[c * RED + t], a);
        hid[t] = fmaxf(a, 0.f);
    }
    __syncthreads();
    for (int c = t; c < CFEAT; c += 256) {
        float a = b2[c];
        for (int h = 0; h < RED; h++) a = fmaf(hid[h], w2[h * CFEAT + c], a);
        s[b * CFEAT + c] = 1.0f / (1.0f + expf(-a));
    }
}

// ---------------- tensor-core windowed attention ----------------
#define YROWH 1160
#define YROWB 2320
#define PROWH 40
#define ATTN_SS_OFF  (32 * YROWH * 2)                 // 74240
#define ATTN_PS_OFF  (ATTN_SS_OFF + 32 * 33 * 4)      // 78464
#define ATTN_SMEM_BYTES (ATTN_PS_OFF + 32 * PROWH * 2) // 81024

__global__ void __launch_bounds__(256, 2)
attn_kernel(const __half* __restrict__ y, const float* __restrict__ s,
            float* __restrict__ out)
{
    extern __shared__ __align__(128) char smem[];
    __half* Ys = (__half*)smem;
    float*  Ss = (float*)(smem + ATTN_SS_OFF);
    __half* Ps = (__half*)(smem + ATTN_PS_OFF);
    const uint32_t ysb = smem_u32(smem);
    const uint32_t psb = ysb + ATTN_PS_OFF;

    const int win = blockIdx.x;
    const int b = win / (NSEQ / WS);
    const size_t base = (size_t)win * 32;
    const int tid = threadIdx.x;
    const int warp = tid >> 5, lane = tid & 31;
    const float* sb = s + b * CFEAT;

    for (int idx = tid; idx < 32 * 144; idx += 256) {
        const int r = idx / 144, u = idx - r * 144;
        uint4 raw = *(const uint4*)(y + (base + r) * CFEAT + u * 8);
        const float4 s0 = *(const float4*)(sb + u * 8);
        const float4 s1 = *(const float4*)(sb + u * 8 + 4);
        __half2* hp = (__half2*)&raw;
        float2 f0 = __half22float2(hp[0]);
        float2 f1 = __half22float2(hp[1]);
        float2 f2 = __half22float2(hp[2]);
        float2 f3 = __half22float2(hp[3]);
        uint4 o;
        __half2 t0 = __floats2half2_rn(f0.x * s0.x, f0.y * s0.y);
        __half2 t1 = __floats2half2_rn(f1.x * s0.z, f1.y * s0.w);
        __half2 t2 = __floats2half2_rn(f2.x * s1.x, f2.y * s1.y);
        __half2 t3 = __floats2half2_rn(f3.x * s1.z, f3.y * s1.w);
        o.x = *(uint32_t*)&t0; o.y = *(uint32_t*)&t1;
        o.z = *(uint32_t*)&t2; o.w = *(uint32_t*)&t3;
        *(uint4*)(Ys + r * YROWH + u * 8) = o;
    }
    for (int i = tid; i < 32 * 33; i += 256) Ss[i] = 0.f;
    __syncthreads();

    const int aRow = (lane & 7) + 8 * ((lane >> 3) & 1);
    const int aC   = lane >> 4;
    const int bRow = (lane & 7) + 8 * ((lane >> 4) & 1);
    const int bC   = (lane >> 3) & 1;

    // phase 2: S partials
    {
        float acc[2][4][4];
#pragma unroll
        for (int im = 0; im < 2; im++)
#pragma unroll
            for (int in = 0; in < 4; in++)
#pragma unroll
                for (int c = 0; c < 4; c++) acc[im][in][c] = 0.f;
        const int kch0 = warp * 18;
#pragma unroll
        for (int ks = 0; ks < 9; ks++) {
            const int c0 = kch0 + 2 * ks;
            uint32_t af[2][4], bf[2][4];
#pragma unroll
            for (int im = 0; im < 2; im++)
                LDSM_X4(af[im], ysb + (uint32_t)(im * 16 + aRow) * YROWB
                                    + (uint32_t)(c0 + aC) * 16);
#pragma unroll
            for (int jn = 0; jn < 2; jn++)
                LDSM_X4(bf[jn], ysb + (uint32_t)(jn * 16 + bRow) * YROWB
                                    + (uint32_t)(c0 + bC) * 16);
#pragma unroll
            for (int im = 0; im < 2; im++)
#pragma unroll
                for (int jn = 0; jn < 2; jn++) {
                    mma_f16(acc[im][2 * jn],     af[im], bf[jn][0], bf[jn][1]);
                    mma_f16(acc[im][2 * jn + 1], af[im], bf[jn][2], bf[jn][3]);
                }
        }
        const int g = lane >> 2, t2 = lane & 3;
#pragma unroll
        for (int im = 0; im < 2; im++)
#pragma unroll
            for (int in = 0; in < 4; in++) {
                const int r0 = im * 16 + g, c0 = in * 8 + 2 * t2;
                atomicAdd(&Ss[r0 * 33 + c0],           acc[im][in][0]);
                atomicAdd(&Ss[r0 * 33 + c0 + 1],       acc[im][in][1]);
                atomicAdd(&Ss[(r0 + 8) * 33 + c0],     acc[im][in][2]);
                atomicAdd(&Ss[(r0 + 8) * 33 + c0 + 1], acc[im][in][3]);
            }
    }
    __syncthreads();

    // phase 3: softmax -> P fp16
    {
        const float scale = 1.0f / sqrtf((float)CFEAT);
        for (int q = warp; q < 32; q += 8) {
            float v = Ss[q * 33 + lane] * scale;
            float m = v;
#pragma unroll
            for (int o = 16; o > 0; o >>= 1) m = fmaxf(m, __shfl_xor_sync(0xffffffffu, m, o));
            float e = expf(v - m);
            float sum = e;
#pragma unroll
            for (int o = 16; o > 0; o >>= 1) sum += __shfl_xor_sync(0xffffffffu, sum, o);
            Ps[q * PROWH + lane] = __float2half_rn(e / sum);
        }
    }
    __syncthreads();

    // phase 4: out = P @ Y
    {
        uint32_t af[2][2][4];
#pragma unroll
        for (int kk = 0; kk < 2; kk++)
#pragma unroll
            for (int im = 0; im < 2; im++)
                LDSM_X4(af[kk][im], psb + (uint32_t)(im * 16 + aRow) * (PROWH * 2)
                                        + (uint32_t)(kk * 2 + aC) * 16);
        const int cch0 = warp * 18;
        const int g = lane >> 2, t2 = lane & 3;
#pragma unroll
        for (int jn = 0; jn < 9; jn++) {
            float acc[2][2][4];
#pragma unroll
            for (int im = 0; im < 2; im++)
#pragma unroll
                for (int in = 0; in < 2; in++)
#pragma unroll
                    for (int c = 0; c < 4; c++) acc[im][in][c] = 0.f;
#pragma unroll
            for (int kk = 0; kk < 2; kk++) {
                uint32_t bt[4];
                LDSM_X4_T(bt, ysb + (uint32_t)(kk * 16 + aRow) * YROWB
                                  + (uint32_t)(cch0 + 2 * jn + aC) * 16);
#pragma unroll
                for (int im = 0; im < 2; im++) {
                    mma_f16(acc[im][0], af[kk][im], bt[0], bt[1]);
                    mma_f16(acc[im][1], af[kk][im], bt[2], bt[3]);
                }
            }
#pragma unroll
            for (int im = 0; im < 2; im++) {
                const int row = im * 16 + g;
#pragma unroll
                for (int in = 0; in < 2; in++) {
                    const int col = warp * 144 + jn * 16 + in * 8 + 2 * t2;
                    *(float2*)(out + (base + row) * CFEAT + col) =
                        make_float2(acc[im][in][0], acc[im][in][1]);
                    *(float2*)(out + (base + row + 8) * CFEAT + col) =
                        make_float2(acc[im][in][2], acc[im][in][3]);
                }
            }
        }
    }
}

// ---------------- launch ----------------
extern "C" void kernel_launch(void* const* d_in, const int* in_sizes, int n_in,
                              void* d_out, int out_size)
{
    const float* x    = (const float*)d_in[0];
    const float* W1   = (const float*)d_in[1];
    const float* b1   = (const float*)d_in[2];
    const float* g1   = (const float*)d_in[3];
    const float* be1  = (const float*)d_in[4];
    const float* W2   = (const float*)d_in[5];
    const float* b2   = (const float*)d_in[6];
    const float* g2   = (const float*)d_in[7];
    const float* be2  = (const float*)d_in[8];
    const float* W3   = (const float*)d_in[9];
    const float* b3   = (const float*)d_in[10];
    const float* g3   = (const float*)d_in[11];
    const float* be3  = (const float*)d_in[12];
    const float* Wo   = (const float*)d_in[13];
    const float* bo   = (const float*)d_in[14];
    const float* caw1 = (const float*)d_in[15];
    const float* cab1 = (const float*)d_in[16];
    const float* caw2 = (const float*)d_in[17];
    const float* cab2 = (const float*)d_in[18];
    float* out = (float*)d_out;

    float *poolp, *sp, *statsp;
    float *t2p, *u2p, *t3p, *u3p, *t4p, *u4p;
    __half *xh, *h1h, *h2h, *h3h, *yh, *w1h, *w2h, *w3h, *woh;
    cudaGetSymbolAddress((void**)&poolp, g_pool);
    cudaGetSymbolAddress((void**)&sp,  g_s);
    cudaGetSymbolAddress((void**)&statsp, g_stats);
    cudaGetSymbolAddress((void**)&t2p, g_t2);
    cudaGetSymbolAddress((void**)&u2p, g_u2);
    cudaGetSymbolAddress((void**)&t3p, g_t3);
    cudaGetSymbolAddress((void**)&u3p, g_u3);
    cudaGetSymbolAddress((void**)&t4p, g_t4);
    cudaGetSymbolAddress((void**)&u4p, g_u4);
    cudaGetSymbolAddress((void**)&xh,  g_xh);
    cudaGetSymbolAddress((void**)&h1h, g_h1h);
    cudaGetSymbolAddress((void**)&h2h, g_h2h);
    cudaGetSymbolAddress((void**)&h3h, g_h3h);
    cudaGetSymbolAddress((void**)&yh,  g_yh);
    cudaGetSymbolAddress((void**)&w1h, g_w1h);
    cudaGetSymbolAddress((void**)&w2h, g_w2h);
    cudaGetSymbolAddress((void**)&w3h, g_w3h);
    cudaGetSymbolAddress((void**)&woh, g_woh);

    float* s1sum = statsp;               float* s1sq = statsp + MTOT;
    float* s2sum = statsp + 2 * MTOT;    float* s2sq = statsp + 3 * MTOT;
    float* s3sum = statsp + 4 * MTOT;    float* s3sq = statsp + 5 * MTOT;

    cudaFuncSetAttribute((const void*)mma_gemm<CFEAT, true, false, true, false>,
                         cudaFuncAttributeMaxDynamicSharedMemorySize, GEMM_SMEM_BYTES);
    cudaFuncSetAttribute((const void*)mma_gemm<HD1, true, false, true, true>,
                         cudaFuncAttributeMaxDynamicSharedMemorySize, GEMM_SMEM_BYTES);
    cudaFuncSetAttribute((const void*)mma_gemm<HD2, true, false, true, true>,
                         cudaFuncAttributeMaxDynamicSharedMemorySize, GEMM_SMEM_BYTES);
    cudaFuncSetAttribute((const void*)mma_gemm<HD3, false, true, false, true>,
                         cudaFuncAttributeMaxDynamicSharedMemorySize, GEMM_SMEM_BYTES);
    cudaFuncSetAttribute((const void*)attn_kernel,
                         cudaFuncAttributeMaxDynamicSharedMemorySize, ATTN_SMEM_BYTES);

    // Launch order (ncu -s 5 -c 1 profiles launch #6 = GEMM1):
    //   1:f2h 2:transpose 3:colsums 4:memset(stats) 5:memset(pool) 6:GEMM1 ...
    f2h_kernel<<<(MTOT * CFEAT / 8 + 255) / 256, 256>>>(
        (const float4*)x, (uint4*)xh, MTOT * CFEAT / 8);
    transpose_all<<<dim3(864, 4), 256>>>(W1, W2, W3, Wo, g1, g2, g3,
                                         w1h, w2h, w3h, woh);
    colsums<<<dim3((CFEAT + 255) / 256, 3), 256>>>(W2, W3, Wo, g1, be1, g2, be2,
                                                   g3, be3, t2p, u2p, t3p, u3p, t4p, u4p);
    cudaMemsetAsync(statsp, 0, 6 * (size_t)MTOT * sizeof(float));
    cudaMemsetAsync(poolp, 0, NBATCH * CFEAT * sizeof(float));

    dim3 blk(256);
    // layer 1: GELU(x @ W1 + b1) -> h1 (raw), emit row stats
    mma_gemm<CFEAT, true, false, true, false>
        <<<dim3(HD1 / BN, MTOT / BM), blk, GEMM_SMEM_BYTES>>>(
        xh, w1h, b1, h1h, HD1, nullptr, s1sum, s1sq, nullptr, nullptr, nullptr, nullptr);
    // layer 2: LN folded (stats1, t2/u2), GELU, emit stats2
    mma_gemm<HD1, true, false, true, true>
        <<<dim3(HD2 / BN, MTOT / BM), blk, GEMM_SMEM_BYTES>>>(
        h1h, w2h, b2, h2h, HD2, nullptr, s2sum, s2sq, s1sum, s1sq, t2p, u2p);
    // layer 3: LN folded (stats2, t3/u3), GELU, emit stats3
    mma_gemm<HD2, true, false, true, true>
        <<<dim3(HD3 / BN, MTOT / BM), blk, GEMM_SMEM_BYTES>>>(
        h2h, w3h, b3, h3h, HD3, nullptr, s3sum, s3sq, s2sum, s2sq, t3p, u3p);
    // layer 4: LN folded (stats3, t4/u4), no GELU, fp16 y + pooling
    mma_gemm<HD3, false, true, false, true>
        <<<dim3(CFEAT / BN, MTOT / BM), blk, GEMM_SMEM_BYTES>>>(
        h3h, woh, bo, yh, CFEAT, poolp, nullptr, nullptr, s3sum, s3sq, t4p, u4p);
    // SE gate
    se_kernel<<<NBATCH, 256>>>(poolp, caw1, cab1, caw2, cab2, sp);
    // tensor-core SE-scale + windowed attention -> final output
    attn_kernel<<<NWIN, 256, ATTN_SMEM_BYTES>>>(yh, sp, out);
}